// round 4
// baseline (speedup 1.0000x reference)
#include <cuda_runtime.h>
#include <math_constants.h>

#define NVEC   16384
#define KCODES 8192
#define CDIM   256
#define ZELEMS (16*256*32*32)   /* 4194304 */
#define NTILES 512              /* 32 n-rows each */
#define KCHUNKS 8               /* 1024 k each */
#define NUNITS (NTILES*KCHUNKS) /* 4096 */
#define GRID_P 304

__device__ float  g_zz[NVEC];
__device__ float  g_ee[KCODES];
__device__ int    g_idx[NVEC];
__device__ double g_loss;
__device__ int    g_unit;
__device__ float  g_pd[NTILES*KCHUNKS*32];
__device__ int    g_pk[NTILES*KCHUNKS*32];

typedef unsigned long long ull;

__device__ __forceinline__ void fma2(ull& d, ull a, ull b) {
    asm("fma.rn.f32x2 %0, %1, %2, %0;" : "+l"(d) : "l"(a), "l"(b));
}
__device__ __forceinline__ void unpack2(float& lo, float& hi, ull v) {
    unsigned a, b;
    asm("mov.b64 {%0, %1}, %2;" : "=r"(a), "=r"(b) : "l"(v));
    lo = __uint_as_float(a); hi = __uint_as_float(b);
}

// ---------------------------------------------------------------------------
// zz[n], ee[k] (sequential fp32 mul-add, matching reference); reset counters.
// z layout: [b][c][hw], b=n>>10, hw=n&1023
// ---------------------------------------------------------------------------
__global__ void prologue_kernel(const float* __restrict__ z,
                                const float* __restrict__ emb) {
    int i = blockIdx.x * blockDim.x + threadIdx.x;
    if (i == 0) { g_loss = 0.0; g_unit = 0; }
    if (i < NVEC) {
        int b = i >> 10, hw = i & 1023;
        const float* p = z + (size_t)b * 262144 + hw;
        float acc = 0.f;
        #pragma unroll 8
        for (int c = 0; c < CDIM; c++) {
            float v = p[(size_t)c * 1024];
            acc = __fadd_rn(acc, __fmul_rn(v, v));
        }
        g_zz[i] = acc;
    } else if (i < NVEC + KCODES) {
        int k = i - NVEC;
        const float* p = emb + (size_t)k * CDIM;
        float acc = 0.f;
        #pragma unroll 8
        for (int c = 0; c < CDIM; c++) {
            float v = p[c];
            acc = __fadd_rn(acc, __fmul_rn(v, v));
        }
        g_ee[k] = acc;
    }
}

// ---------------------------------------------------------------------------
// Persistent fused distance GEMM + per-chunk argmin.
// Unit = (ntile: 32 n-rows, kchunk: 1024 k). Dynamic queue over 4096 units.
// Packing: f32x2 lanes = adjacent k. e pairs free from natural [c][k'] smem
// (k' = k ^ ((c&15)<<2) swizzle); z dup panel zs[c][dup n] built once/unit.
// Thread (tx=t&31, ty=t>>5): 4 n (ty*4+i) x 8 k (4tx+{0..3}, 128+4tx+{0..3})
// per 256-k tile, kt = 4 tiles per unit. Per-lane accumulation c=0..255
// sequential fma -> bit-identical to verified R1/R2 path.
// ---------------------------------------------------------------------------
__global__ __launch_bounds__(256, 2)
void argmin_kernel(const float* __restrict__ z, const float* __restrict__ emb) {
    extern __shared__ float smem[];
    float* zs = smem;            // 16384 floats: [256 c][64 dup-n floats]
    float* es = smem + 16384;    // 2 x 4096 floats: [16 c][256 k'] each
    float* sd = es;              // scratch overlay after mainloop
    int*   si = (int*)(es + 1024);
    __shared__ int s_u;

    const int t  = threadIdx.x;
    const int tx = t & 31, ty = t >> 5;
    const int cq  = t & 3;       // loader: c-float4 index
    const int kkb = t >> 2;      // loader: k base (+64 per iter)

    int cur_ntile = -1;
    float zzr[4];

    for (;;) {
        if (t == 0) s_u = atomicAdd(&g_unit, 1);
        __syncthreads();
        const int u = s_u;
        if (u >= NUNITS) break;
        const int ntile  = u >> 3;
        const int kchunk = u & 7;

        if (ntile != cur_ntile) {
            cur_ntile = ntile;
            const int n0 = ntile * 32;
            const int b = n0 >> 10, hw0 = n0 & 1023;
            __syncthreads();   // everyone past zs reads of previous unit
            #pragma unroll
            for (int it = 0; it < 8; it++) {
                int idx = t + 256 * it;
                int c = idx >> 3, nq = idx & 7;
                float4 w = *(const float4*)&z[(size_t)b * 262144 + c * 1024 + hw0 + nq * 4];
                *(float4*)&zs[c * 64 + nq * 8]     = make_float4(w.x, w.x, w.y, w.y);
                *(float4*)&zs[c * 64 + nq * 8 + 4] = make_float4(w.z, w.z, w.w, w.w);
            }
            #pragma unroll
            for (int i = 0; i < 4; i++) zzr[i] = g_zz[n0 + ty * 4 + i];
        }

        float bestd[4]; int bestk[4];
        #pragma unroll
        for (int i = 0; i < 4; i++) { bestd[i] = CUDART_INF_F; bestk[i] = 0; }

        #pragma unroll 1
        for (int kt = 0; kt < 4; kt++) {
            const int kbase = kchunk * 1024 + kt * 256;

            ull acc[4][4];
            #pragma unroll
            for (int i = 0; i < 4; i++)
                #pragma unroll
                for (int p = 0; p < 4; p++) acc[i][p] = 0ull;

            float4 pre[4];
            // preload + store chunk 0
            #pragma unroll
            for (int it = 0; it < 4; it++) {
                int idx = t + 256 * it;
                int kk = (idx >> 2);
                int cql = idx & 3;
                pre[it] = *(const float4*)&emb[(size_t)(kbase + kk) * 256 + 4 * cql];
            }
            __syncthreads();   // es free (covers zs fill too)
            #pragma unroll
            for (int it = 0; it < 4; it++) {
                int idx = t + 256 * it;
                int kk = idx >> 2, cql = idx & 3;
                float* eb = es;
                float vj[4] = { pre[it].x, pre[it].y, pre[it].z, pre[it].w };
                #pragma unroll
                for (int j = 0; j < 4; j++) {
                    int cl = 4 * cql + j;
                    eb[cl * 256 + (kk ^ (cl << 2))] = vj[j];
                }
            }
            __syncthreads();

            #pragma unroll 1
            for (int ch = 0; ch < 16; ch++) {
                if (ch < 15) {
                    const int c0n = (ch + 1) * 16;
                    #pragma unroll
                    for (int it = 0; it < 4; it++) {
                        int idx = t + 256 * it;
                        int kk = idx >> 2, cql = idx & 3;
                        pre[it] = *(const float4*)&emb[(size_t)(kbase + kk) * 256 + c0n + 4 * cql];
                    }
                }
                const float* eb = es + (ch & 1) * 4096;

                #pragma unroll
                for (int c = 0; c < 16; c++) {
                    const int cg = ch * 16 + c;
                    const int swf = c << 2;   // (c&15)<<2, float-index XOR
                    ulonglong2 zA = *(const ulonglong2*)&zs[cg * 64 + ty * 8];
                    ulonglong2 zB = *(const ulonglong2*)&zs[cg * 64 + ty * 8 + 4];
                    ulonglong2 eA = *(const ulonglong2*)&eb[c * 256 + ((tx * 4) ^ swf)];
                    ulonglong2 eB = *(const ulonglong2*)&eb[c * 256 + ((128 + tx * 4) ^ swf)];
                    fma2(acc[0][0], zA.x, eA.x); fma2(acc[0][1], zA.x, eA.y);
                    fma2(acc[0][2], zA.x, eB.x); fma2(acc[0][3], zA.x, eB.y);
                    fma2(acc[1][0], zA.y, eA.x); fma2(acc[1][1], zA.y, eA.y);
                    fma2(acc[1][2], zA.y, eB.x); fma2(acc[1][3], zA.y, eB.y);
                    fma2(acc[2][0], zB.x, eA.x); fma2(acc[2][1], zB.x, eA.y);
                    fma2(acc[2][2], zB.x, eB.x); fma2(acc[2][3], zB.x, eB.y);
                    fma2(acc[3][0], zB.y, eA.x); fma2(acc[3][1], zB.y, eA.y);
                    fma2(acc[3][2], zB.y, eB.x); fma2(acc[3][3], zB.y, eB.y);
                }

                if (ch < 15) {
                    float* ebn = es + ((ch + 1) & 1) * 4096;
                    #pragma unroll
                    for (int it = 0; it < 4; it++) {
                        int idx = t + 256 * it;
                        int kk = idx >> 2, cql = idx & 3;
                        float vj[4] = { pre[it].x, pre[it].y, pre[it].z, pre[it].w };
                        #pragma unroll
                        for (int j = 0; j < 4; j++) {
                            int cl = 4 * cql + j;
                            ebn[cl * 256 + (kk ^ (cl << 2))] = vj[j];
                        }
                    }
                    __syncthreads();
                }
            }

            // epilogue: rounded distances, running argmin (k ascending)
            float4 eeA = *(const float4*)&g_ee[kbase + 4 * tx];
            float4 eeB = *(const float4*)&g_ee[kbase + 128 + 4 * tx];
            float eev[8] = { eeA.x, eeA.y, eeA.z, eeA.w, eeB.x, eeB.y, eeB.z, eeB.w };
            #pragma unroll
            for (int p = 0; p < 4; p++) {
                int klo = kbase + (p >> 1) * 128 + 4 * tx + (p & 1) * 2;
                float eel = eev[(p >> 1) * 4 + (p & 1) * 2];
                float eeh = eev[(p >> 1) * 4 + (p & 1) * 2 + 1];
                #pragma unroll
                for (int i = 0; i < 4; i++) {
                    float dlo, dhi;
                    unpack2(dlo, dhi, acc[i][p]);
                    float d0 = __fsub_rn(__fadd_rn(zzr[i], eel), __fmul_rn(2.0f, dlo));
                    float d1 = __fsub_rn(__fadd_rn(zzr[i], eeh), __fmul_rn(2.0f, dhi));
                    if (d0 < bestd[i]) { bestd[i] = d0; bestk[i] = klo; }
                    if (d1 < bestd[i]) { bestd[i] = d1; bestk[i] = klo + 1; }
                }
            }
        }

        // per-unit reduce across tx; write partials
        __syncthreads();   // es mainloop reads done -> scratch reuse
        #pragma unroll
        for (int i = 0; i < 4; i++) {
            sd[(ty * 4 + i) * 32 + tx] = bestd[i];
            si[(ty * 4 + i) * 32 + tx] = bestk[i];
        }
        __syncthreads();
        if (t < 32) {
            float bd = CUDART_INF_F; int bk = 0x7fffffff;
            #pragma unroll 4
            for (int x = 0; x < 32; x++) {
                float d = sd[t * 32 + x];
                int   k = si[t * 32 + x];
                if (d < bd || (d == bd && k < bk)) { bd = d; bk = k; }
            }
            g_pd[(ntile * 8 + kchunk) * 32 + t] = bd;
            g_pk[(ntile * 8 + kchunk) * 32 + t] = bk;
        }
        __syncthreads();   // scratch/es/s_u safe for next unit
    }
}

// ---------------------------------------------------------------------------
// Combine per-chunk partials: chunk ascending == k ascending; strict <
// replicates reference first-index argmin across the full K range.
// ---------------------------------------------------------------------------
__global__ void combine_kernel() {
    int n = blockIdx.x * 256 + threadIdx.x;
    if (n >= NVEC) return;
    int ntile = n >> 5, nl = n & 31;
    float bd = CUDART_INF_F; int bk = 0;
    #pragma unroll
    for (int ch = 0; ch < KCHUNKS; ch++) {
        float d = g_pd[(ntile * 8 + ch) * 32 + nl];
        int   k = g_pk[(ntile * 8 + ch) * 32 + nl];
        if (d < bd) { bd = d; bk = k; }
    }
    g_idx[n] = bk;
}

// ---------------------------------------------------------------------------
// out[o] = fl(z + fl(zq - z)) ; loss = sum fl(zq-z)^2 (double atomics)
// ---------------------------------------------------------------------------
__global__ void gather_kernel(const float* __restrict__ z,
                              const float* __restrict__ emb,
                              float* __restrict__ out) {
    int o = blockIdx.x * 256 + threadIdx.x;
    int rem = o & 262143;
    int b  = o >> 18;
    int c  = rem >> 10;
    int hw = rem & 1023;
    int n  = (b << 10) + hw;
    float zv = z[o];
    float q  = emb[(size_t)g_idx[n] * CDIM + c];
    float diff = __fsub_rn(q, zv);
    out[o] = __fadd_rn(zv, diff);
    float d2 = __fmul_rn(diff, diff);

    __shared__ float red[256];
    red[threadIdx.x] = d2;
    __syncthreads();
    for (int s = 128; s > 0; s >>= 1) {
        if (threadIdx.x < s) red[threadIdx.x] += red[threadIdx.x + s];
        __syncthreads();
    }
    if (threadIdx.x == 0) atomicAdd(&g_loss, (double)red[0]);
}

__global__ void tail_kernel(float* __restrict__ out, int out_size) {
    int i = blockIdx.x * 256 + threadIdx.x;
    if (i < NVEC && out_size >= ZELEMS + NVEC)
        out[ZELEMS + i] = (float)g_idx[i];
    if (i == 0 && out_size >= ZELEMS + NVEC + 1) {
        float m = (float)(g_loss / (double)ZELEMS);
        out[ZELEMS + NVEC] = __fadd_rn(m, __fmul_rn(0.25f, m)); // m + BETA*m
    }
}

// ---------------------------------------------------------------------------
extern "C" void kernel_launch(void* const* d_in, const int* in_sizes, int n_in,
                              void* d_out, int out_size) {
    const float* z   = (const float*)d_in[0];
    const float* emb = (const float*)d_in[1];
    float* out = (float*)d_out;

    cudaFuncSetAttribute(argmin_kernel,
                         cudaFuncAttributeMaxDynamicSharedMemorySize, 98304);

    prologue_kernel<<<(NVEC + KCODES + 255) / 256, 256>>>(z, emb);
    argmin_kernel<<<GRID_P, 256, 98304>>>(z, emb);
    combine_kernel<<<NVEC / 256, 256>>>();
    gather_kernel<<<ZELEMS / 256, 256>>>(z, emb, out);
    tail_kernel<<<(NVEC + 255) / 256, 256>>>(out, out_size);
}

// round 5
// speedup vs baseline: 2.1855x; 2.1855x over previous
#include <cuda_runtime.h>
#include <cuda_bf16.h>
#include <math_constants.h>

#define NVEC   16384
#define KCODES 8192
#define CDIM   256
#define ZELEMS (16*256*32*32)   /* 4194304 */
#define MARGIN 5e-4f

__device__ float  g_zz[NVEC];
__device__ float  g_ee[KCODES];
__device__ int    g_idx[NVEC];
__device__ double g_loss;
__device__ __nv_bfloat16 g_Zh[NVEC * CDIM];
__device__ __nv_bfloat16 g_Zl[NVEC * CDIM];
__device__ __nv_bfloat16 g_Eh[KCODES * CDIM];
__device__ __nv_bfloat16 g_El[KCODES * CDIM];
__device__ float  g_stmin[(size_t)NVEC * 256];   /* per (n, 32-k subtile) approx min */

// ---------------------------------------------------------------------------
__device__ __forceinline__ unsigned smem_u32(const void* p) {
    return (unsigned)__cvta_generic_to_shared(p);
}
__device__ __forceinline__ void ldsm4(unsigned& r0, unsigned& r1,
                                      unsigned& r2, unsigned& r3, unsigned a) {
    asm volatile("ldmatrix.sync.aligned.m8n8.x4.shared.b16 {%0,%1,%2,%3}, [%4];"
                 : "=r"(r0), "=r"(r1), "=r"(r2), "=r"(r3) : "r"(a));
}
__device__ __forceinline__ void mma16816(float* c, const unsigned* a, const unsigned* b) {
    asm volatile("mma.sync.aligned.m16n8k16.row.col.f32.bf16.bf16.f32 "
                 "{%0,%1,%2,%3},{%4,%5,%6,%7},{%8,%9},{%0,%1,%2,%3};"
                 : "+f"(c[0]), "+f"(c[1]), "+f"(c[2]), "+f"(c[3])
                 : "r"(a[0]), "r"(a[1]), "r"(a[2]), "r"(a[3]), "r"(b[0]), "r"(b[1]));
}
__device__ __forceinline__ void cp16(unsigned s, const void* g) {
    asm volatile("cp.async.cg.shared.global [%0], [%1], 16;" :: "r"(s), "l"(g));
}

// ---------------------------------------------------------------------------
// zz[n], ee[k]: exact fp32 (sequential mul+add, validated bit-exact recipe)
// ---------------------------------------------------------------------------
__global__ void prologue_kernel(const float* __restrict__ z,
                                const float* __restrict__ emb) {
    int i = blockIdx.x * blockDim.x + threadIdx.x;
    if (i == 0) g_loss = 0.0;
    if (i < NVEC) {
        int b = i >> 10, hw = i & 1023;
        const float* p = z + (size_t)b * 262144 + hw;
        float acc = 0.f;
        #pragma unroll 8
        for (int c = 0; c < CDIM; c++) {
            float v = p[(size_t)c * 1024];
            acc = __fadd_rn(acc, __fmul_rn(v, v));
        }
        g_zz[i] = acc;
    } else if (i < NVEC + KCODES) {
        int k = i - NVEC;
        const float* p = emb + (size_t)k * CDIM;
        float acc = 0.f;
        #pragma unroll 8
        for (int c = 0; c < CDIM; c++) {
            float v = p[c];
            acc = __fadd_rn(acc, __fmul_rn(v, v));
        }
        g_ee[k] = acc;
    }
}

// ---------------------------------------------------------------------------
// bf16 2-term splits
// ---------------------------------------------------------------------------
__global__ void split_z_kernel(const float* __restrict__ z) {
    int idx = blockIdx.x * 256 + threadIdx.x;       // 16384*64
    int n = idx >> 6, cq = idx & 63;
    int b = n >> 10, hw = n & 1023;
    #pragma unroll
    for (int j = 0; j < 4; j++) {
        float v = z[(size_t)b * 262144 + (size_t)(cq * 4 + j) * 1024 + hw];
        __nv_bfloat16 h = __float2bfloat16_rn(v);
        __nv_bfloat16 l = __float2bfloat16_rn(v - __bfloat162float(h));
        g_Zh[(size_t)n * 256 + cq * 4 + j] = h;
        g_Zl[(size_t)n * 256 + cq * 4 + j] = l;
    }
}
__global__ void split_e_kernel(const float* __restrict__ emb) {
    int idx = blockIdx.x * 256 + threadIdx.x;       // 8192*32
    int k = idx >> 5, cq = idx & 31;
    #pragma unroll
    for (int j = 0; j < 8; j++) {
        float v = emb[(size_t)k * 256 + cq * 8 + j];
        __nv_bfloat16 h = __float2bfloat16_rn(v);
        __nv_bfloat16 l = __float2bfloat16_rn(v - __bfloat162float(h));
        g_Eh[(size_t)k * 256 + cq * 8 + j] = h;
        g_El[(size_t)k * 256 + cq * 8 + j] = l;
    }
}

// ---------------------------------------------------------------------------
// Filter GEMM: dot~ = Zh*Eh + Zl*Eh + Zh*El (K=768 concatenated), fp32 acc.
// CTA 128n x 128k, 8 warps (2x4), warp 64x32, mma m16n8k16 bf16.
// Epilogue: d~ = fl(fl(zz+ee) - fl(2*dot~)); per-(row, 32k-subtile) min
// -> g_stmin. Warp's 32-k span == exactly one subtile.
// ---------------------------------------------------------------------------
__global__ __launch_bounds__(256, 2)
void filter_gemm_kernel() {
    extern __shared__ char sm[];
    const unsigned smA = smem_u32(sm);
    const unsigned smB = smA + 32768;

    const int t = threadIdx.x;
    const int lane = t & 31, warp = t >> 5;
    const int wm = warp >> 2, wn = warp & 3;
    const int bm = blockIdx.x >> 6, bn = blockIdx.x & 63;

    const __nv_bfloat16* segA[3] = { g_Zh, g_Zl, g_Zh };
    const __nv_bfloat16* segB[3] = { g_Eh, g_Eh, g_El };

    float acc[4][4][4];
    #pragma unroll
    for (int mi = 0; mi < 4; mi++)
        #pragma unroll
        for (int ni = 0; ni < 4; ni++)
            #pragma unroll
            for (int r = 0; r < 4; r++) acc[mi][ni][r] = 0.f;

    // ldmatrix lane constants
    const int rA = lane & 15, cAsel = lane >> 4, l7 = lane & 7;
    const int rB = (lane & 7) + ((lane >> 4) << 3), cBsel = (lane >> 3) & 1;

    // loader: idx = i*256+t -> row = idx>>3, ch = idx&7 (16B chunks of 64-col rows)
    const int lrow = t >> 3, lch = t & 7;
    const unsigned ldst_off = (unsigned)(lrow * 128 + ((lch ^ (lrow & 7)) << 4));

    #define ISSUE_CHUNK(q, buf) do {                                          \
        int seg_ = (q) >> 2, coff_ = ((q) & 3) * 64;                           \
        const __nv_bfloat16* pa_ = segA[seg_];                                 \
        const __nv_bfloat16* pb_ = segB[seg_];                                 \
        _Pragma("unroll")                                                      \
        for (int i_ = 0; i_ < 4; i_++) {                                       \
            int row_ = lrow + i_ * 32;                                         \
            unsigned off_ = ldst_off + i_ * 32 * 128;                          \
            cp16(smA + (buf) * 16384 + off_,                                   \
                 pa_ + (size_t)(bm * 128 + row_) * 256 + coff_ + lch * 8);     \
            cp16(smB + (buf) * 16384 + off_,                                   \
                 pb_ + (size_t)(bn * 128 + row_) * 256 + coff_ + lch * 8);     \
        }                                                                      \
        asm volatile("cp.async.commit_group;");                                \
    } while (0)

    ISSUE_CHUNK(0, 0);

    #pragma unroll 1
    for (int q = 0; q < 12; q++) {
        if (q < 11) {
            ISSUE_CHUNK(q + 1, (q + 1) & 1);
            asm volatile("cp.async.wait_group 1;");
        } else {
            asm volatile("cp.async.wait_group 0;");
        }
        __syncthreads();

        const unsigned Ab = smA + (q & 1) * 16384;
        const unsigned Bb = smB + (q & 1) * 16384;

        #pragma unroll
        for (int ks = 0; ks < 4; ks++) {
            unsigned a[4][4], b[4][2];
            #pragma unroll
            for (int mi = 0; mi < 4; mi++) {
                int row = wm * 64 + mi * 16 + rA;
                unsigned ad = Ab + row * 128 + (((2 * ks + cAsel) ^ l7) << 4);
                ldsm4(a[mi][0], a[mi][1], a[mi][2], a[mi][3], ad);
            }
            #pragma unroll
            for (int nj = 0; nj < 2; nj++) {
                int row = wn * 32 + nj * 16 + rB;
                unsigned bd = Bb + row * 128 + (((2 * ks + cBsel) ^ l7) << 4);
                unsigned r0, r1, r2, r3;
                ldsm4(r0, r1, r2, r3, bd);
                b[2 * nj][0] = r0; b[2 * nj][1] = r1;
                b[2 * nj + 1][0] = r2; b[2 * nj + 1][1] = r3;
            }
            #pragma unroll
            for (int mi = 0; mi < 4; mi++)
                #pragma unroll
                for (int ni = 0; ni < 4; ni++)
                    mma16816(acc[mi][ni], a[mi], b[ni]);
        }
        __syncthreads();
    }

    // epilogue
    const int stIdx = bn * 4 + wn;
    #pragma unroll
    for (int mi = 0; mi < 4; mi++) {
        int r0 = bm * 128 + wm * 64 + mi * 16 + (lane >> 2);
        int r1 = r0 + 8;
        float zz0 = g_zz[r0], zz1 = g_zz[r1];
        float vlo = CUDART_INF_F, vhi = CUDART_INF_F;
        #pragma unroll
        for (int ni = 0; ni < 4; ni++) {
            int col = bn * 128 + wn * 32 + ni * 8 + (lane & 3) * 2;
            float e0 = g_ee[col], e1 = g_ee[col + 1];
            float d00 = __fsub_rn(__fadd_rn(zz0, e0), __fmul_rn(2.f, acc[mi][ni][0]));
            float d01 = __fsub_rn(__fadd_rn(zz0, e1), __fmul_rn(2.f, acc[mi][ni][1]));
            float d10 = __fsub_rn(__fadd_rn(zz1, e0), __fmul_rn(2.f, acc[mi][ni][2]));
            float d11 = __fsub_rn(__fadd_rn(zz1, e1), __fmul_rn(2.f, acc[mi][ni][3]));
            vlo = fminf(vlo, fminf(d00, d01));
            vhi = fminf(vhi, fminf(d10, d11));
        }
        vlo = fminf(vlo, __shfl_xor_sync(0xffffffffu, vlo, 1));
        vlo = fminf(vlo, __shfl_xor_sync(0xffffffffu, vlo, 2));
        vhi = fminf(vhi, __shfl_xor_sync(0xffffffffu, vhi, 1));
        vhi = fminf(vhi, __shfl_xor_sync(0xffffffffu, vhi, 2));
        if ((lane & 3) == 0) {
            g_stmin[(size_t)r0 * 256 + stIdx] = vlo;
            g_stmin[(size_t)r1 * 256 + stIdx] = vhi;
        }
    }
}

// ---------------------------------------------------------------------------
// Rescore: per n (one block, 128 thr): global approx min m*, flag subtiles
// with stmin <= m* + MARGIN, exact bit-matched rescore of flagged ks
// (sequential fmaf c=0..255, rn chain), lexicographic (d, k) argmin.
// ---------------------------------------------------------------------------
__global__ __launch_bounds__(128)
void rescore_kernel(const float* __restrict__ z, const float* __restrict__ emb) {
    __shared__ float zrow[256];
    __shared__ float es[32 * 257];
    __shared__ short s_list[256];
    __shared__ int   s_cnt;

    const int n = blockIdx.x;
    const int t = threadIdx.x;
    const int b = n >> 10, hw = n & 1023;

    // z row (exact fp32)
    zrow[t]       = z[(size_t)b * 262144 + (size_t)t * 1024 + hw];
    zrow[t + 128] = z[(size_t)b * 262144 + (size_t)(t + 128) * 1024 + hw];

    // warp 0: min + flagged-subtile list
    if (t < 32) {
        float4 va = *(const float4*)&g_stmin[(size_t)n * 256 + t * 8];
        float4 vb = *(const float4*)&g_stmin[(size_t)n * 256 + t * 8 + 4];
        float v[8] = { va.x, va.y, va.z, va.w, vb.x, vb.y, vb.z, vb.w };
        float mn = v[0];
        #pragma unroll
        for (int j = 1; j < 8; j++) mn = fminf(mn, v[j]);
        #pragma unroll
        for (int o = 16; o; o >>= 1) mn = fminf(mn, __shfl_xor_sync(0xffffffffu, mn, o));
        float thr = mn + MARGIN;
        if (t == 0) s_cnt = 0;
        __syncwarp();
        #pragma unroll
        for (int j = 0; j < 8; j++) {
            unsigned msk = __ballot_sync(0xffffffffu, v[j] <= thr);
            if (t == 0) {
                while (msk) {
                    int bit = __ffs(msk) - 1;
                    msk &= msk - 1;
                    s_list[s_cnt++] = (short)(bit * 8 + j);
                }
            }
        }
    }
    __syncthreads();

    const float zzv = g_zz[n];
    float bd = CUDART_INF_F; int bk = 0x7fffffff;
    const int cnt = s_cnt;

    for (int i = 0; i < cnt; i++) {
        const int st = s_list[i];
        // stage e subtile [32 k][256 c] fp32, padded rows
        #pragma unroll
        for (int q = 0; q < 16; q++) {
            int idx = q * 128 + t;                 // 2048 float4
            int row = idx >> 6, c4 = idx & 63;
            float4 w = *(const float4*)&emb[(size_t)(st * 32 + row) * 256 + c4 * 4];
            float* d = &es[row * 257 + c4 * 4];
            d[0] = w.x; d[1] = w.y; d[2] = w.z; d[3] = w.w;
        }
        __syncthreads();
        if (t < 32) {
            const float* er = &es[t * 257];
            float a0 = 0.f;
            #pragma unroll 8
            for (int c = 0; c < 256; c++) a0 = fmaf(zrow[c], er[c], a0);
            int k = st * 32 + t;
            float d = __fsub_rn(__fadd_rn(zzv, g_ee[k]), __fmul_rn(2.f, a0));
            if (d < bd || (d == bd && k < bk)) { bd = d; bk = k; }
        }
        __syncthreads();
    }

    if (t < 32) {
        #pragma unroll
        for (int o = 16; o; o >>= 1) {
            float od = __shfl_xor_sync(0xffffffffu, bd, o);
            int   ok = __shfl_xor_sync(0xffffffffu, bk, o);
            if (od < bd || (od == bd && ok < bk)) { bd = od; bk = ok; }
        }
        if (t == 0) g_idx[n] = bk;
    }
}

// ---------------------------------------------------------------------------
// out[o] = fl(z + fl(zq - z)) ; loss = sum fl(zq-z)^2
// ---------------------------------------------------------------------------
__global__ void gather_kernel(const float* __restrict__ z,
                              const float* __restrict__ emb,
                              float* __restrict__ out) {
    int o = blockIdx.x * 256 + threadIdx.x;
    int rem = o & 262143;
    int b  = o >> 18;
    int c  = rem >> 10;
    int hw = rem & 1023;
    int n  = (b << 10) + hw;
    float zv = z[o];
    float q  = emb[(size_t)g_idx[n] * CDIM + c];
    float diff = __fsub_rn(q, zv);
    out[o] = __fadd_rn(zv, diff);
    float d2 = __fmul_rn(diff, diff);

    __shared__ float red[256];
    red[threadIdx.x] = d2;
    __syncthreads();
    for (int s = 128; s > 0; s >>= 1) {
        if (threadIdx.x < s) red[threadIdx.x] += red[threadIdx.x + s];
        __syncthreads();
    }
    if (threadIdx.x == 0) atomicAdd(&g_loss, (double)red[0]);
}

__global__ void tail_kernel(float* __restrict__ out, int out_size) {
    int i = blockIdx.x * 256 + threadIdx.x;
    if (i < NVEC && out_size >= ZELEMS + NVEC)
        out[ZELEMS + i] = (float)g_idx[i];
    if (i == 0 && out_size >= ZELEMS + NVEC + 1) {
        float m = (float)(g_loss / (double)ZELEMS);
        out[ZELEMS + NVEC] = __fadd_rn(m, __fmul_rn(0.25f, m)); // m + BETA*m
    }
}

// ---------------------------------------------------------------------------
extern "C" void kernel_launch(void* const* d_in, const int* in_sizes, int n_in,
                              void* d_out, int out_size) {
    const float* z   = (const float*)d_in[0];
    const float* emb = (const float*)d_in[1];
    float* out = (float*)d_out;

    cudaFuncSetAttribute(filter_gemm_kernel,
                         cudaFuncAttributeMaxDynamicSharedMemorySize, 65536);

    prologue_kernel<<<(NVEC + KCODES + 255) / 256, 256>>>(z, emb);
    split_z_kernel<<<NVEC * 64 / 256, 256>>>(z);
    split_e_kernel<<<KCODES * 32 / 256, 256>>>(emb);
    filter_gemm_kernel<<<128 * 64, 256, 65536>>>();
    rescore_kernel<<<NVEC, 128>>>(z, emb);
    gather_kernel<<<ZELEMS / 256, 256>>>(z, emb, out);
    tail_kernel<<<(NVEC + 255) / 256, 256>>>(out, out_size);
}

// round 6
// speedup vs baseline: 3.9539x; 1.8091x over previous
#include <cuda_runtime.h>
#include <cuda_bf16.h>
#include <math_constants.h>

#define NVEC   16384
#define KCODES 8192
#define CDIM   256
#define ZELEMS (16*256*32*32)   /* 4194304 */
#define UNITS  1024             /* per-n units of 8 k */
#define MARGIN 4e-4f
#define CAND_MAX (1u<<22)

__device__ float  g_zz[NVEC];
__device__ float  g_ee[KCODES];
__device__ int    g_idx[NVEC];
__device__ double g_loss;
__device__ __nv_bfloat16 g_Zh[(size_t)NVEC * CDIM];
__device__ __nv_bfloat16 g_Eh[(size_t)KCODES * CDIM];
__device__ float  g_stmin[(size_t)NVEC * UNITS];       /* 64MB: per (n, 8k-unit) approx min */
__device__ unsigned g_cand[CAND_MAX];
__device__ unsigned g_ncand;
__device__ unsigned long long g_best[NVEC];

// ---------------------------------------------------------------------------
__device__ __forceinline__ unsigned smem_u32(const void* p) {
    return (unsigned)__cvta_generic_to_shared(p);
}
__device__ __forceinline__ void ldsm4(unsigned& r0, unsigned& r1,
                                      unsigned& r2, unsigned& r3, unsigned a) {
    asm volatile("ldmatrix.sync.aligned.m8n8.x4.shared.b16 {%0,%1,%2,%3}, [%4];"
                 : "=r"(r0), "=r"(r1), "=r"(r2), "=r"(r3) : "r"(a));
}
__device__ __forceinline__ void mma16816(float* c, const unsigned* a, const unsigned* b) {
    asm volatile("mma.sync.aligned.m16n8k16.row.col.f32.bf16.bf16.f32 "
                 "{%0,%1,%2,%3},{%4,%5,%6,%7},{%8,%9},{%0,%1,%2,%3};"
                 : "+f"(c[0]), "+f"(c[1]), "+f"(c[2]), "+f"(c[3])
                 : "r"(a[0]), "r"(a[1]), "r"(a[2]), "r"(a[3]), "r"(b[0]), "r"(b[1]));
}
__device__ __forceinline__ void cp16(unsigned s, const void* g) {
    asm volatile("cp.async.cg.shared.global [%0], [%1], 16;" :: "r"(s), "l"(g));
}

// ---------------------------------------------------------------------------
// zz[n], ee[k]: exact fp32 (sequential mul+add, validated); reset state.
// ---------------------------------------------------------------------------
__global__ void prologue_kernel(const float* __restrict__ z,
                                const float* __restrict__ emb) {
    int i = blockIdx.x * blockDim.x + threadIdx.x;
    if (i == 0) { g_loss = 0.0; g_ncand = 0u; }
    if (i < NVEC) {
        g_best[i] = 0xFFFFFFFFFFFFFFFFull;
        int b = i >> 10, hw = i & 1023;
        const float* p = z + (size_t)b * 262144 + hw;
        float acc = 0.f;
        #pragma unroll 8
        for (int c = 0; c < CDIM; c++) {
            float v = p[(size_t)c * 1024];
            acc = __fadd_rn(acc, __fmul_rn(v, v));
        }
        g_zz[i] = acc;
    } else if (i < NVEC + KCODES) {
        int k = i - NVEC;
        const float* p = emb + (size_t)k * CDIM;
        float acc = 0.f;
        #pragma unroll 8
        for (int c = 0; c < CDIM; c++) {
            float v = p[c];
            acc = __fadd_rn(acc, __fmul_rn(v, v));
        }
        g_ee[k] = acc;
    }
}

// ---------------------------------------------------------------------------
// bf16 high parts only (single-segment filter). Coalesced layouts.
// ---------------------------------------------------------------------------
__global__ void split_z_kernel(const float* __restrict__ z) {
    int idx = blockIdx.x * 256 + threadIdx.x;   // 16384*64
    int n = idx & 16383, cq = idx >> 14;        // consecutive t -> consecutive n (coalesced reads)
    int b = n >> 10, hw = n & 1023;
    #pragma unroll
    for (int j = 0; j < 4; j++) {
        float v = z[(size_t)b * 262144 + (size_t)(cq * 4 + j) * 1024 + hw];
        g_Zh[(size_t)n * 256 + cq * 4 + j] = __float2bfloat16_rn(v);
    }
}
__global__ void split_e_kernel(const float* __restrict__ emb) {
    int idx = blockIdx.x * 256 + threadIdx.x;   // 8192*32
    int k = idx >> 5, cq = idx & 31;
    #pragma unroll
    for (int j = 0; j < 8; j++) {
        float v = emb[(size_t)k * 256 + cq * 8 + j];
        g_Eh[(size_t)k * 256 + cq * 8 + j] = __float2bfloat16_rn(v);
    }
}

// ---------------------------------------------------------------------------
// Filter GEMM: dot~ = Zh*Eh (K=256), fp32 acc. CTA 128n x 128k, 8 warps (2x4),
// warp 64x32, mma m16n8k16. Epilogue: d~ per (row, 8k-unit) min -> smem
// transpose -> coalesced g_stmin.
// ---------------------------------------------------------------------------
__global__ __launch_bounds__(256, 2)
void filter_gemm_kernel() {
    extern __shared__ char sm[];
    const unsigned smA = smem_u32(sm);
    const unsigned smB = smA + 32768;

    const int t = threadIdx.x;
    const int lane = t & 31, warp = t >> 5;
    const int wm = warp >> 2, wn = warp & 3;
    const int bm = blockIdx.x >> 6, bn = blockIdx.x & 63;

    float acc[4][4][4];
    #pragma unroll
    for (int mi = 0; mi < 4; mi++)
        #pragma unroll
        for (int ni = 0; ni < 4; ni++)
            #pragma unroll
            for (int r = 0; r < 4; r++) acc[mi][ni][r] = 0.f;

    const int rA = lane & 15, cAsel = lane >> 4, l7 = lane & 7;
    const int rB = (lane & 7) + ((lane >> 4) << 3), cBsel = (lane >> 3) & 1;

    const int lrow = t >> 3, lch = t & 7;
    const unsigned ldst_off = (unsigned)(lrow * 128 + ((lch ^ (lrow & 7)) << 4));

    #define ISSUE_CHUNK(q, buf) do {                                          \
        int coff_ = (q) * 64;                                                  \
        _Pragma("unroll")                                                      \
        for (int i_ = 0; i_ < 4; i_++) {                                       \
            int row_ = lrow + i_ * 32;                                         \
            unsigned off_ = ldst_off + i_ * 32 * 128;                          \
            cp16(smA + (buf) * 16384 + off_,                                   \
                 g_Zh + (size_t)(bm * 128 + row_) * 256 + coff_ + lch * 8);    \
            cp16(smB + (buf) * 16384 + off_,                                   \
                 g_Eh + (size_t)(bn * 128 + row_) * 256 + coff_ + lch * 8);    \
        }                                                                      \
        asm volatile("cp.async.commit_group;");                                \
    } while (0)

    ISSUE_CHUNK(0, 0);

    #pragma unroll 1
    for (int q = 0; q < 4; q++) {
        if (q < 3) {
            ISSUE_CHUNK(q + 1, (q + 1) & 1);
            asm volatile("cp.async.wait_group 1;");
        } else {
            asm volatile("cp.async.wait_group 0;");
        }
        __syncthreads();

        const unsigned Ab = smA + (q & 1) * 16384;
        const unsigned Bb = smB + (q & 1) * 16384;

        #pragma unroll
        for (int ks = 0; ks < 4; ks++) {
            unsigned a[4][4], b[4][2];
            #pragma unroll
            for (int mi = 0; mi < 4; mi++) {
                int row = wm * 64 + mi * 16 + rA;
                unsigned ad = Ab + row * 128 + (((2 * ks + cAsel) ^ l7) << 4);
                ldsm4(a[mi][0], a[mi][1], a[mi][2], a[mi][3], ad);
            }
            #pragma unroll
            for (int nj = 0; nj < 2; nj++) {
                int row = wn * 32 + nj * 16 + rB;
                unsigned bd = Bb + row * 128 + (((2 * ks + cBsel) ^ l7) << 4);
                unsigned r0, r1, r2, r3;
                ldsm4(r0, r1, r2, r3, bd);
                b[2 * nj][0] = r0; b[2 * nj][1] = r1;
                b[2 * nj + 1][0] = r2; b[2 * nj + 1][1] = r3;
            }
            #pragma unroll
            for (int mi = 0; mi < 4; mi++)
                #pragma unroll
                for (int ni = 0; ni < 4; ni++)
                    mma16816(acc[mi][ni], a[mi], b[ni]);
        }
        __syncthreads();
    }

    // epilogue: per-(row, 8k-unit) min -> smem [128 rows][16 units] -> coalesced store
    float* st = (float*)sm;   // 8KB reuse
    #pragma unroll
    for (int mi = 0; mi < 4; mi++) {
        int rl0 = wm * 64 + mi * 16 + (lane >> 2);
        int r0 = bm * 128 + rl0;
        float zz0 = g_zz[r0], zz1 = g_zz[r0 + 8];
        #pragma unroll
        for (int ni = 0; ni < 4; ni++) {
            int col = bn * 128 + wn * 32 + ni * 8 + (lane & 3) * 2;
            float e0 = g_ee[col], e1 = g_ee[col + 1];
            float d00 = __fsub_rn(__fadd_rn(zz0, e0), __fmul_rn(2.f, acc[mi][ni][0]));
            float d01 = __fsub_rn(__fadd_rn(zz0, e1), __fmul_rn(2.f, acc[mi][ni][1]));
            float d10 = __fsub_rn(__fadd_rn(zz1, e0), __fmul_rn(2.f, acc[mi][ni][2]));
            float d11 = __fsub_rn(__fadd_rn(zz1, e1), __fmul_rn(2.f, acc[mi][ni][3]));
            float vlo = fminf(d00, d01), vhi = fminf(d10, d11);
            vlo = fminf(vlo, __shfl_xor_sync(0xffffffffu, vlo, 1));
            vlo = fminf(vlo, __shfl_xor_sync(0xffffffffu, vlo, 2));
            vhi = fminf(vhi, __shfl_xor_sync(0xffffffffu, vhi, 1));
            vhi = fminf(vhi, __shfl_xor_sync(0xffffffffu, vhi, 2));
            if ((lane & 3) == 0) {
                st[rl0 * 16 + wn * 4 + ni] = vlo;
                st[(rl0 + 8) * 16 + wn * 4 + ni] = vhi;
            }
        }
    }
    __syncthreads();
    // 2048 floats: thread t writes 8 floats (2 float4)
    {
        int rl = t >> 1, u0 = (t & 1) * 8;
        float* dst = &g_stmin[(size_t)(bm * 128 + rl) * UNITS + bn * 16 + u0];
        float* src = &st[rl * 16 + u0];
        *(float4*)dst = *(float4*)src;
        *(float4*)(dst + 4) = *(float4*)(src + 4);
    }
}

// ---------------------------------------------------------------------------
// Extraction: warp per n. Global min over 1024 unit-mins, flag units within
// MARGIN, append (n<<10|unit) to global candidate list.
// ---------------------------------------------------------------------------
__global__ __launch_bounds__(256)
void extract_kernel() {
    int n = (blockIdx.x * 256 + threadIdx.x) >> 5;
    int lane = threadIdx.x & 31;
    if (n >= NVEC) return;
    const float4* row = (const float4*)&g_stmin[(size_t)n * UNITS];

    float4 v[8];
    float mn = CUDART_INF_F;
    #pragma unroll
    for (int j = 0; j < 8; j++) {
        v[j] = row[j * 32 + lane];
        mn = fminf(mn, fminf(fminf(v[j].x, v[j].y), fminf(v[j].z, v[j].w)));
    }
    #pragma unroll
    for (int o = 16; o; o >>= 1) mn = fminf(mn, __shfl_xor_sync(0xffffffffu, mn, o));
    const float thr = mn + MARGIN;

    unsigned cnt = 0;
    #pragma unroll
    for (int j = 0; j < 8; j++) {
        cnt += (v[j].x <= thr) + (v[j].y <= thr) + (v[j].z <= thr) + (v[j].w <= thr);
    }
    // exclusive warp scan
    unsigned p = cnt;
    #pragma unroll
    for (int o = 1; o < 32; o <<= 1) {
        unsigned tv = __shfl_up_sync(0xffffffffu, p, o);
        if (lane >= o) p += tv;
    }
    unsigned excl = p - cnt;
    unsigned total = __shfl_sync(0xffffffffu, p, 31);
    unsigned base = 0;
    if (lane == 31) base = atomicAdd(&g_ncand, total);
    base = __shfl_sync(0xffffffffu, base, 31);

    unsigned w = base + excl;
    #pragma unroll
    for (int j = 0; j < 8; j++) {
        int u0 = (j * 32 + lane) * 4;
        float vv[4] = { v[j].x, v[j].y, v[j].z, v[j].w };
        #pragma unroll
        for (int c = 0; c < 4; c++)
            if (vv[c] <= thr && w < CAND_MAX)
                g_cand[w++] = ((unsigned)n << 10) | (unsigned)(u0 + c);
    }
}

// ---------------------------------------------------------------------------
// Rescore: persistent, warp per candidate (n, 8k-unit). Stage emb unit (8KB,
// contiguous) into padded smem; 8 lanes run the bit-exact sequential-fma dot;
// lexicographic (d_bits, k) min -> atomicMin(g_best[n]).
// ---------------------------------------------------------------------------
#define RS_BLOCKS 592
__global__ __launch_bounds__(128)
void rescore_kernel(const float* __restrict__ z, const float* __restrict__ emb) {
    __shared__ float es[4][8 * 260];
    const int warp = threadIdx.x >> 5, lane = threadIdx.x & 31;
    const int gwarp = blockIdx.x * 4 + warp;
    const int stride = RS_BLOCKS * 4;
    const unsigned ncand = g_ncand;
    float* dst = es[warp];

    for (unsigned ci = gwarp; ci < ncand; ci += stride) {
        unsigned cd = g_cand[ci];
        int n = cd >> 10, unit = cd & 1023;

        const float4* src = (const float4*)(emb + (size_t)unit * 2048);
        #pragma unroll
        for (int j = 0; j < 16; j++) {
            int f = j * 32 + lane;        // 0..511
            int k = f >> 6, c4 = f & 63;
            *(float4*)&dst[k * 260 + c4 * 4] = src[f];
        }
        __syncwarp();
        if (lane < 8) {
            int k = unit * 8 + lane;
            int b = n >> 10, hw = n & 1023;
            const float* zp = z + (size_t)b * 262144 + hw;
            const float* er = &dst[lane * 260];
            float acc = 0.f;
            #pragma unroll 8
            for (int c = 0; c < 256; c++)
                acc = fmaf(zp[(size_t)c * 1024], er[c], acc);
            float d = __fsub_rn(__fadd_rn(g_zz[n], g_ee[k]), __fmul_rn(2.f, acc));
            unsigned long long key =
                ((unsigned long long)__float_as_uint(d) << 32) | (unsigned)k;
            #pragma unroll
            for (int o = 4; o; o >>= 1) {
                unsigned long long ok = __shfl_xor_sync(0xffu, key, o);
                if (ok < key) key = ok;
            }
            if (lane == 0) atomicMin(&g_best[n], key);
        }
        __syncwarp();
    }
}

__global__ void idx_kernel() {
    int n = blockIdx.x * 256 + threadIdx.x;
    if (n < NVEC) g_idx[n] = (int)(unsigned)(g_best[n] & 0xFFFFFFFFull);
}

// ---------------------------------------------------------------------------
// out[o] = fl(z + fl(zq - z)) ; loss = sum fl(zq-z)^2
// ---------------------------------------------------------------------------
__global__ void gather_kernel(const float* __restrict__ z,
                              const float* __restrict__ emb,
                              float* __restrict__ out) {
    int o = blockIdx.x * 256 + threadIdx.x;
    int rem = o & 262143;
    int b  = o >> 18;
    int c  = rem >> 10;
    int hw = rem & 1023;
    int n  = (b << 10) + hw;
    float zv = z[o];
    float q  = emb[(size_t)g_idx[n] * CDIM + c];
    float diff = __fsub_rn(q, zv);
    out[o] = __fadd_rn(zv, diff);
    float d2 = __fmul_rn(diff, diff);

    #pragma unroll
    for (int off = 16; off; off >>= 1)
        d2 += __shfl_xor_sync(0xffffffffu, d2, off);
    __shared__ float red[8];
    if ((threadIdx.x & 31) == 0) red[threadIdx.x >> 5] = d2;
    __syncthreads();
    if (threadIdx.x < 8) {
        float s = red[threadIdx.x];
        #pragma unroll
        for (int off = 4; off; off >>= 1)
            s += __shfl_xor_sync(0xffu, s, off);
        if (threadIdx.x == 0) atomicAdd(&g_loss, (double)s);
    }
}

__global__ void tail_kernel(float* __restrict__ out, int out_size) {
    int i = blockIdx.x * 256 + threadIdx.x;
    if (i < NVEC && out_size >= ZELEMS + NVEC)
        out[ZELEMS + i] = (float)g_idx[i];
    if (i == 0 && out_size >= ZELEMS + NVEC + 1) {
        float m = (float)(g_loss / (double)ZELEMS);
        out[ZELEMS + NVEC] = __fadd_rn(m, __fmul_rn(0.25f, m)); // m + BETA*m
    }
}

// ---------------------------------------------------------------------------
extern "C" void kernel_launch(void* const* d_in, const int* in_sizes, int n_in,
                              void* d_out, int out_size) {
    const float* z   = (const float*)d_in[0];
    const float* emb = (const float*)d_in[1];
    float* out = (float*)d_out;

    cudaFuncSetAttribute(filter_gemm_kernel,
                         cudaFuncAttributeMaxDynamicSharedMemorySize, 65536);

    prologue_kernel<<<(NVEC + KCODES + 255) / 256, 256>>>(z, emb);
    split_z_kernel<<<NVEC * 64 / 256, 256>>>(z);
    split_e_kernel<<<KCODES * 32 / 256, 256>>>(emb);
    filter_gemm_kernel<<<128 * 64, 256, 65536>>>();
    extract_kernel<<<NVEC * 32 / 256, 256>>>();
    rescore_kernel<<<RS_BLOCKS, 128>>>(z, emb);
    idx_kernel<<<NVEC / 256, 256>>>();
    gather_kernel<<<ZELEMS / 256, 256>>>(z, emb, out);
    tail_kernel<<<(NVEC + 255) / 256, 256>>>(out, out_size);
}

// round 7
// speedup vs baseline: 3.9624x; 1.0022x over previous
#include <cuda_runtime.h>
#include <cuda_bf16.h>
#include <math_constants.h>

#define NVEC   16384
#define KCODES 8192
#define CDIM   256
#define ZELEMS (16*256*32*32)   /* 4194304 */
#define UNITS  1024             /* per-n units of 8 k */
#define MARGIN 4e-4f
#define CAND_MAX (1u<<22)

__device__ float  g_zz[NVEC];
__device__ float  g_ee[KCODES];
__device__ int    g_idx[NVEC];
__device__ double g_loss;
__device__ __nv_bfloat16 g_Zh[(size_t)NVEC * CDIM];
__device__ __nv_bfloat16 g_Eh[(size_t)KCODES * CDIM];
__device__ float  g_stmin[(size_t)NVEC * UNITS];       /* 64MB: per (n, 8k-unit) approx min */
__device__ unsigned g_cand[CAND_MAX];
__device__ unsigned g_ncand;
__device__ unsigned long long g_best[NVEC];

// ---------------------------------------------------------------------------
__device__ __forceinline__ unsigned smem_u32(const void* p) {
    return (unsigned)__cvta_generic_to_shared(p);
}
__device__ __forceinline__ void ldsm4(unsigned& r0, unsigned& r1,
                                      unsigned& r2, unsigned& r3, unsigned a) {
    asm volatile("ldmatrix.sync.aligned.m8n8.x4.shared.b16 {%0,%1,%2,%3}, [%4];"
                 : "=r"(r0), "=r"(r1), "=r"(r2), "=r"(r3) : "r"(a));
}
__device__ __forceinline__ void mma16816(float* c, const unsigned* a, const unsigned* b) {
    asm volatile("mma.sync.aligned.m16n8k16.row.col.f32.bf16.bf16.f32 "
                 "{%0,%1,%2,%3},{%4,%5,%6,%7},{%8,%9},{%0,%1,%2,%3};"
                 : "+f"(c[0]), "+f"(c[1]), "+f"(c[2]), "+f"(c[3])
                 : "r"(a[0]), "r"(a[1]), "r"(a[2]), "r"(a[3]), "r"(b[0]), "r"(b[1]));
}
__device__ __forceinline__ void cp16(unsigned s, const void* g) {
    asm volatile("cp.async.cg.shared.global [%0], [%1], 16;" :: "r"(s), "l"(g));
}

// ---------------------------------------------------------------------------
// zz[n], ee[k]: exact fp32 (sequential mul+add, validated); reset state.
// ---------------------------------------------------------------------------
__global__ void prologue_kernel(const float* __restrict__ z,
                                const float* __restrict__ emb) {
    int i = blockIdx.x * blockDim.x + threadIdx.x;
    if (i == 0) { g_loss = 0.0; g_ncand = 0u; }
    if (i < NVEC) {
        g_best[i] = 0xFFFFFFFFFFFFFFFFull;
        int b = i >> 10, hw = i & 1023;
        const float* p = z + (size_t)b * 262144 + hw;
        float acc = 0.f;
        #pragma unroll 8
        for (int c = 0; c < CDIM; c++) {
            float v = p[(size_t)c * 1024];
            acc = __fadd_rn(acc, __fmul_rn(v, v));
        }
        g_zz[i] = acc;
    } else if (i < NVEC + KCODES) {
        int k = i - NVEC;
        const float* p = emb + (size_t)k * CDIM;
        float acc = 0.f;
        #pragma unroll 8
        for (int c = 0; c < CDIM; c++) {
            float v = p[c];
            acc = __fadd_rn(acc, __fmul_rn(v, v));
        }
        g_ee[k] = acc;
    }
}

// ---------------------------------------------------------------------------
// bf16 high parts only (single-segment filter). Coalesced layouts.
// ---------------------------------------------------------------------------
__global__ void split_z_kernel(const float* __restrict__ z) {
    int idx = blockIdx.x * 256 + threadIdx.x;   // 16384*64
    int n = idx & 16383, cq = idx >> 14;        // consecutive t -> consecutive n (coalesced reads)
    int b = n >> 10, hw = n & 1023;
    #pragma unroll
    for (int j = 0; j < 4; j++) {
        float v = z[(size_t)b * 262144 + (size_t)(cq * 4 + j) * 1024 + hw];
        g_Zh[(size_t)n * 256 + cq * 4 + j] = __float2bfloat16_rn(v);
    }
}
__global__ void split_e_kernel(const float* __restrict__ emb) {
    int idx = blockIdx.x * 256 + threadIdx.x;   // 8192*32
    int k = idx >> 5, cq = idx & 31;
    #pragma unroll
    for (int j = 0; j < 8; j++) {
        float v = emb[(size_t)k * 256 + cq * 8 + j];
        g_Eh[(size_t)k * 256 + cq * 8 + j] = __float2bfloat16_rn(v);
    }
}

// ---------------------------------------------------------------------------
// Filter GEMM: dot~ = Zh*Eh (K=256), fp32 acc. CTA 128n x 128k, 8 warps (2x4),
// warp 64x32, mma m16n8k16. Epilogue: d~ per (row, 8k-unit) min -> smem
// transpose -> coalesced g_stmin.
// ---------------------------------------------------------------------------
__global__ __launch_bounds__(256, 2)
void filter_gemm_kernel() {
    extern __shared__ char sm[];
    const unsigned smA = smem_u32(sm);
    const unsigned smB = smA + 32768;

    const int t = threadIdx.x;
    const int lane = t & 31, warp = t >> 5;
    const int wm = warp >> 2, wn = warp & 3;
    const int bm = blockIdx.x >> 6, bn = blockIdx.x & 63;

    float acc[4][4][4];
    #pragma unroll
    for (int mi = 0; mi < 4; mi++)
        #pragma unroll
        for (int ni = 0; ni < 4; ni++)
            #pragma unroll
            for (int r = 0; r < 4; r++) acc[mi][ni][r] = 0.f;

    const int rA = lane & 15, cAsel = lane >> 4, l7 = lane & 7;
    const int rB = (lane & 7) + ((lane >> 4) << 3), cBsel = (lane >> 3) & 1;

    const int lrow = t >> 3, lch = t & 7;
    const unsigned ldst_off = (unsigned)(lrow * 128 + ((lch ^ (lrow & 7)) << 4));

    #define ISSUE_CHUNK(q, buf) do {                                          \
        int coff_ = (q) * 64;                                                  \
        _Pragma("unroll")                                                      \
        for (int i_ = 0; i_ < 4; i_++) {                                       \
            int row_ = lrow + i_ * 32;                                         \
            unsigned off_ = ldst_off + i_ * 32 * 128;                          \
            cp16(smA + (buf) * 16384 + off_,                                   \
                 g_Zh + (size_t)(bm * 128 + row_) * 256 + coff_ + lch * 8);    \
            cp16(smB + (buf) * 16384 + off_,                                   \
                 g_Eh + (size_t)(bn * 128 + row_) * 256 + coff_ + lch * 8);    \
        }                                                                      \
        asm volatile("cp.async.commit_group;");                                \
    } while (0)

    ISSUE_CHUNK(0, 0);

    #pragma unroll 1
    for (int q = 0; q < 4; q++) {
        if (q < 3) {
            ISSUE_CHUNK(q + 1, (q + 1) & 1);
            asm volatile("cp.async.wait_group 1;");
        } else {
            asm volatile("cp.async.wait_group 0;");
        }
        __syncthreads();

        const unsigned Ab = smA + (q & 1) * 16384;
        const unsigned Bb = smB + (q & 1) * 16384;

        #pragma unroll
        for (int ks = 0; ks < 4; ks++) {
            unsigned a[4][4], b[4][2];
            #pragma unroll
            for (int mi = 0; mi < 4; mi++) {
                int row = wm * 64 + mi * 16 + rA;
                unsigned ad = Ab + row * 128 + (((2 * ks + cAsel) ^ l7) << 4);
                ldsm4(a[mi][0], a[mi][1], a[mi][2], a[mi][3], ad);
            }
            #pragma unroll
            for (int nj = 0; nj < 2; nj++) {
                int row = wn * 32 + nj * 16 + rB;
                unsigned bd = Bb + row * 128 + (((2 * ks + cBsel) ^ l7) << 4);
                unsigned r0, r1, r2, r3;
                ldsm4(r0, r1, r2, r3, bd);
                b[2 * nj][0] = r0; b[2 * nj][1] = r1;
                b[2 * nj + 1][0] = r2; b[2 * nj + 1][1] = r3;
            }
            #pragma unroll
            for (int mi = 0; mi < 4; mi++)
                #pragma unroll
                for (int ni = 0; ni < 4; ni++)
                    mma16816(acc[mi][ni], a[mi], b[ni]);
        }
        __syncthreads();
    }

    // epilogue: per-(row, 8k-unit) min -> smem [128 rows][16 units] -> coalesced store
    float* st = (float*)sm;   // 8KB reuse
    #pragma unroll
    for (int mi = 0; mi < 4; mi++) {
        int rl0 = wm * 64 + mi * 16 + (lane >> 2);
        int r0 = bm * 128 + rl0;
        float zz0 = g_zz[r0], zz1 = g_zz[r0 + 8];
        #pragma unroll
        for (int ni = 0; ni < 4; ni++) {
            int col = bn * 128 + wn * 32 + ni * 8 + (lane & 3) * 2;
            float e0 = g_ee[col], e1 = g_ee[col + 1];
            float d00 = __fsub_rn(__fadd_rn(zz0, e0), __fmul_rn(2.f, acc[mi][ni][0]));
            float d01 = __fsub_rn(__fadd_rn(zz0, e1), __fmul_rn(2.f, acc[mi][ni][1]));
            float d10 = __fsub_rn(__fadd_rn(zz1, e0), __fmul_rn(2.f, acc[mi][ni][2]));
            float d11 = __fsub_rn(__fadd_rn(zz1, e1), __fmul_rn(2.f, acc[mi][ni][3]));
            float vlo = fminf(d00, d01), vhi = fminf(d10, d11);
            vlo = fminf(vlo, __shfl_xor_sync(0xffffffffu, vlo, 1));
            vlo = fminf(vlo, __shfl_xor_sync(0xffffffffu, vlo, 2));
            vhi = fminf(vhi, __shfl_xor_sync(0xffffffffu, vhi, 1));
            vhi = fminf(vhi, __shfl_xor_sync(0xffffffffu, vhi, 2));
            if ((lane & 3) == 0) {
                st[rl0 * 16 + wn * 4 + ni] = vlo;
                st[(rl0 + 8) * 16 + wn * 4 + ni] = vhi;
            }
        }
    }
    __syncthreads();
    // 2048 floats: thread t writes 8 floats (2 float4)
    {
        int rl = t >> 1, u0 = (t & 1) * 8;
        float* dst = &g_stmin[(size_t)(bm * 128 + rl) * UNITS + bn * 16 + u0];
        float* src = &st[rl * 16 + u0];
        *(float4*)dst = *(float4*)src;
        *(float4*)(dst + 4) = *(float4*)(src + 4);
    }
}

// ---------------------------------------------------------------------------
// Extraction: warp per n. Global min over 1024 unit-mins, flag units within
// MARGIN, append (n<<10|unit) to global candidate list.
// ---------------------------------------------------------------------------
__global__ __launch_bounds__(256)
void extract_kernel() {
    int n = (blockIdx.x * 256 + threadIdx.x) >> 5;
    int lane = threadIdx.x & 31;
    if (n >= NVEC) return;
    const float4* row = (const float4*)&g_stmin[(size_t)n * UNITS];

    float4 v[8];
    float mn = CUDART_INF_F;
    #pragma unroll
    for (int j = 0; j < 8; j++) {
        v[j] = row[j * 32 + lane];
        mn = fminf(mn, fminf(fminf(v[j].x, v[j].y), fminf(v[j].z, v[j].w)));
    }
    #pragma unroll
    for (int o = 16; o; o >>= 1) mn = fminf(mn, __shfl_xor_sync(0xffffffffu, mn, o));
    const float thr = mn + MARGIN;

    unsigned cnt = 0;
    #pragma unroll
    for (int j = 0; j < 8; j++) {
        cnt += (v[j].x <= thr) + (v[j].y <= thr) + (v[j].z <= thr) + (v[j].w <= thr);
    }
    // exclusive warp scan
    unsigned p = cnt;
    #pragma unroll
    for (int o = 1; o < 32; o <<= 1) {
        unsigned tv = __shfl_up_sync(0xffffffffu, p, o);
        if (lane >= o) p += tv;
    }
    unsigned excl = p - cnt;
    unsigned total = __shfl_sync(0xffffffffu, p, 31);
    unsigned base = 0;
    if (lane == 31) base = atomicAdd(&g_ncand, total);
    base = __shfl_sync(0xffffffffu, base, 31);

    unsigned w = base + excl;
    #pragma unroll
    for (int j = 0; j < 8; j++) {
        int u0 = (j * 32 + lane) * 4;
        float vv[4] = { v[j].x, v[j].y, v[j].z, v[j].w };
        #pragma unroll
        for (int c = 0; c < 4; c++)
            if (vv[c] <= thr && w < CAND_MAX)
                g_cand[w++] = ((unsigned)n << 10) | (unsigned)(u0 + c);
    }
}

// ---------------------------------------------------------------------------
// Rescore: persistent, warp per candidate (n, 8k-unit). Stage emb unit (8KB,
// contiguous) into padded smem; 8 lanes run the bit-exact sequential-fma dot;
// lexicographic (d_bits, k) min -> atomicMin(g_best[n]).
// ---------------------------------------------------------------------------
#define RS_BLOCKS 592
__global__ __launch_bounds__(128)
void rescore_kernel(const float* __restrict__ z, const float* __restrict__ emb) {
    __shared__ float es[4][8 * 260];
    const int warp = threadIdx.x >> 5, lane = threadIdx.x & 31;
    const int gwarp = blockIdx.x * 4 + warp;
    const int stride = RS_BLOCKS * 4;
    const unsigned ncand = g_ncand;
    float* dst = es[warp];

    for (unsigned ci = gwarp; ci < ncand; ci += stride) {
        unsigned cd = g_cand[ci];
        int n = cd >> 10, unit = cd & 1023;

        const float4* src = (const float4*)(emb + (size_t)unit * 2048);
        #pragma unroll
        for (int j = 0; j < 16; j++) {
            int f = j * 32 + lane;        // 0..511
            int k = f >> 6, c4 = f & 63;
            *(float4*)&dst[k * 260 + c4 * 4] = src[f];
        }
        __syncwarp();
        if (lane < 8) {
            int k = unit * 8 + lane;
            int b = n >> 10, hw = n & 1023;
            const float* zp = z + (size_t)b * 262144 + hw;
            const float* er = &dst[lane * 260];
            float acc = 0.f;
            #pragma unroll 8
            for (int c = 0; c < 256; c++)
                acc = fmaf(zp[(size_t)c * 1024], er[c], acc);
            float d = __fsub_rn(__fadd_rn(g_zz[n], g_ee[k]), __fmul_rn(2.f, acc));
            unsigned long long key =
                ((unsigned long long)__float_as_uint(d) << 32) | (unsigned)k;
            #pragma unroll
            for (int o = 4; o; o >>= 1) {
                unsigned long long ok = __shfl_xor_sync(0xffu, key, o);
                if (ok < key) key = ok;
            }
            if (lane == 0) atomicMin(&g_best[n], key);
        }
        __syncwarp();
    }
}

__global__ void idx_kernel() {
    int n = blockIdx.x * 256 + threadIdx.x;
    if (n < NVEC) g_idx[n] = (int)(unsigned)(g_best[n] & 0xFFFFFFFFull);
}

// ---------------------------------------------------------------------------
// out[o] = fl(z + fl(zq - z)) ; loss = sum fl(zq-z)^2
// ---------------------------------------------------------------------------
__global__ void gather_kernel(const float* __restrict__ z,
                              const float* __restrict__ emb,
                              float* __restrict__ out) {
    int o = blockIdx.x * 256 + threadIdx.x;
    int rem = o & 262143;
    int b  = o >> 18;
    int c  = rem >> 10;
    int hw = rem & 1023;
    int n  = (b << 10) + hw;
    float zv = z[o];
    float q  = emb[(size_t)g_idx[n] * CDIM + c];
    float diff = __fsub_rn(q, zv);
    out[o] = __fadd_rn(zv, diff);
    float d2 = __fmul_rn(diff, diff);

    #pragma unroll
    for (int off = 16; off; off >>= 1)
        d2 += __shfl_xor_sync(0xffffffffu, d2, off);
    __shared__ float red[8];
    if ((threadIdx.x & 31) == 0) red[threadIdx.x >> 5] = d2;
    __syncthreads();
    if (threadIdx.x < 8) {
        float s = red[threadIdx.x];
        #pragma unroll
        for (int off = 4; off; off >>= 1)
            s += __shfl_xor_sync(0xffu, s, off);
        if (threadIdx.x == 0) atomicAdd(&g_loss, (double)s);
    }
}

__global__ void tail_kernel(float* __restrict__ out, int out_size) {
    int i = blockIdx.x * 256 + threadIdx.x;
    if (i < NVEC && out_size >= ZELEMS + NVEC)
        out[ZELEMS + i] = (float)g_idx[i];
    if (i == 0 && out_size >= ZELEMS + NVEC + 1) {
        float m = (float)(g_loss / (double)ZELEMS);
        out[ZELEMS + NVEC] = __fadd_rn(m, __fmul_rn(0.25f, m)); // m + BETA*m
    }
}

// ---------------------------------------------------------------------------
extern "C" void kernel_launch(void* const* d_in, const int* in_sizes, int n_in,
                              void* d_out, int out_size) {
    const float* z   = (const float*)d_in[0];
    const float* emb = (const float*)d_in[1];
    float* out = (float*)d_out;

    cudaFuncSetAttribute(filter_gemm_kernel,
                         cudaFuncAttributeMaxDynamicSharedMemorySize, 65536);

    prologue_kernel<<<(NVEC + KCODES + 255) / 256, 256>>>(z, emb);
    split_z_kernel<<<NVEC * 64 / 256, 256>>>(z);
    split_e_kernel<<<KCODES * 32 / 256, 256>>>(emb);
    filter_gemm_kernel<<<128 * 64, 256, 65536>>>();
    extract_kernel<<<NVEC * 32 / 256, 256>>>();
    rescore_kernel<<<RS_BLOCKS, 128>>>(z, emb);
    idx_kernel<<<NVEC / 256, 256>>>();
    gather_kernel<<<ZELEMS / 256, 256>>>(z, emb, out);
    tail_kernel<<<(NVEC + 255) / 256, 256>>>(out, out_size);
}

// round 8
// speedup vs baseline: 3.9637x; 1.0003x over previous
#include <cuda_runtime.h>
#include <cuda_bf16.h>
#include <math_constants.h>

#define NVEC   16384
#define KCODES 8192
#define CDIM   256
#define ZELEMS (16*256*32*32)   /* 4194304 */
#define UNITS  1024             /* per-n units of 8 k */
#define MARGIN 4e-4f
#define CAND_MAX (1u<<22)

__device__ float  g_zz[NVEC];
__device__ float  g_ee[KCODES];
__device__ int    g_idx[NVEC];
__device__ double g_loss;
__device__ __nv_bfloat16 g_Zh[(size_t)NVEC * CDIM];
__device__ __nv_bfloat16 g_Eh[(size_t)KCODES * CDIM];
__device__ float  g_stmin[(size_t)NVEC * UNITS];       /* 64MB: per (n, 8k-unit) approx min */
__device__ unsigned g_cand[CAND_MAX];
__device__ unsigned g_ncand;
__device__ unsigned long long g_best[NVEC];

// ---------------------------------------------------------------------------
__device__ __forceinline__ unsigned smem_u32(const void* p) {
    return (unsigned)__cvta_generic_to_shared(p);
}
__device__ __forceinline__ void ldsm4(unsigned& r0, unsigned& r1,
                                      unsigned& r2, unsigned& r3, unsigned a) {
    asm volatile("ldmatrix.sync.aligned.m8n8.x4.shared.b16 {%0,%1,%2,%3}, [%4];"
                 : "=r"(r0), "=r"(r1), "=r"(r2), "=r"(r3) : "r"(a));
}
__device__ __forceinline__ void mma16816(float* c, const unsigned* a, const unsigned* b) {
    asm volatile("mma.sync.aligned.m16n8k16.row.col.f32.bf16.bf16.f32 "
                 "{%0,%1,%2,%3},{%4,%5,%6,%7},{%8,%9},{%0,%1,%2,%3};"
                 : "+f"(c[0]), "+f"(c[1]), "+f"(c[2]), "+f"(c[3])
                 : "r"(a[0]), "r"(a[1]), "r"(a[2]), "r"(a[3]), "r"(b[0]), "r"(b[1]));
}
__device__ __forceinline__ void cp16(unsigned s, const void* g) {
    asm volatile("cp.async.cg.shared.global [%0], [%1], 16;" :: "r"(s), "l"(g));
}

// ---------------------------------------------------------------------------
// zz[n], ee[k]: exact fp32 (sequential mul+add, validated); reset state.
// ---------------------------------------------------------------------------
__global__ void prologue_kernel(const float* __restrict__ z,
                                const float* __restrict__ emb) {
    int i = blockIdx.x * blockDim.x + threadIdx.x;
    if (i == 0) { g_loss = 0.0; g_ncand = 0u; }
    if (i < NVEC) {
        g_best[i] = 0xFFFFFFFFFFFFFFFFull;
        int b = i >> 10, hw = i & 1023;
        const float* p = z + (size_t)b * 262144 + hw;
        float acc = 0.f;
        #pragma unroll 8
        for (int c = 0; c < CDIM; c++) {
            float v = p[(size_t)c * 1024];
            acc = __fadd_rn(acc, __fmul_rn(v, v));
        }
        g_zz[i] = acc;
    } else if (i < NVEC + KCODES) {
        int k = i - NVEC;
        const float* p = emb + (size_t)k * CDIM;
        float acc = 0.f;
        #pragma unroll 8
        for (int c = 0; c < CDIM; c++) {
            float v = p[c];
            acc = __fadd_rn(acc, __fmul_rn(v, v));
        }
        g_ee[k] = acc;
    }
}

// ---------------------------------------------------------------------------
// bf16 high parts only (single-segment filter). Coalesced layouts.
// ---------------------------------------------------------------------------
__global__ void split_z_kernel(const float* __restrict__ z) {
    int idx = blockIdx.x * 256 + threadIdx.x;   // 16384*64
    int n = idx & 16383, cq = idx >> 14;        // consecutive t -> consecutive n (coalesced reads)
    int b = n >> 10, hw = n & 1023;
    #pragma unroll
    for (int j = 0; j < 4; j++) {
        float v = z[(size_t)b * 262144 + (size_t)(cq * 4 + j) * 1024 + hw];
        g_Zh[(size_t)n * 256 + cq * 4 + j] = __float2bfloat16_rn(v);
    }
}
__global__ void split_e_kernel(const float* __restrict__ emb) {
    int idx = blockIdx.x * 256 + threadIdx.x;   // 8192*32
    int k = idx >> 5, cq = idx & 31;
    #pragma unroll
    for (int j = 0; j < 8; j++) {
        float v = emb[(size_t)k * 256 + cq * 8 + j];
        g_Eh[(size_t)k * 256 + cq * 8 + j] = __float2bfloat16_rn(v);
    }
}

// ---------------------------------------------------------------------------
// Filter GEMM: dot~ = Zh*Eh (K=256), fp32 acc. CTA 128n x 128k, 8 warps (2x4),
// warp 64x32, mma m16n8k16. Epilogue: d~ per (row, 8k-unit) min -> smem
// transpose -> coalesced g_stmin.
// ---------------------------------------------------------------------------
__global__ __launch_bounds__(256, 2)
void filter_gemm_kernel() {
    extern __shared__ char sm[];
    const unsigned smA = smem_u32(sm);
    const unsigned smB = smA + 32768;

    const int t = threadIdx.x;
    const int lane = t & 31, warp = t >> 5;
    const int wm = warp >> 2, wn = warp & 3;
    const int bm = blockIdx.x >> 6, bn = blockIdx.x & 63;

    float acc[4][4][4];
    #pragma unroll
    for (int mi = 0; mi < 4; mi++)
        #pragma unroll
        for (int ni = 0; ni < 4; ni++)
            #pragma unroll
            for (int r = 0; r < 4; r++) acc[mi][ni][r] = 0.f;

    const int rA = lane & 15, cAsel = lane >> 4, l7 = lane & 7;
    const int rB = (lane & 7) + ((lane >> 4) << 3), cBsel = (lane >> 3) & 1;

    const int lrow = t >> 3, lch = t & 7;
    const unsigned ldst_off = (unsigned)(lrow * 128 + ((lch ^ (lrow & 7)) << 4));

    #define ISSUE_CHUNK(q, buf) do {                                          \
        int coff_ = (q) * 64;                                                  \
        _Pragma("unroll")                                                      \
        for (int i_ = 0; i_ < 4; i_++) {                                       \
            int row_ = lrow + i_ * 32;                                         \
            unsigned off_ = ldst_off + i_ * 32 * 128;                          \
            cp16(smA + (buf) * 16384 + off_,                                   \
                 g_Zh + (size_t)(bm * 128 + row_) * 256 + coff_ + lch * 8);    \
            cp16(smB + (buf) * 16384 + off_,                                   \
                 g_Eh + (size_t)(bn * 128 + row_) * 256 + coff_ + lch * 8);    \
        }                                                                      \
        asm volatile("cp.async.commit_group;");                                \
    } while (0)

    ISSUE_CHUNK(0, 0);

    #pragma unroll 1
    for (int q = 0; q < 4; q++) {
        if (q < 3) {
            ISSUE_CHUNK(q + 1, (q + 1) & 1);
            asm volatile("cp.async.wait_group 1;");
        } else {
            asm volatile("cp.async.wait_group 0;");
        }
        __syncthreads();

        const unsigned Ab = smA + (q & 1) * 16384;
        const unsigned Bb = smB + (q & 1) * 16384;

        #pragma unroll
        for (int ks = 0; ks < 4; ks++) {
            unsigned a[4][4], b[4][2];
            #pragma unroll
            for (int mi = 0; mi < 4; mi++) {
                int row = wm * 64 + mi * 16 + rA;
                unsigned ad = Ab + row * 128 + (((2 * ks + cAsel) ^ l7) << 4);
                ldsm4(a[mi][0], a[mi][1], a[mi][2], a[mi][3], ad);
            }
            #pragma unroll
            for (int nj = 0; nj < 2; nj++) {
                int row = wn * 32 + nj * 16 + rB;
                unsigned bd = Bb + row * 128 + (((2 * ks + cBsel) ^ l7) << 4);
                unsigned r0, r1, r2, r3;
                ldsm4(r0, r1, r2, r3, bd);
                b[2 * nj][0] = r0; b[2 * nj][1] = r1;
                b[2 * nj + 1][0] = r2; b[2 * nj + 1][1] = r3;
            }
            #pragma unroll
            for (int mi = 0; mi < 4; mi++)
                #pragma unroll
                for (int ni = 0; ni < 4; ni++)
                    mma16816(acc[mi][ni], a[mi], b[ni]);
        }
        __syncthreads();
    }

    // epilogue: per-(row, 8k-unit) min -> smem [128 rows][16 units] -> coalesced store
    float* st = (float*)sm;   // 8KB reuse
    #pragma unroll
    for (int mi = 0; mi < 4; mi++) {
        int rl0 = wm * 64 + mi * 16 + (lane >> 2);
        int r0 = bm * 128 + rl0;
        float zz0 = g_zz[r0], zz1 = g_zz[r0 + 8];
        #pragma unroll
        for (int ni = 0; ni < 4; ni++) {
            int col = bn * 128 + wn * 32 + ni * 8 + (lane & 3) * 2;
            float e0 = g_ee[col], e1 = g_ee[col + 1];
            float d00 = __fsub_rn(__fadd_rn(zz0, e0), __fmul_rn(2.f, acc[mi][ni][0]));
            float d01 = __fsub_rn(__fadd_rn(zz0, e1), __fmul_rn(2.f, acc[mi][ni][1]));
            float d10 = __fsub_rn(__fadd_rn(zz1, e0), __fmul_rn(2.f, acc[mi][ni][2]));
            float d11 = __fsub_rn(__fadd_rn(zz1, e1), __fmul_rn(2.f, acc[mi][ni][3]));
            float vlo = fminf(d00, d01), vhi = fminf(d10, d11);
            vlo = fminf(vlo, __shfl_xor_sync(0xffffffffu, vlo, 1));
            vlo = fminf(vlo, __shfl_xor_sync(0xffffffffu, vlo, 2));
            vhi = fminf(vhi, __shfl_xor_sync(0xffffffffu, vhi, 1));
            vhi = fminf(vhi, __shfl_xor_sync(0xffffffffu, vhi, 2));
            if ((lane & 3) == 0) {
                st[rl0 * 16 + wn * 4 + ni] = vlo;
                st[(rl0 + 8) * 16 + wn * 4 + ni] = vhi;
            }
        }
    }
    __syncthreads();
    // 2048 floats: thread t writes 8 floats (2 float4)
    {
        int rl = t >> 1, u0 = (t & 1) * 8;
        float* dst = &g_stmin[(size_t)(bm * 128 + rl) * UNITS + bn * 16 + u0];
        float* src = &st[rl * 16 + u0];
        *(float4*)dst = *(float4*)src;
        *(float4*)(dst + 4) = *(float4*)(src + 4);
    }
}

// ---------------------------------------------------------------------------
// Extraction: warp per n. Global min over 1024 unit-mins, flag units within
// MARGIN, append (n<<10|unit) to global candidate list.
// ---------------------------------------------------------------------------
__global__ __launch_bounds__(256)
void extract_kernel() {
    int n = (blockIdx.x * 256 + threadIdx.x) >> 5;
    int lane = threadIdx.x & 31;
    if (n >= NVEC) return;
    const float4* row = (const float4*)&g_stmin[(size_t)n * UNITS];

    float4 v[8];
    float mn = CUDART_INF_F;
    #pragma unroll
    for (int j = 0; j < 8; j++) {
        v[j] = row[j * 32 + lane];
        mn = fminf(mn, fminf(fminf(v[j].x, v[j].y), fminf(v[j].z, v[j].w)));
    }
    #pragma unroll
    for (int o = 16; o; o >>= 1) mn = fminf(mn, __shfl_xor_sync(0xffffffffu, mn, o));
    const float thr = mn + MARGIN;

    unsigned cnt = 0;
    #pragma unroll
    for (int j = 0; j < 8; j++) {
        cnt += (v[j].x <= thr) + (v[j].y <= thr) + (v[j].z <= thr) + (v[j].w <= thr);
    }
    // exclusive warp scan
    unsigned p = cnt;
    #pragma unroll
    for (int o = 1; o < 32; o <<= 1) {
        unsigned tv = __shfl_up_sync(0xffffffffu, p, o);
        if (lane >= o) p += tv;
    }
    unsigned excl = p - cnt;
    unsigned total = __shfl_sync(0xffffffffu, p, 31);
    unsigned base = 0;
    if (lane == 31) base = atomicAdd(&g_ncand, total);
    base = __shfl_sync(0xffffffffu, base, 31);

    unsigned w = base + excl;
    #pragma unroll
    for (int j = 0; j < 8; j++) {
        int u0 = (j * 32 + lane) * 4;
        float vv[4] = { v[j].x, v[j].y, v[j].z, v[j].w };
        #pragma unroll
        for (int c = 0; c < 4; c++)
            if (vv[c] <= thr && w < CAND_MAX)
                g_cand[w++] = ((unsigned)n << 10) | (unsigned)(u0 + c);
    }
}

// ---------------------------------------------------------------------------
// Rescore: persistent, warp per candidate (n, 8k-unit). Stage emb unit (8KB,
// contiguous) into padded smem; 8 lanes run the bit-exact sequential-fma dot;
// lexicographic (d_bits, k) min -> atomicMin(g_best[n]).
// ---------------------------------------------------------------------------
#define RS_BLOCKS 592
__global__ __launch_bounds__(128)
void rescore_kernel(const float* __restrict__ z, const float* __restrict__ emb) {
    __shared__ float es[4][8 * 260];
    const int warp = threadIdx.x >> 5, lane = threadIdx.x & 31;
    const int gwarp = blockIdx.x * 4 + warp;
    const int stride = RS_BLOCKS * 4;
    const unsigned ncand = g_ncand;
    float* dst = es[warp];

    for (unsigned ci = gwarp; ci < ncand; ci += stride) {
        unsigned cd = g_cand[ci];
        int n = cd >> 10, unit = cd & 1023;

        const float4* src = (const float4*)(emb + (size_t)unit * 2048);
        #pragma unroll
        for (int j = 0; j < 16; j++) {
            int f = j * 32 + lane;        // 0..511
            int k = f >> 6, c4 = f & 63;
            *(float4*)&dst[k * 260 + c4 * 4] = src[f];
        }
        __syncwarp();
        if (lane < 8) {
            int k = unit * 8 + lane;
            int b = n >> 10, hw = n & 1023;
            const float* zp = z + (size_t)b * 262144 + hw;
            const float* er = &dst[lane * 260];
            float acc = 0.f;
            #pragma unroll 8
            for (int c = 0; c < 256; c++)
                acc = fmaf(zp[(size_t)c * 1024], er[c], acc);
            float d = __fsub_rn(__fadd_rn(g_zz[n], g_ee[k]), __fmul_rn(2.f, acc));
            unsigned long long key =
                ((unsigned long long)__float_as_uint(d) << 32) | (unsigned)k;
            #pragma unroll
            for (int o = 4; o; o >>= 1) {
                unsigned long long ok = __shfl_xor_sync(0xffu, key, o);
                if (ok < key) key = ok;
            }
            if (lane == 0) atomicMin(&g_best[n], key);
        }
        __syncwarp();
    }
}

__global__ void idx_kernel() {
    int n = blockIdx.x * 256 + threadIdx.x;
    if (n < NVEC) g_idx[n] = (int)(unsigned)(g_best[n] & 0xFFFFFFFFull);
}

// ---------------------------------------------------------------------------
// out[o] = fl(z + fl(zq - z)) ; loss = sum fl(zq-z)^2
// ---------------------------------------------------------------------------
__global__ void gather_kernel(const float* __restrict__ z,
                              const float* __restrict__ emb,
                              float* __restrict__ out) {
    int o = blockIdx.x * 256 + threadIdx.x;
    int rem = o & 262143;
    int b  = o >> 18;
    int c  = rem >> 10;
    int hw = rem & 1023;
    int n  = (b << 10) + hw;
    float zv = z[o];
    float q  = emb[(size_t)g_idx[n] * CDIM + c];
    float diff = __fsub_rn(q, zv);
    out[o] = __fadd_rn(zv, diff);
    float d2 = __fmul_rn(diff, diff);

    #pragma unroll
    for (int off = 16; off; off >>= 1)
        d2 += __shfl_xor_sync(0xffffffffu, d2, off);
    __shared__ float red[8];
    if ((threadIdx.x & 31) == 0) red[threadIdx.x >> 5] = d2;
    __syncthreads();
    if (threadIdx.x < 8) {
        float s = red[threadIdx.x];
        #pragma unroll
        for (int off = 4; off; off >>= 1)
            s += __shfl_xor_sync(0xffu, s, off);
        if (threadIdx.x == 0) atomicAdd(&g_loss, (double)s);
    }
}

__global__ void tail_kernel(float* __restrict__ out, int out_size) {
    int i = blockIdx.x * 256 + threadIdx.x;
    if (i < NVEC && out_size >= ZELEMS + NVEC)
        out[ZELEMS + i] = (float)g_idx[i];
    if (i == 0 && out_size >= ZELEMS + NVEC + 1) {
        float m = (float)(g_loss / (double)ZELEMS);
        out[ZELEMS + NVEC] = __fadd_rn(m, __fmul_rn(0.25f, m)); // m + BETA*m
    }
}

// ---------------------------------------------------------------------------
extern "C" void kernel_launch(void* const* d_in, const int* in_sizes, int n_in,
                              void* d_out, int out_size) {
    const float* z   = (const float*)d_in[0];
    const float* emb = (const float*)d_in[1];
    float* out = (float*)d_out;

    cudaFuncSetAttribute(filter_gemm_kernel,
                         cudaFuncAttributeMaxDynamicSharedMemorySize, 65536);

    prologue_kernel<<<(NVEC + KCODES + 255) / 256, 256>>>(z, emb);
    split_z_kernel<<<NVEC * 64 / 256, 256>>>(z);
    split_e_kernel<<<KCODES * 32 / 256, 256>>>(emb);
    filter_gemm_kernel<<<128 * 64, 256, 65536>>>();
    extract_kernel<<<NVEC * 32 / 256, 256>>>();
    rescore_kernel<<<RS_BLOCKS, 128>>>(z, emb);
    idx_kernel<<<NVEC / 256, 256>>>();
    gather_kernel<<<ZELEMS / 256, 256>>>(z, emb, out);
    tail_kernel<<<(NVEC + 255) / 256, 256>>>(out, out_size);
}

// round 9
// speedup vs baseline: 3.9787x; 1.0038x over previous
#include <cuda_runtime.h>
#include <cuda_bf16.h>
#include <math_constants.h>

#define NVEC   16384
#define KCODES 8192
#define CDIM   256
#define ZELEMS (16*256*32*32)   /* 4194304 */
#define UNITS  1024             /* per-n units of 8 k */
#define MARGIN 4e-4f
#define CAND_MAX (1u<<22)

__device__ float  g_zz[NVEC];
__device__ float  g_ee[KCODES];
__device__ int    g_idx[NVEC];
__device__ double g_loss;
__device__ __nv_bfloat16 g_Zh[(size_t)NVEC * CDIM];
__device__ __nv_bfloat16 g_Eh[(size_t)KCODES * CDIM];
__device__ float  g_stmin[(size_t)NVEC * UNITS];       /* 64MB: per (n, 8k-unit) approx min */
__device__ unsigned g_cand[CAND_MAX];
__device__ unsigned g_ncand;
__device__ unsigned long long g_best[NVEC];

// ---------------------------------------------------------------------------
__device__ __forceinline__ unsigned smem_u32(const void* p) {
    return (unsigned)__cvta_generic_to_shared(p);
}
__device__ __forceinline__ void ldsm4(unsigned& r0, unsigned& r1,
                                      unsigned& r2, unsigned& r3, unsigned a) {
    asm volatile("ldmatrix.sync.aligned.m8n8.x4.shared.b16 {%0,%1,%2,%3}, [%4];"
                 : "=r"(r0), "=r"(r1), "=r"(r2), "=r"(r3) : "r"(a));
}
__device__ __forceinline__ void mma16816(float* c, const unsigned* a, const unsigned* b) {
    asm volatile("mma.sync.aligned.m16n8k16.row.col.f32.bf16.bf16.f32 "
                 "{%0,%1,%2,%3},{%4,%5,%6,%7},{%8,%9},{%0,%1,%2,%3};"
                 : "+f"(c[0]), "+f"(c[1]), "+f"(c[2]), "+f"(c[3])
                 : "r"(a[0]), "r"(a[1]), "r"(a[2]), "r"(a[3]), "r"(b[0]), "r"(b[1]));
}
__device__ __forceinline__ void cp16(unsigned s, const void* g) {
    asm volatile("cp.async.cg.shared.global [%0], [%1], 16;" :: "r"(s), "l"(g));
}

// ---------------------------------------------------------------------------
// zz[n], ee[k]: exact fp32 (sequential mul+add, validated); reset state.
// ---------------------------------------------------------------------------
__global__ void prologue_kernel(const float* __restrict__ z,
                                const float* __restrict__ emb) {
    int i = blockIdx.x * blockDim.x + threadIdx.x;
    if (i == 0) { g_loss = 0.0; g_ncand = 0u; }
    if (i < NVEC) {
        g_best[i] = 0xFFFFFFFFFFFFFFFFull;
        int b = i >> 10, hw = i & 1023;
        const float* p = z + (size_t)b * 262144 + hw;
        float acc = 0.f;
        #pragma unroll 8
        for (int c = 0; c < CDIM; c++) {
            float v = p[(size_t)c * 1024];
            acc = __fadd_rn(acc, __fmul_rn(v, v));
        }
        g_zz[i] = acc;
    } else if (i < NVEC + KCODES) {
        int k = i - NVEC;
        const float* p = emb + (size_t)k * CDIM;
        float acc = 0.f;
        #pragma unroll 8
        for (int c = 0; c < CDIM; c++) {
            float v = p[c];
            acc = __fadd_rn(acc, __fmul_rn(v, v));
        }
        g_ee[k] = acc;
    }
}

// ---------------------------------------------------------------------------
// bf16 high parts only (single-segment filter). Coalesced layouts.
// ---------------------------------------------------------------------------
__global__ void split_z_kernel(const float* __restrict__ z) {
    int idx = blockIdx.x * 256 + threadIdx.x;   // 16384*64
    int n = idx & 16383, cq = idx >> 14;        // consecutive t -> consecutive n (coalesced reads)
    int b = n >> 10, hw = n & 1023;
    #pragma unroll
    for (int j = 0; j < 4; j++) {
        float v = z[(size_t)b * 262144 + (size_t)(cq * 4 + j) * 1024 + hw];
        g_Zh[(size_t)n * 256 + cq * 4 + j] = __float2bfloat16_rn(v);
    }
}
__global__ void split_e_kernel(const float* __restrict__ emb) {
    int idx = blockIdx.x * 256 + threadIdx.x;   // 8192*32
    int k = idx >> 5, cq = idx & 31;
    #pragma unroll
    for (int j = 0; j < 8; j++) {
        float v = emb[(size_t)k * 256 + cq * 8 + j];
        g_Eh[(size_t)k * 256 + cq * 8 + j] = __float2bfloat16_rn(v);
    }
}

// ---------------------------------------------------------------------------
// Filter GEMM: dot~ = Zh*Eh (K=256), fp32 acc. CTA 128n x 128k, 8 warps (2x4),
// warp 64x32, mma m16n8k16. Epilogue: d~ per (row, 8k-unit) min -> smem
// transpose -> coalesced g_stmin.
// ---------------------------------------------------------------------------
__global__ __launch_bounds__(256, 2)
void filter_gemm_kernel() {
    extern __shared__ char sm[];
    const unsigned smA = smem_u32(sm);
    const unsigned smB = smA + 32768;

    const int t = threadIdx.x;
    const int lane = t & 31, warp = t >> 5;
    const int wm = warp >> 2, wn = warp & 3;
    const int bm = blockIdx.x >> 6, bn = blockIdx.x & 63;

    float acc[4][4][4];
    #pragma unroll
    for (int mi = 0; mi < 4; mi++)
        #pragma unroll
        for (int ni = 0; ni < 4; ni++)
            #pragma unroll
            for (int r = 0; r < 4; r++) acc[mi][ni][r] = 0.f;

    const int rA = lane & 15, cAsel = lane >> 4, l7 = lane & 7;
    const int rB = (lane & 7) + ((lane >> 4) << 3), cBsel = (lane >> 3) & 1;

    const int lrow = t >> 3, lch = t & 7;
    const unsigned ldst_off = (unsigned)(lrow * 128 + ((lch ^ (lrow & 7)) << 4));

    #define ISSUE_CHUNK(q, buf) do {                                          \
        int coff_ = (q) * 64;                                                  \
        _Pragma("unroll")                                                      \
        for (int i_ = 0; i_ < 4; i_++) {                                       \
            int row_ = lrow + i_ * 32;                                         \
            unsigned off_ = ldst_off + i_ * 32 * 128;                          \
            cp16(smA + (buf) * 16384 + off_,                                   \
                 g_Zh + (size_t)(bm * 128 + row_) * 256 + coff_ + lch * 8);    \
            cp16(smB + (buf) * 16384 + off_,                                   \
                 g_Eh + (size_t)(bn * 128 + row_) * 256 + coff_ + lch * 8);    \
        }                                                                      \
        asm volatile("cp.async.commit_group;");                                \
    } while (0)

    ISSUE_CHUNK(0, 0);

    #pragma unroll 1
    for (int q = 0; q < 4; q++) {
        if (q < 3) {
            ISSUE_CHUNK(q + 1, (q + 1) & 1);
            asm volatile("cp.async.wait_group 1;");
        } else {
            asm volatile("cp.async.wait_group 0;");
        }
        __syncthreads();

        const unsigned Ab = smA + (q & 1) * 16384;
        const unsigned Bb = smB + (q & 1) * 16384;

        #pragma unroll
        for (int ks = 0; ks < 4; ks++) {
            unsigned a[4][4], b[4][2];
            #pragma unroll
            for (int mi = 0; mi < 4; mi++) {
                int row = wm * 64 + mi * 16 + rA;
                unsigned ad = Ab + row * 128 + (((2 * ks + cAsel) ^ l7) << 4);
                ldsm4(a[mi][0], a[mi][1], a[mi][2], a[mi][3], ad);
            }
            #pragma unroll
            for (int nj = 0; nj < 2; nj++) {
                int row = wn * 32 + nj * 16 + rB;
                unsigned bd = Bb + row * 128 + (((2 * ks + cBsel) ^ l7) << 4);
                unsigned r0, r1, r2, r3;
                ldsm4(r0, r1, r2, r3, bd);
                b[2 * nj][0] = r0; b[2 * nj][1] = r1;
                b[2 * nj + 1][0] = r2; b[2 * nj + 1][1] = r3;
            }
            #pragma unroll
            for (int mi = 0; mi < 4; mi++)
                #pragma unroll
                for (int ni = 0; ni < 4; ni++)
                    mma16816(acc[mi][ni], a[mi], b[ni]);
        }
        __syncthreads();
    }

    // epilogue: per-(row, 8k-unit) min -> smem [128 rows][16 units] -> coalesced store
    float* st = (float*)sm;   // 8KB reuse
    #pragma unroll
    for (int mi = 0; mi < 4; mi++) {
        int rl0 = wm * 64 + mi * 16 + (lane >> 2);
        int r0 = bm * 128 + rl0;
        float zz0 = g_zz[r0], zz1 = g_zz[r0 + 8];
        #pragma unroll
        for (int ni = 0; ni < 4; ni++) {
            int col = bn * 128 + wn * 32 + ni * 8 + (lane & 3) * 2;
            float e0 = g_ee[col], e1 = g_ee[col + 1];
            float d00 = __fsub_rn(__fadd_rn(zz0, e0), __fmul_rn(2.f, acc[mi][ni][0]));
            float d01 = __fsub_rn(__fadd_rn(zz0, e1), __fmul_rn(2.f, acc[mi][ni][1]));
            float d10 = __fsub_rn(__fadd_rn(zz1, e0), __fmul_rn(2.f, acc[mi][ni][2]));
            float d11 = __fsub_rn(__fadd_rn(zz1, e1), __fmul_rn(2.f, acc[mi][ni][3]));
            float vlo = fminf(d00, d01), vhi = fminf(d10, d11);
            vlo = fminf(vlo, __shfl_xor_sync(0xffffffffu, vlo, 1));
            vlo = fminf(vlo, __shfl_xor_sync(0xffffffffu, vlo, 2));
            vhi = fminf(vhi, __shfl_xor_sync(0xffffffffu, vhi, 1));
            vhi = fminf(vhi, __shfl_xor_sync(0xffffffffu, vhi, 2));
            if ((lane & 3) == 0) {
                st[rl0 * 16 + wn * 4 + ni] = vlo;
                st[(rl0 + 8) * 16 + wn * 4 + ni] = vhi;
            }
        }
    }
    __syncthreads();
    // 2048 floats: thread t writes 8 floats (2 float4)
    {
        int rl = t >> 1, u0 = (t & 1) * 8;
        float* dst = &g_stmin[(size_t)(bm * 128 + rl) * UNITS + bn * 16 + u0];
        float* src = &st[rl * 16 + u0];
        *(float4*)dst = *(float4*)src;
        *(float4*)(dst + 4) = *(float4*)(src + 4);
    }
}

// ---------------------------------------------------------------------------
// Extraction: warp per n. Global min over 1024 unit-mins, flag units within
// MARGIN, append (n<<10|unit) to global candidate list.
// ---------------------------------------------------------------------------
__global__ __launch_bounds__(256)
void extract_kernel() {
    int n = (blockIdx.x * 256 + threadIdx.x) >> 5;
    int lane = threadIdx.x & 31;
    if (n >= NVEC) return;
    const float4* row = (const float4*)&g_stmin[(size_t)n * UNITS];

    float4 v[8];
    float mn = CUDART_INF_F;
    #pragma unroll
    for (int j = 0; j < 8; j++) {
        v[j] = row[j * 32 + lane];
        mn = fminf(mn, fminf(fminf(v[j].x, v[j].y), fminf(v[j].z, v[j].w)));
    }
    #pragma unroll
    for (int o = 16; o; o >>= 1) mn = fminf(mn, __shfl_xor_sync(0xffffffffu, mn, o));
    const float thr = mn + MARGIN;

    unsigned cnt = 0;
    #pragma unroll
    for (int j = 0; j < 8; j++) {
        cnt += (v[j].x <= thr) + (v[j].y <= thr) + (v[j].z <= thr) + (v[j].w <= thr);
    }
    // exclusive warp scan
    unsigned p = cnt;
    #pragma unroll
    for (int o = 1; o < 32; o <<= 1) {
        unsigned tv = __shfl_up_sync(0xffffffffu, p, o);
        if (lane >= o) p += tv;
    }
    unsigned excl = p - cnt;
    unsigned total = __shfl_sync(0xffffffffu, p, 31);
    unsigned base = 0;
    if (lane == 31) base = atomicAdd(&g_ncand, total);
    base = __shfl_sync(0xffffffffu, base, 31);

    unsigned w = base + excl;
    #pragma unroll
    for (int j = 0; j < 8; j++) {
        int u0 = (j * 32 + lane) * 4;
        float vv[4] = { v[j].x, v[j].y, v[j].z, v[j].w };
        #pragma unroll
        for (int c = 0; c < 4; c++)
            if (vv[c] <= thr && w < CAND_MAX)
                g_cand[w++] = ((unsigned)n << 10) | (unsigned)(u0 + c);
    }
}

// ---------------------------------------------------------------------------
// Rescore: persistent, warp per candidate (n, 8k-unit). Stage emb unit (8KB,
// contiguous) into padded smem; 8 lanes run the bit-exact sequential-fma dot;
// lexicographic (d_bits, k) min -> atomicMin(g_best[n]).
// ---------------------------------------------------------------------------
#define RS_BLOCKS 592
__global__ __launch_bounds__(128)
void rescore_kernel(const float* __restrict__ z, const float* __restrict__ emb) {
    __shared__ float es[4][8 * 260];
    const int warp = threadIdx.x >> 5, lane = threadIdx.x & 31;
    const int gwarp = blockIdx.x * 4 + warp;
    const int stride = RS_BLOCKS * 4;
    const unsigned ncand = g_ncand;
    float* dst = es[warp];

    for (unsigned ci = gwarp; ci < ncand; ci += stride) {
        unsigned cd = g_cand[ci];
        int n = cd >> 10, unit = cd & 1023;

        const float4* src = (const float4*)(emb + (size_t)unit * 2048);
        #pragma unroll
        for (int j = 0; j < 16; j++) {
            int f = j * 32 + lane;        // 0..511
            int k = f >> 6, c4 = f & 63;
            *(float4*)&dst[k * 260 + c4 * 4] = src[f];
        }
        __syncwarp();
        if (lane < 8) {
            int k = unit * 8 + lane;
            int b = n >> 10, hw = n & 1023;
            const float* zp = z + (size_t)b * 262144 + hw;
            const float* er = &dst[lane * 260];
            float acc = 0.f;
            #pragma unroll 8
            for (int c = 0; c < 256; c++)
                acc = fmaf(zp[(size_t)c * 1024], er[c], acc);
            float d = __fsub_rn(__fadd_rn(g_zz[n], g_ee[k]), __fmul_rn(2.f, acc));
            unsigned long long key =
                ((unsigned long long)__float_as_uint(d) << 32) | (unsigned)k;
            #pragma unroll
            for (int o = 4; o; o >>= 1) {
                unsigned long long ok = __shfl_xor_sync(0xffu, key, o);
                if (ok < key) key = ok;
            }
            if (lane == 0) atomicMin(&g_best[n], key);
        }
        __syncwarp();
    }
}

__global__ void idx_kernel() {
    int n = blockIdx.x * 256 + threadIdx.x;
    if (n < NVEC) g_idx[n] = (int)(unsigned)(g_best[n] & 0xFFFFFFFFull);
}

// ---------------------------------------------------------------------------
// out[o] = fl(z + fl(zq - z)) ; loss = sum fl(zq-z)^2
// ---------------------------------------------------------------------------
__global__ void gather_kernel(const float* __restrict__ z,
                              const float* __restrict__ emb,
                              float* __restrict__ out) {
    int o = blockIdx.x * 256 + threadIdx.x;
    int rem = o & 262143;
    int b  = o >> 18;
    int c  = rem >> 10;
    int hw = rem & 1023;
    int n  = (b << 10) + hw;
    float zv = z[o];
    float q  = emb[(size_t)g_idx[n] * CDIM + c];
    float diff = __fsub_rn(q, zv);
    out[o] = __fadd_rn(zv, diff);
    float d2 = __fmul_rn(diff, diff);

    #pragma unroll
    for (int off = 16; off; off >>= 1)
        d2 += __shfl_xor_sync(0xffffffffu, d2, off);
    __shared__ float red[8];
    if ((threadIdx.x & 31) == 0) red[threadIdx.x >> 5] = d2;
    __syncthreads();
    if (threadIdx.x < 8) {
        float s = red[threadIdx.x];
        #pragma unroll
        for (int off = 4; off; off >>= 1)
            s += __shfl_xor_sync(0xffu, s, off);
        if (threadIdx.x == 0) atomicAdd(&g_loss, (double)s);
    }
}

__global__ void tail_kernel(float* __restrict__ out, int out_size) {
    int i = blockIdx.x * 256 + threadIdx.x;
    if (i < NVEC && out_size >= ZELEMS + NVEC)
        out[ZELEMS + i] = (float)g_idx[i];
    if (i == 0 && out_size >= ZELEMS + NVEC + 1) {
        float m = (float)(g_loss / (double)ZELEMS);
        out[ZELEMS + NVEC] = __fadd_rn(m, __fmul_rn(0.25f, m)); // m + BETA*m
    }
}

// ---------------------------------------------------------------------------
extern "C" void kernel_launch(void* const* d_in, const int* in_sizes, int n_in,
                              void* d_out, int out_size) {
    const float* z   = (const float*)d_in[0];
    const float* emb = (const float*)d_in[1];
    float* out = (float*)d_out;

    cudaFuncSetAttribute(filter_gemm_kernel,
                         cudaFuncAttributeMaxDynamicSharedMemorySize, 65536);

    prologue_kernel<<<(NVEC + KCODES + 255) / 256, 256>>>(z, emb);
    split_z_kernel<<<NVEC * 64 / 256, 256>>>(z);
    split_e_kernel<<<KCODES * 32 / 256, 256>>>(emb);
    filter_gemm_kernel<<<128 * 64, 256, 65536>>>();
    extract_kernel<<<NVEC * 32 / 256, 256>>>();
    rescore_kernel<<<RS_BLOCKS, 128>>>(z, emb);
    idx_kernel<<<NVEC / 256, 256>>>();
    gather_kernel<<<ZELEMS / 256, 256>>>(z, emb, out);
    tail_kernel<<<(NVEC + 255) / 256, 256>>>(out, out_size);
}

// round 10
// speedup vs baseline: 4.7901x; 1.2039x over previous
#include <cuda_runtime.h>
#include <cuda_bf16.h>
#include <math_constants.h>

#define NVEC   16384
#define KCODES 8192
#define CDIM   256
#define ZELEMS (16*256*32*32)   /* 4194304 */
#define UNITS  1024             /* per-n units of 8 k */
#define MARGIN 4e-4f
#define CAND_MAX (1u<<22)

__device__ float  g_zz[NVEC];
__device__ float  g_ee[KCODES];
__device__ double g_loss;
__device__ __nv_bfloat16 g_Zh[(size_t)NVEC * CDIM];
__device__ __nv_bfloat16 g_Eh[(size_t)KCODES * CDIM];
__device__ float  g_stmin[(size_t)NVEC * UNITS];
__device__ unsigned g_cand[CAND_MAX];
__device__ unsigned g_ncand;
__device__ unsigned long long g_best[NVEC];
__device__ float  g_zq[(size_t)NVEC * CDIM];

// ---------------------------------------------------------------------------
__device__ __forceinline__ unsigned smem_u32(const void* p) {
    return (unsigned)__cvta_generic_to_shared(p);
}
__device__ __forceinline__ void ldsm4(unsigned& r0, unsigned& r1,
                                      unsigned& r2, unsigned& r3, unsigned a) {
    asm volatile("ldmatrix.sync.aligned.m8n8.x4.shared.b16 {%0,%1,%2,%3}, [%4];"
                 : "=r"(r0), "=r"(r1), "=r"(r2), "=r"(r3) : "r"(a));
}
__device__ __forceinline__ void mma16816(float* c, const unsigned* a, const unsigned* b) {
    asm volatile("mma.sync.aligned.m16n8k16.row.col.f32.bf16.bf16.f32 "
                 "{%0,%1,%2,%3},{%4,%5,%6,%7},{%8,%9},{%0,%1,%2,%3};"
                 : "+f"(c[0]), "+f"(c[1]), "+f"(c[2]), "+f"(c[3])
                 : "r"(a[0]), "r"(a[1]), "r"(a[2]), "r"(a[3]), "r"(b[0]), "r"(b[1]));
}
__device__ __forceinline__ void cp16(unsigned s, const void* g) {
    asm volatile("cp.async.cg.shared.global [%0], [%1], 16;" :: "r"(s), "l"(g));
}
__device__ __forceinline__ unsigned bf2pack(float lo, float hi) {
    __nv_bfloat162 t = __floats2bfloat162_rn(lo, hi);   /* .x = lo (low addr) */
    return *(unsigned*)&t;
}

// ---------------------------------------------------------------------------
// prep: per-n -> zz (sequential fp32 mul+add, bit-order preserved) + bf16 row
//        of Zh written in contiguous 64B chunks; per-k -> ee + Eh row.
// ---------------------------------------------------------------------------
__global__ void prep_kernel(const float* __restrict__ z,
                            const float* __restrict__ emb) {
    int i = blockIdx.x * 256 + threadIdx.x;
    if (i == 0) { g_loss = 0.0; g_ncand = 0u; }
    if (i < NVEC) {
        g_best[i] = 0xFFFFFFFFFFFFFFFFull;
        int b = i >> 10, hw = i & 1023;
        const float* p = z + (size_t)b * 262144 + hw;
        float acc = 0.f;
        #pragma unroll 1
        for (int ch = 0; ch < 8; ch++) {
            float v[32];
            #pragma unroll
            for (int j = 0; j < 32; j++)
                v[j] = p[(size_t)(ch * 32 + j) * 1024];
            #pragma unroll
            for (int j = 0; j < 32; j++)
                acc = __fadd_rn(acc, __fmul_rn(v[j], v[j]));
            uint4* dst = (uint4*)&g_Zh[(size_t)i * 256 + ch * 32];
            #pragma unroll
            for (int q = 0; q < 4; q++)
                dst[q] = make_uint4(bf2pack(v[q*8+0], v[q*8+1]), bf2pack(v[q*8+2], v[q*8+3]),
                                    bf2pack(v[q*8+4], v[q*8+5]), bf2pack(v[q*8+6], v[q*8+7]));
        }
        g_zz[i] = acc;
    } else if (i < NVEC + KCODES) {
        int k = i - NVEC;
        const float4* p = (const float4*)(emb + (size_t)k * 256);
        float acc = 0.f;
        #pragma unroll 1
        for (int ch = 0; ch < 8; ch++) {
            float v[32];
            #pragma unroll
            for (int q = 0; q < 8; q++) {
                float4 w = p[ch * 8 + q];
                v[q*4] = w.x; v[q*4+1] = w.y; v[q*4+2] = w.z; v[q*4+3] = w.w;
            }
            #pragma unroll
            for (int j = 0; j < 32; j++)
                acc = __fadd_rn(acc, __fmul_rn(v[j], v[j]));
            uint4* dst = (uint4*)&g_Eh[(size_t)k * 256 + ch * 32];
            #pragma unroll
            for (int q = 0; q < 4; q++)
                dst[q] = make_uint4(bf2pack(v[q*8+0], v[q*8+1]), bf2pack(v[q*8+2], v[q*8+3]),
                                    bf2pack(v[q*8+4], v[q*8+5]), bf2pack(v[q*8+6], v[q*8+7]));
        }
        g_ee[k] = acc;
    }
}

// ---------------------------------------------------------------------------
// Filter GEMM: dot~ = Zh*Eh (K=256), fp32 acc. CTA 128n x 128k, 8 warps (2x4),
// warp 64x32, mma m16n8k16. 3-stage cp.async circular pipeline, 1 sync/chunk.
// Epilogue: per-(row, 8k-unit) min -> smem transpose -> coalesced g_stmin.
// ---------------------------------------------------------------------------
__global__ __launch_bounds__(256, 2)
void filter_gemm_kernel() {
    extern __shared__ char sm[];
    const unsigned smBase = smem_u32(sm);

    const int t = threadIdx.x;
    const int lane = t & 31, warp = t >> 5;
    const int wm = warp >> 2, wn = warp & 3;
    const int bm = blockIdx.x >> 6, bn = blockIdx.x & 63;

    float acc[4][4][4];
    #pragma unroll
    for (int mi = 0; mi < 4; mi++)
        #pragma unroll
        for (int ni = 0; ni < 4; ni++)
            #pragma unroll
            for (int r = 0; r < 4; r++) acc[mi][ni][r] = 0.f;

    const int rA = lane & 15, cAsel = lane >> 4, l7 = lane & 7;
    const int rB = (lane & 7) + ((lane >> 4) << 3), cBsel = (lane >> 3) & 1;

    const int lrow = t >> 3, lch = t & 7;
    const unsigned ldst_off = (unsigned)(lrow * 128 + ((lch ^ (lrow & 7)) << 4));

    #define ISSUE_CHUNK(q, s) do {                                            \
        int coff_ = (q) * 64;                                                  \
        _Pragma("unroll")                                                      \
        for (int i_ = 0; i_ < 4; i_++) {                                       \
            int row_ = lrow + i_ * 32;                                         \
            unsigned off_ = ldst_off + i_ * 32 * 128;                          \
            cp16(smBase + (s) * 32768 + off_,                                  \
                 g_Zh + (size_t)(bm * 128 + row_) * 256 + coff_ + lch * 8);    \
            cp16(smBase + (s) * 32768 + 16384 + off_,                          \
                 g_Eh + (size_t)(bn * 128 + row_) * 256 + coff_ + lch * 8);    \
        }                                                                      \
        asm volatile("cp.async.commit_group;");                                \
    } while (0)

    ISSUE_CHUNK(0, 0);
    ISSUE_CHUNK(1, 1);

    #pragma unroll
    for (int q = 0; q < 4; q++) {
        if (q < 3) asm volatile("cp.async.wait_group 1;");
        else       asm volatile("cp.async.wait_group 0;");
        __syncthreads();

        const unsigned Ab = smBase + (q % 3) * 32768;
        const unsigned Bb = Ab + 16384;

        #pragma unroll
        for (int ks = 0; ks < 4; ks++) {
            unsigned a[4][4], b[4][2];
            #pragma unroll
            for (int mi = 0; mi < 4; mi++) {
                int row = wm * 64 + mi * 16 + rA;
                unsigned ad = Ab + row * 128 + (((2 * ks + cAsel) ^ l7) << 4);
                ldsm4(a[mi][0], a[mi][1], a[mi][2], a[mi][3], ad);
            }
            #pragma unroll
            for (int nj = 0; nj < 2; nj++) {
                int row = wn * 32 + nj * 16 + rB;
                unsigned bd = Bb + row * 128 + (((2 * ks + cBsel) ^ l7) << 4);
                unsigned r0, r1, r2, r3;
                ldsm4(r0, r1, r2, r3, bd);
                b[2 * nj][0] = r0; b[2 * nj][1] = r1;
                b[2 * nj + 1][0] = r2; b[2 * nj + 1][1] = r3;
            }
            #pragma unroll
            for (int mi = 0; mi < 4; mi++)
                #pragma unroll
                for (int ni = 0; ni < 4; ni++)
                    mma16816(acc[mi][ni], a[mi], b[ni]);
        }
        if (q < 2) ISSUE_CHUNK(q + 2, (q + 2) % 3);
    }

    __syncthreads();   // stage 0 region about to be reused as scratch
    float* st = (float*)sm;   // [128 rows][16 units]
    #pragma unroll
    for (int mi = 0; mi < 4; mi++) {
        int rl0 = wm * 64 + mi * 16 + (lane >> 2);
        int r0 = bm * 128 + rl0;
        float zz0 = g_zz[r0], zz1 = g_zz[r0 + 8];
        #pragma unroll
        for (int ni = 0; ni < 4; ni++) {
            int col = bn * 128 + wn * 32 + ni * 8 + (lane & 3) * 2;
            float e0 = g_ee[col], e1 = g_ee[col + 1];
            float d00 = __fsub_rn(__fadd_rn(zz0, e0), __fmul_rn(2.f, acc[mi][ni][0]));
            float d01 = __fsub_rn(__fadd_rn(zz0, e1), __fmul_rn(2.f, acc[mi][ni][1]));
            float d10 = __fsub_rn(__fadd_rn(zz1, e0), __fmul_rn(2.f, acc[mi][ni][2]));
            float d11 = __fsub_rn(__fadd_rn(zz1, e1), __fmul_rn(2.f, acc[mi][ni][3]));
            float vlo = fminf(d00, d01), vhi = fminf(d10, d11);
            vlo = fminf(vlo, __shfl_xor_sync(0xffffffffu, vlo, 1));
            vlo = fminf(vlo, __shfl_xor_sync(0xffffffffu, vlo, 2));
            vhi = fminf(vhi, __shfl_xor_sync(0xffffffffu, vhi, 1));
            vhi = fminf(vhi, __shfl_xor_sync(0xffffffffu, vhi, 2));
            if ((lane & 3) == 0) {
                st[rl0 * 16 + wn * 4 + ni] = vlo;
                st[(rl0 + 8) * 16 + wn * 4 + ni] = vhi;
            }
        }
    }
    __syncthreads();
    {
        int rl = t >> 1, u0 = (t & 1) * 8;
        float* dst = &g_stmin[(size_t)(bm * 128 + rl) * UNITS + bn * 16 + u0];
        float* src = &st[rl * 16 + u0];
        *(float4*)dst = *(float4*)src;
        *(float4*)(dst + 4) = *(float4*)(src + 4);
    }
}

// ---------------------------------------------------------------------------
// Extraction: warp per n. Global min over 1024 unit-mins, flag units within
// MARGIN, append (n<<10|unit) to global candidate list.
// ---------------------------------------------------------------------------
__global__ __launch_bounds__(256)
void extract_kernel() {
    int n = (blockIdx.x * 256 + threadIdx.x) >> 5;
    int lane = threadIdx.x & 31;
    if (n >= NVEC) return;
    const float4* row = (const float4*)&g_stmin[(size_t)n * UNITS];

    float4 v[8];
    float mn = CUDART_INF_F;
    #pragma unroll
    for (int j = 0; j < 8; j++) {
        v[j] = row[j * 32 + lane];
        mn = fminf(mn, fminf(fminf(v[j].x, v[j].y), fminf(v[j].z, v[j].w)));
    }
    #pragma unroll
    for (int o = 16; o; o >>= 1) mn = fminf(mn, __shfl_xor_sync(0xffffffffu, mn, o));
    const float thr = mn + MARGIN;

    unsigned cnt = 0;
    #pragma unroll
    for (int j = 0; j < 8; j++)
        cnt += (v[j].x <= thr) + (v[j].y <= thr) + (v[j].z <= thr) + (v[j].w <= thr);

    unsigned p = cnt;
    #pragma unroll
    for (int o = 1; o < 32; o <<= 1) {
        unsigned tv = __shfl_up_sync(0xffffffffu, p, o);
        if (lane >= o) p += tv;
    }
    unsigned excl = p - cnt;
    unsigned total = __shfl_sync(0xffffffffu, p, 31);
    unsigned base = 0;
    if (lane == 31) base = atomicAdd(&g_ncand, total);
    base = __shfl_sync(0xffffffffu, base, 31);

    unsigned w = base + excl;
    #pragma unroll
    for (int j = 0; j < 8; j++) {
        int u0 = (j * 32 + lane) * 4;
        float vv[4] = { v[j].x, v[j].y, v[j].z, v[j].w };
        #pragma unroll
        for (int c = 0; c < 4; c++)
            if (vv[c] <= thr && w < CAND_MAX)
                g_cand[w++] = ((unsigned)n << 10) | (unsigned)(u0 + c);
    }
}

// ---------------------------------------------------------------------------
// Rescore: persistent, warp per candidate (n, 8k-unit). Bit-exact sequential
// fma dot; lexicographic (d_bits, k) min -> atomicMin(g_best[n]).
// ---------------------------------------------------------------------------
#define RS_BLOCKS 592
__global__ __launch_bounds__(128)
void rescore_kernel(const float* __restrict__ z, const float* __restrict__ emb) {
    __shared__ float es[4][8 * 260];
    const int warp = threadIdx.x >> 5, lane = threadIdx.x & 31;
    const int gwarp = blockIdx.x * 4 + warp;
    const int stride = RS_BLOCKS * 4;
    const unsigned ncand = g_ncand;
    float* dst = es[warp];

    for (unsigned ci = gwarp; ci < ncand; ci += stride) {
        unsigned cd = g_cand[ci];
        int n = cd >> 10, unit = cd & 1023;

        const float4* src = (const float4*)(emb + (size_t)unit * 2048);
        #pragma unroll
        for (int j = 0; j < 16; j++) {
            int f = j * 32 + lane;
            int k = f >> 6, c4 = f & 63;
            *(float4*)&dst[k * 260 + c4 * 4] = src[f];
        }
        __syncwarp();
        if (lane < 8) {
            int k = unit * 8 + lane;
            int b = n >> 10, hw = n & 1023;
            const float* zp = z + (size_t)b * 262144 + hw;
            const float* er = &dst[lane * 260];
            float acc = 0.f;
            #pragma unroll 8
            for (int c = 0; c < 256; c++)
                acc = fmaf(zp[(size_t)c * 1024], er[c], acc);
            float d = __fsub_rn(__fadd_rn(g_zz[n], g_ee[k]), __fmul_rn(2.f, acc));
            unsigned long long key =
                ((unsigned long long)__float_as_uint(d) << 32) | (unsigned)k;
            #pragma unroll
            for (int o = 4; o; o >>= 1) {
                unsigned long long ok = __shfl_xor_sync(0xffu, key, o);
                if (ok < key) key = ok;
            }
            if (lane == 0) atomicMin(&g_best[n], key);
        }
        __syncwarp();
    }
}

// ---------------------------------------------------------------------------
// gatherq: zq[n][c] = emb[idx[n]][c], fully coalesced (thread per (n, f4)).
// ---------------------------------------------------------------------------
__global__ void gatherq_kernel(const float* __restrict__ emb) {
    int idx = blockIdx.x * 256 + threadIdx.x;      // NVEC*64
    int n = idx >> 6, f = idx & 63;
    unsigned k = (unsigned)(g_best[n] & 0xFFFFFFFFull);
    ((float4*)g_zq)[(size_t)n * 64 + f] = ((const float4*)emb)[(size_t)k * 64 + f];
}

// ---------------------------------------------------------------------------
// finish: out[o] = fl(z + fl(zq - z)) via 32x32 smem transpose tile; all
// global accesses coalesced. loss = sum fl(zq-z)^2 (double atomics).
// ---------------------------------------------------------------------------
__global__ __launch_bounds__(256)
void finish_kernel(const float* __restrict__ z, float* __restrict__ out) {
    __shared__ float s[32 * 33];
    const int bid = blockIdx.x;
    const int b = bid >> 8, ct = (bid >> 5) & 7, ht = bid & 31;
    const int c0 = ct * 32, hw0 = ht * 32;
    const int t = threadIdx.x;

    {   // load zq tile [32 hw rows][32 c]
        int r = t >> 3, q4 = t & 7;
        int n = b * 1024 + hw0 + r;
        float4 w = *(const float4*)&g_zq[(size_t)n * 256 + c0 + q4 * 4];
        float* d = &s[r * 33 + q4 * 4];
        d[0] = w.x; d[1] = w.y; d[2] = w.z; d[3] = w.w;
    }
    __syncthreads();

    const int hwl = t & 31, cl0 = t >> 5;
    float d2s = 0.f;
    #pragma unroll
    for (int it = 0; it < 4; it++) {
        int cl = cl0 + it * 8;
        size_t o = (size_t)b * 262144 + (size_t)(c0 + cl) * 1024 + hw0 + hwl;
        float zv = z[o];
        float q  = s[hwl * 33 + cl];
        float diff = __fsub_rn(q, zv);
        out[o] = __fadd_rn(zv, diff);
        d2s += __fmul_rn(diff, diff);
    }

    #pragma unroll
    for (int off = 16; off; off >>= 1)
        d2s += __shfl_xor_sync(0xffffffffu, d2s, off);
    __shared__ float red[8];
    if ((t & 31) == 0) red[t >> 5] = d2s;
    __syncthreads();
    if (t < 8) {
        float v = red[t];
        #pragma unroll
        for (int off = 4; off; off >>= 1)
            v += __shfl_xor_sync(0xffu, v, off);
        if (t == 0) atomicAdd(&g_loss, (double)v);
    }
}

__global__ void tail_kernel(float* __restrict__ out, int out_size) {
    int i = blockIdx.x * 256 + threadIdx.x;
    if (i < NVEC && out_size >= ZELEMS + NVEC)
        out[ZELEMS + i] = (float)(unsigned)(g_best[i] & 0xFFFFFFFFull);
    if (i == 0 && out_size >= ZELEMS + NVEC + 1) {
        float m = (float)(g_loss / (double)ZELEMS);
        out[ZELEMS + NVEC] = __fadd_rn(m, __fmul_rn(0.25f, m)); // m + BETA*m
    }
}

// ---------------------------------------------------------------------------
extern "C" void kernel_launch(void* const* d_in, const int* in_sizes, int n_in,
                              void* d_out, int out_size) {
    const float* z   = (const float*)d_in[0];
    const float* emb = (const float*)d_in[1];
    float* out = (float*)d_out;

    cudaFuncSetAttribute(filter_gemm_kernel,
                         cudaFuncAttributeMaxDynamicSharedMemorySize, 98304);

    prep_kernel<<<(NVEC + KCODES + 255) / 256, 256>>>(z, emb);
    filter_gemm_kernel<<<128 * 64, 256, 98304>>>();
    extract_kernel<<<NVEC * 32 / 256, 256>>>();
    rescore_kernel<<<RS_BLOCKS, 128>>>(z, emb);
    gatherq_kernel<<<NVEC * 64 / 256, 256>>>(emb);
    finish_kernel<<<16 * 8 * 32, 256>>>(z, out);
    tail_kernel<<<(NVEC + 255) / 256, 256>>>(out, out_size);
}

// round 11
// speedup vs baseline: 5.7776x; 1.2061x over previous
#include <cuda_runtime.h>
#include <cuda_bf16.h>
#include <math_constants.h>

#define NVEC   16384
#define KCODES 8192
#define CDIM   256
#define ZELEMS (16*256*32*32)   /* 4194304 */
#define UNITS  1024             /* per-n units of 8 k */
#define MARGIN 4e-4f
#define CAND_MAX (1u<<22)

__device__ float  g_zz[NVEC];
__device__ float  g_ee[KCODES];
__device__ double g_loss;
__device__ __nv_bfloat16 g_Zh[(size_t)NVEC * CDIM];
__device__ __nv_bfloat16 g_Eh[(size_t)KCODES * CDIM];
__device__ float  g_zt[(size_t)NVEC * CDIM];     /* z transposed to [n][c], fp32 */
__device__ float  g_stmin[(size_t)NVEC * UNITS];
__device__ unsigned g_cand[CAND_MAX];
__device__ unsigned g_ncand;
__device__ unsigned long long g_best[NVEC];
__device__ float  g_zq[(size_t)NVEC * CDIM];

// ---------------------------------------------------------------------------
__device__ __forceinline__ unsigned smem_u32(const void* p) {
    return (unsigned)__cvta_generic_to_shared(p);
}
__device__ __forceinline__ void ldsm4(unsigned& r0, unsigned& r1,
                                      unsigned& r2, unsigned& r3, unsigned a) {
    asm volatile("ldmatrix.sync.aligned.m8n8.x4.shared.b16 {%0,%1,%2,%3}, [%4];"
                 : "=r"(r0), "=r"(r1), "=r"(r2), "=r"(r3) : "r"(a));
}
__device__ __forceinline__ void mma16816(float* c, const unsigned* a, const unsigned* b) {
    asm volatile("mma.sync.aligned.m16n8k16.row.col.f32.bf16.bf16.f32 "
                 "{%0,%1,%2,%3},{%4,%5,%6,%7},{%8,%9},{%0,%1,%2,%3};"
                 : "+f"(c[0]), "+f"(c[1]), "+f"(c[2]), "+f"(c[3])
                 : "r"(a[0]), "r"(a[1]), "r"(a[2]), "r"(a[3]), "r"(b[0]), "r"(b[1]));
}
__device__ __forceinline__ void cp16(unsigned s, const void* g) {
    asm volatile("cp.async.cg.shared.global [%0], [%1], 16;" :: "r"(s), "l"(g));
}
__device__ __forceinline__ unsigned bf2pack(float lo, float hi) {
    __nv_bfloat162 t = __floats2bfloat162_rn(lo, hi);
    return *(unsigned*)&t;
}

// ---------------------------------------------------------------------------
// prep: per-n -> zz (sequential fp32 mul+add) + bf16 Zh row + fp32 g_zt row;
//       per-k -> ee + bf16 Eh row. All row writes thread-contiguous.
// ---------------------------------------------------------------------------
__global__ void prep_kernel(const float* __restrict__ z,
                            const float* __restrict__ emb) {
    int i = blockIdx.x * 256 + threadIdx.x;
    if (i == 0) { g_loss = 0.0; g_ncand = 0u; }
    if (i < NVEC) {
        g_best[i] = 0xFFFFFFFFFFFFFFFFull;
        int b = i >> 10, hw = i & 1023;
        const float* p = z + (size_t)b * 262144 + hw;
        float acc = 0.f;
        #pragma unroll 1
        for (int ch = 0; ch < 8; ch++) {
            float v[32];
            #pragma unroll
            for (int j = 0; j < 32; j++)
                v[j] = p[(size_t)(ch * 32 + j) * 1024];
            #pragma unroll
            for (int j = 0; j < 32; j++)
                acc = __fadd_rn(acc, __fmul_rn(v[j], v[j]));
            uint4* dst = (uint4*)&g_Zh[(size_t)i * 256 + ch * 32];
            #pragma unroll
            for (int q = 0; q < 4; q++)
                dst[q] = make_uint4(bf2pack(v[q*8+0], v[q*8+1]), bf2pack(v[q*8+2], v[q*8+3]),
                                    bf2pack(v[q*8+4], v[q*8+5]), bf2pack(v[q*8+6], v[q*8+7]));
            float4* zt = (float4*)&g_zt[(size_t)i * 256 + ch * 32];
            #pragma unroll
            for (int q = 0; q < 8; q++)
                zt[q] = make_float4(v[q*4], v[q*4+1], v[q*4+2], v[q*4+3]);
        }
        g_zz[i] = acc;
    } else if (i < NVEC + KCODES) {
        int k = i - NVEC;
        const float4* p = (const float4*)(emb + (size_t)k * 256);
        float acc = 0.f;
        #pragma unroll 1
        for (int ch = 0; ch < 8; ch++) {
            float v[32];
            #pragma unroll
            for (int q = 0; q < 8; q++) {
                float4 w = p[ch * 8 + q];
                v[q*4] = w.x; v[q*4+1] = w.y; v[q*4+2] = w.z; v[q*4+3] = w.w;
            }
            #pragma unroll
            for (int j = 0; j < 32; j++)
                acc = __fadd_rn(acc, __fmul_rn(v[j], v[j]));
            uint4* dst = (uint4*)&g_Eh[(size_t)k * 256 + ch * 32];
            #pragma unroll
            for (int q = 0; q < 4; q++)
                dst[q] = make_uint4(bf2pack(v[q*8+0], v[q*8+1]), bf2pack(v[q*8+2], v[q*8+3]),
                                    bf2pack(v[q*8+4], v[q*8+5]), bf2pack(v[q*8+6], v[q*8+7]));
        }
        g_ee[k] = acc;
    }
}

// ---------------------------------------------------------------------------
// Filter GEMM: dot~ = Zh*Eh (K=256), fp32 acc. CTA 128n x 128k, 8 warps (2x4),
// warp 64x32, mma m16n8k16. 3-stage cp.async circular pipeline, 1 sync/chunk.
// Epilogue: per-(row, 8k-unit) min -> smem transpose -> coalesced g_stmin.
// ---------------------------------------------------------------------------
__global__ __launch_bounds__(256, 2)
void filter_gemm_kernel() {
    extern __shared__ char sm[];
    const unsigned smBase = smem_u32(sm);

    const int t = threadIdx.x;
    const int lane = t & 31, warp = t >> 5;
    const int wm = warp >> 2, wn = warp & 3;
    const int bm = blockIdx.x >> 6, bn = blockIdx.x & 63;

    float acc[4][4][4];
    #pragma unroll
    for (int mi = 0; mi < 4; mi++)
        #pragma unroll
        for (int ni = 0; ni < 4; ni++)
            #pragma unroll
            for (int r = 0; r < 4; r++) acc[mi][ni][r] = 0.f;

    const int rA = lane & 15, cAsel = lane >> 4, l7 = lane & 7;
    const int rB = (lane & 7) + ((lane >> 4) << 3), cBsel = (lane >> 3) & 1;

    const int lrow = t >> 3, lch = t & 7;
    const unsigned ldst_off = (unsigned)(lrow * 128 + ((lch ^ (lrow & 7)) << 4));

    #define ISSUE_CHUNK(q, s) do {                                            \
        int coff_ = (q) * 64;                                                  \
        _Pragma("unroll")                                                      \
        for (int i_ = 0; i_ < 4; i_++) {                                       \
            int row_ = lrow + i_ * 32;                                         \
            unsigned off_ = ldst_off + i_ * 32 * 128;                          \
            cp16(smBase + (s) * 32768 + off_,                                  \
                 g_Zh + (size_t)(bm * 128 + row_) * 256 + coff_ + lch * 8);    \
            cp16(smBase + (s) * 32768 + 16384 + off_,                          \
                 g_Eh + (size_t)(bn * 128 + row_) * 256 + coff_ + lch * 8);    \
        }                                                                      \
        asm volatile("cp.async.commit_group;");                                \
    } while (0)

    ISSUE_CHUNK(0, 0);
    ISSUE_CHUNK(1, 1);

    #pragma unroll
    for (int q = 0; q < 4; q++) {
        if (q < 3) asm volatile("cp.async.wait_group 1;");
        else       asm volatile("cp.async.wait_group 0;");
        __syncthreads();

        const unsigned Ab = smBase + (q % 3) * 32768;
        const unsigned Bb = Ab + 16384;

        #pragma unroll
        for (int ks = 0; ks < 4; ks++) {
            unsigned a[4][4], b[4][2];
            #pragma unroll
            for (int mi = 0; mi < 4; mi++) {
                int row = wm * 64 + mi * 16 + rA;
                unsigned ad = Ab + row * 128 + (((2 * ks + cAsel) ^ l7) << 4);
                ldsm4(a[mi][0], a[mi][1], a[mi][2], a[mi][3], ad);
            }
            #pragma unroll
            for (int nj = 0; nj < 2; nj++) {
                int row = wn * 32 + nj * 16 + rB;
                unsigned bd = Bb + row * 128 + (((2 * ks + cBsel) ^ l7) << 4);
                unsigned r0, r1, r2, r3;
                ldsm4(r0, r1, r2, r3, bd);
                b[2 * nj][0] = r0; b[2 * nj][1] = r1;
                b[2 * nj + 1][0] = r2; b[2 * nj + 1][1] = r3;
            }
            #pragma unroll
            for (int mi = 0; mi < 4; mi++)
                #pragma unroll
                for (int ni = 0; ni < 4; ni++)
                    mma16816(acc[mi][ni], a[mi], b[ni]);
        }
        if (q < 2) ISSUE_CHUNK(q + 2, (q + 2) % 3);
    }

    __syncthreads();
    float* st = (float*)sm;   // [128 rows][16 units]
    #pragma unroll
    for (int mi = 0; mi < 4; mi++) {
        int rl0 = wm * 64 + mi * 16 + (lane >> 2);
        int r0 = bm * 128 + rl0;
        float zz0 = g_zz[r0], zz1 = g_zz[r0 + 8];
        #pragma unroll
        for (int ni = 0; ni < 4; ni++) {
            int col = bn * 128 + wn * 32 + ni * 8 + (lane & 3) * 2;
            float e0 = g_ee[col], e1 = g_ee[col + 1];
            float d00 = __fsub_rn(__fadd_rn(zz0, e0), __fmul_rn(2.f, acc[mi][ni][0]));
            float d01 = __fsub_rn(__fadd_rn(zz0, e1), __fmul_rn(2.f, acc[mi][ni][1]));
            float d10 = __fsub_rn(__fadd_rn(zz1, e0), __fmul_rn(2.f, acc[mi][ni][2]));
            float d11 = __fsub_rn(__fadd_rn(zz1, e1), __fmul_rn(2.f, acc[mi][ni][3]));
            float vlo = fminf(d00, d01), vhi = fminf(d10, d11);
            vlo = fminf(vlo, __shfl_xor_sync(0xffffffffu, vlo, 1));
            vlo = fminf(vlo, __shfl_xor_sync(0xffffffffu, vlo, 2));
            vhi = fminf(vhi, __shfl_xor_sync(0xffffffffu, vhi, 1));
            vhi = fminf(vhi, __shfl_xor_sync(0xffffffffu, vhi, 2));
            if ((lane & 3) == 0) {
                st[rl0 * 16 + wn * 4 + ni] = vlo;
                st[(rl0 + 8) * 16 + wn * 4 + ni] = vhi;
            }
        }
    }
    __syncthreads();
    {
        int rl = t >> 1, u0 = (t & 1) * 8;
        float* dst = &g_stmin[(size_t)(bm * 128 + rl) * UNITS + bn * 16 + u0];
        float* src = &st[rl * 16 + u0];
        *(float4*)dst = *(float4*)src;
        *(float4*)(dst + 4) = *(float4*)(src + 4);
    }
}

// ---------------------------------------------------------------------------
// Extraction: warp per n. Global min over 1024 unit-mins, flag units within
// MARGIN, append (n<<10|unit) to global candidate list.
// ---------------------------------------------------------------------------
__global__ __launch_bounds__(256)
void extract_kernel() {
    int n = (blockIdx.x * 256 + threadIdx.x) >> 5;
    int lane = threadIdx.x & 31;
    if (n >= NVEC) return;
    const float4* row = (const float4*)&g_stmin[(size_t)n * UNITS];

    float4 v[8];
    float mn = CUDART_INF_F;
    #pragma unroll
    for (int j = 0; j < 8; j++) {
        v[j] = row[j * 32 + lane];
        mn = fminf(mn, fminf(fminf(v[j].x, v[j].y), fminf(v[j].z, v[j].w)));
    }
    #pragma unroll
    for (int o = 16; o; o >>= 1) mn = fminf(mn, __shfl_xor_sync(0xffffffffu, mn, o));
    const float thr = mn + MARGIN;

    unsigned cnt = 0;
    #pragma unroll
    for (int j = 0; j < 8; j++)
        cnt += (v[j].x <= thr) + (v[j].y <= thr) + (v[j].z <= thr) + (v[j].w <= thr);

    unsigned p = cnt;
    #pragma unroll
    for (int o = 1; o < 32; o <<= 1) {
        unsigned tv = __shfl_up_sync(0xffffffffu, p, o);
        if (lane >= o) p += tv;
    }
    unsigned excl = p - cnt;
    unsigned total = __shfl_sync(0xffffffffu, p, 31);
    unsigned base = 0;
    if (lane == 31) base = atomicAdd(&g_ncand, total);
    base = __shfl_sync(0xffffffffu, base, 31);

    unsigned w = base + excl;
    #pragma unroll
    for (int j = 0; j < 8; j++) {
        int u0 = (j * 32 + lane) * 4;
        float vv[4] = { v[j].x, v[j].y, v[j].z, v[j].w };
        #pragma unroll
        for (int c = 0; c < 4; c++)
            if (vv[c] <= thr && w < CAND_MAX)
                g_cand[w++] = ((unsigned)n << 10) | (unsigned)(u0 + c);
    }
}

// ---------------------------------------------------------------------------
// Rescore: 4 candidates per warp, 32 lanes active. Lane: sub=lane>>3 ->
// candidate, kl=lane&7 -> k within unit. Bit-exact sequential fma chain
// (c ascending; float4 comps x,y,z,w ascending) on g_zt (broadcast within
// 8-lane group) and emb row (contiguous per lane). 8-lane shuffle reduce ->
// one atomicMin(g_best[n]) per candidate.
// ---------------------------------------------------------------------------
#define RS_BLOCKS 592
__global__ __launch_bounds__(128)
void rescore_kernel(const float* __restrict__ zt_unused,
                    const float* __restrict__ emb) {
    const int warp = threadIdx.x >> 5, lane = threadIdx.x & 31;
    const int sub = lane >> 3, kl = lane & 7;
    const unsigned gwarp = blockIdx.x * 4 + warp;
    const unsigned stride4 = RS_BLOCKS * 4 * 4;
    const unsigned ncand = g_ncand;

    for (unsigned base = gwarp * 4; base < ncand; base += stride4) {
        unsigned ci = base + (unsigned)sub;
        bool active = ci < ncand;
        unsigned cd = g_cand[active ? ci : 0];
        int n = cd >> 10, unit = cd & 1023;
        int k = unit * 8 + kl;

        const float4* zr = (const float4*)&g_zt[(size_t)n * 256];
        const float4* er = (const float4*)&emb[(size_t)k * 256];
        float acc = 0.f;
        #pragma unroll 8
        for (int c4 = 0; c4 < 64; c4++) {
            float4 zf = zr[c4];
            float4 ef = er[c4];
            acc = fmaf(zf.x, ef.x, acc);
            acc = fmaf(zf.y, ef.y, acc);
            acc = fmaf(zf.z, ef.z, acc);
            acc = fmaf(zf.w, ef.w, acc);
        }
        float d = __fsub_rn(__fadd_rn(g_zz[n], g_ee[k]), __fmul_rn(2.f, acc));
        unsigned long long key =
            ((unsigned long long)__float_as_uint(d) << 32) | (unsigned)k;
        #pragma unroll
        for (int o = 4; o; o >>= 1) {
            unsigned long long ok = __shfl_xor_sync(0xffffffffu, key, o);
            if (ok < key) key = ok;
        }
        if (kl == 0 && active) atomicMin(&g_best[n], key);
    }
}

// ---------------------------------------------------------------------------
// gatherq: zq[n][c] = emb[idx[n]][c], fully coalesced (thread per (n, f4)).
// ---------------------------------------------------------------------------
__global__ void gatherq_kernel(const float* __restrict__ emb) {
    int idx = blockIdx.x * 256 + threadIdx.x;      // NVEC*64
    int n = idx >> 6, f = idx & 63;
    unsigned k = (unsigned)(g_best[n] & 0xFFFFFFFFull);
    ((float4*)g_zq)[(size_t)n * 64 + f] = ((const float4*)emb)[(size_t)k * 64 + f];
}

// ---------------------------------------------------------------------------
// finish: out[o] = fl(z + fl(zq - z)) via 32x32 smem transpose tile; all
// global accesses coalesced. loss = sum fl(zq-z)^2 (double atomics).
// ---------------------------------------------------------------------------
__global__ __launch_bounds__(256)
void finish_kernel(const float* __restrict__ z, float* __restrict__ out) {
    __shared__ float s[32 * 33];
    const int bid = blockIdx.x;
    const int b = bid >> 8, ct = (bid >> 5) & 7, ht = bid & 31;
    const int c0 = ct * 32, hw0 = ht * 32;
    const int t = threadIdx.x;

    {
        int r = t >> 3, q4 = t & 7;
        int n = b * 1024 + hw0 + r;
        float4 w = *(const float4*)&g_zq[(size_t)n * 256 + c0 + q4 * 4];
        float* d = &s[r * 33 + q4 * 4];
        d[0] = w.x; d[1] = w.y; d[2] = w.z; d[3] = w.w;
    }
    __syncthreads();

    const int hwl = t & 31, cl0 = t >> 5;
    float d2s = 0.f;
    #pragma unroll
    for (int it = 0; it < 4; it++) {
        int cl = cl0 + it * 8;
        size_t o = (size_t)b * 262144 + (size_t)(c0 + cl) * 1024 + hw0 + hwl;
        float zv = z[o];
        float q  = s[hwl * 33 + cl];
        float diff = __fsub_rn(q, zv);
        out[o] = __fadd_rn(zv, diff);
        d2s += __fmul_rn(diff, diff);
    }

    #pragma unroll
    for (int off = 16; off; off >>= 1)
        d2s += __shfl_xor_sync(0xffffffffu, d2s, off);
    __shared__ float red[8];
    if ((t & 31) == 0) red[t >> 5] = d2s;
    __syncthreads();
    if (t < 8) {
        float v = red[t];
        #pragma unroll
        for (int off = 4; off; off >>= 1)
            v += __shfl_xor_sync(0xffu, v, off);
        if (t == 0) atomicAdd(&g_loss, (double)v);
    }
}

__global__ void tail_kernel(float* __restrict__ out, int out_size) {
    int i = blockIdx.x * 256 + threadIdx.x;
    if (i < NVEC && out_size >= ZELEMS + NVEC)
        out[ZELEMS + i] = (float)(unsigned)(g_best[i] & 0xFFFFFFFFull);
    if (i == 0 && out_size >= ZELEMS + NVEC + 1) {
        float m = (float)(g_loss / (double)ZELEMS);
        out[ZELEMS + NVEC] = __fadd_rn(m, __fmul_rn(0.25f, m)); // m + BETA*m
    }
}

// ---------------------------------------------------------------------------
extern "C" void kernel_launch(void* const* d_in, const int* in_sizes, int n_in,
                              void* d_out, int out_size) {
    const float* z   = (const float*)d_in[0];
    const float* emb = (const float*)d_in[1];
    float* out = (float*)d_out;

    cudaFuncSetAttribute(filter_gemm_kernel,
                         cudaFuncAttributeMaxDynamicSharedMemorySize, 98304);

    prep_kernel<<<(NVEC + KCODES + 255) / 256, 256>>>(z, emb);
    filter_gemm_kernel<<<128 * 64, 256, 98304>>>();
    extract_kernel<<<NVEC * 32 / 256, 256>>>();
    rescore_kernel<<<RS_BLOCKS, 128>>>(z, emb);
    gatherq_kernel<<<NVEC * 64 / 256, 256>>>(emb);
    finish_kernel<<<16 * 8 * 32, 256>>>(z, out);
    tail_kernel<<<(NVEC + 255) / 256, 256>>>(out, out_size);
}

// round 12
// speedup vs baseline: 6.0044x; 1.0393x over previous
#include <cuda_runtime.h>
#include <cuda_bf16.h>
#include <math_constants.h>

#define NVEC   16384
#define KCODES 8192
#define CDIM   256
#define ZELEMS (16*256*32*32)   /* 4194304 */
#define UNITS  1024             /* per-n units of 8 k */
#define MARGIN 2e-4f
#define CAND_MAX (1u<<22)

__device__ float  g_zz[NVEC];
__device__ float  g_ee[KCODES];
__device__ double g_loss;
__device__ __nv_bfloat16 g_Zh[(size_t)NVEC * CDIM];
__device__ __nv_bfloat16 g_Eh[(size_t)KCODES * CDIM];
__device__ float  g_zt[(size_t)NVEC * CDIM];     /* z transposed to [n][c], fp32 */
__device__ float  g_stmin[(size_t)NVEC * UNITS];
__device__ unsigned g_cand[CAND_MAX];
__device__ unsigned g_ncand;
__device__ unsigned long long g_best[NVEC];
__device__ float  g_zq[(size_t)NVEC * CDIM];

// ---------------------------------------------------------------------------
__device__ __forceinline__ unsigned smem_u32(const void* p) {
    return (unsigned)__cvta_generic_to_shared(p);
}
__device__ __forceinline__ void ldsm4(unsigned& r0, unsigned& r1,
                                      unsigned& r2, unsigned& r3, unsigned a) {
    asm volatile("ldmatrix.sync.aligned.m8n8.x4.shared.b16 {%0,%1,%2,%3}, [%4];"
                 : "=r"(r0), "=r"(r1), "=r"(r2), "=r"(r3) : "r"(a));
}
__device__ __forceinline__ void mma16816(float* c, const unsigned* a, const unsigned* b) {
    asm volatile("mma.sync.aligned.m16n8k16.row.col.f32.bf16.bf16.f32 "
                 "{%0,%1,%2,%3},{%4,%5,%6,%7},{%8,%9},{%0,%1,%2,%3};"
                 : "+f"(c[0]), "+f"(c[1]), "+f"(c[2]), "+f"(c[3])
                 : "r"(a[0]), "r"(a[1]), "r"(a[2]), "r"(a[3]), "r"(b[0]), "r"(b[1]));
}
__device__ __forceinline__ void cp16(unsigned s, const void* g) {
    asm volatile("cp.async.cg.shared.global [%0], [%1], 16;" :: "r"(s), "l"(g));
}
__device__ __forceinline__ unsigned bf2pack(float lo, float hi) {
    __nv_bfloat162 t = __floats2bfloat162_rn(lo, hi);
    return *(unsigned*)&t;
}

// ---------------------------------------------------------------------------
// prep: per-n -> zz (sequential fp32 mul+add) + bf16 Zh row + fp32 g_zt row;
//       per-k -> ee + bf16 Eh row. All row writes thread-contiguous.
// ---------------------------------------------------------------------------
__global__ void prep_kernel(const float* __restrict__ z,
                            const float* __restrict__ emb) {
    int i = blockIdx.x * 256 + threadIdx.x;
    if (i == 0) { g_loss = 0.0; g_ncand = 0u; }
    if (i < NVEC) {
        g_best[i] = 0xFFFFFFFFFFFFFFFFull;
        int b = i >> 10, hw = i & 1023;
        const float* p = z + (size_t)b * 262144 + hw;
        float acc = 0.f;
        #pragma unroll 1
        for (int ch = 0; ch < 8; ch++) {
            float v[32];
            #pragma unroll
            for (int j = 0; j < 32; j++)
                v[j] = p[(size_t)(ch * 32 + j) * 1024];
            #pragma unroll
            for (int j = 0; j < 32; j++)
                acc = __fadd_rn(acc, __fmul_rn(v[j], v[j]));
            uint4* dst = (uint4*)&g_Zh[(size_t)i * 256 + ch * 32];
            #pragma unroll
            for (int q = 0; q < 4; q++)
                dst[q] = make_uint4(bf2pack(v[q*8+0], v[q*8+1]), bf2pack(v[q*8+2], v[q*8+3]),
                                    bf2pack(v[q*8+4], v[q*8+5]), bf2pack(v[q*8+6], v[q*8+7]));
            float4* zt = (float4*)&g_zt[(size_t)i * 256 + ch * 32];
            #pragma unroll
            for (int q = 0; q < 8; q++)
                zt[q] = make_float4(v[q*4], v[q*4+1], v[q*4+2], v[q*4+3]);
        }
        g_zz[i] = acc;
    } else if (i < NVEC + KCODES) {
        int k = i - NVEC;
        const float4* p = (const float4*)(emb + (size_t)k * 256);
        float acc = 0.f;
        #pragma unroll 1
        for (int ch = 0; ch < 8; ch++) {
            float v[32];
            #pragma unroll
            for (int q = 0; q < 8; q++) {
                float4 w = p[ch * 8 + q];
                v[q*4] = w.x; v[q*4+1] = w.y; v[q*4+2] = w.z; v[q*4+3] = w.w;
            }
            #pragma unroll
            for (int j = 0; j < 32; j++)
                acc = __fadd_rn(acc, __fmul_rn(v[j], v[j]));
            uint4* dst = (uint4*)&g_Eh[(size_t)k * 256 + ch * 32];
            #pragma unroll
            for (int q = 0; q < 4; q++)
                dst[q] = make_uint4(bf2pack(v[q*8+0], v[q*8+1]), bf2pack(v[q*8+2], v[q*8+3]),
                                    bf2pack(v[q*8+4], v[q*8+5]), bf2pack(v[q*8+6], v[q*8+7]));
        }
        g_ee[k] = acc;
    }
}

// ---------------------------------------------------------------------------
// Filter GEMM: dot~ = Zh*Eh (K=256), fp32 acc. CTA 128n x 128k, 8 warps (2x4),
// warp 64x32, mma m16n8k16. 3-stage cp.async circular pipeline, 1 sync/chunk.
// Epilogue: per-(row, 8k-unit) min -> smem transpose -> coalesced g_stmin.
// ---------------------------------------------------------------------------
__global__ __launch_bounds__(256, 2)
void filter_gemm_kernel() {
    extern __shared__ char sm[];
    const unsigned smBase = smem_u32(sm);

    const int t = threadIdx.x;
    const int lane = t & 31, warp = t >> 5;
    const int wm = warp >> 2, wn = warp & 3;
    const int bm = blockIdx.x >> 6, bn = blockIdx.x & 63;

    float acc[4][4][4];
    #pragma unroll
    for (int mi = 0; mi < 4; mi++)
        #pragma unroll
        for (int ni = 0; ni < 4; ni++)
            #pragma unroll
            for (int r = 0; r < 4; r++) acc[mi][ni][r] = 0.f;

    const int rA = lane & 15, cAsel = lane >> 4, l7 = lane & 7;
    const int rB = (lane & 7) + ((lane >> 4) << 3), cBsel = (lane >> 3) & 1;

    const int lrow = t >> 3, lch = t & 7;
    const unsigned ldst_off = (unsigned)(lrow * 128 + ((lch ^ (lrow & 7)) << 4));

    #define ISSUE_CHUNK(q, s) do {                                            \
        int coff_ = (q) * 64;                                                  \
        _Pragma("unroll")                                                      \
        for (int i_ = 0; i_ < 4; i_++) {                                       \
            int row_ = lrow + i_ * 32;                                         \
            unsigned off_ = ldst_off + i_ * 32 * 128;                          \
            cp16(smBase + (s) * 32768 + off_,                                  \
                 g_Zh + (size_t)(bm * 128 + row_) * 256 + coff_ + lch * 8);    \
            cp16(smBase + (s) * 32768 + 16384 + off_,                          \
                 g_Eh + (size_t)(bn * 128 + row_) * 256 + coff_ + lch * 8);    \
        }                                                                      \
        asm volatile("cp.async.commit_group;");                                \
    } while (0)

    ISSUE_CHUNK(0, 0);
    ISSUE_CHUNK(1, 1);

    #pragma unroll
    for (int q = 0; q < 4; q++) {
        if (q < 3) asm volatile("cp.async.wait_group 1;");
        else       asm volatile("cp.async.wait_group 0;");
        __syncthreads();

        const unsigned Ab = smBase + (q % 3) * 32768;
        const unsigned Bb = Ab + 16384;

        #pragma unroll
        for (int ks = 0; ks < 4; ks++) {
            unsigned a[4][4], b[4][2];
            #pragma unroll
            for (int mi = 0; mi < 4; mi++) {
                int row = wm * 64 + mi * 16 + rA;
                unsigned ad = Ab + row * 128 + (((2 * ks + cAsel) ^ l7) << 4);
                ldsm4(a[mi][0], a[mi][1], a[mi][2], a[mi][3], ad);
            }
            #pragma unroll
            for (int nj = 0; nj < 2; nj++) {
                int row = wn * 32 + nj * 16 + rB;
                unsigned bd = Bb + row * 128 + (((2 * ks + cBsel) ^ l7) << 4);
                unsigned r0, r1, r2, r3;
                ldsm4(r0, r1, r2, r3, bd);
                b[2 * nj][0] = r0; b[2 * nj][1] = r1;
                b[2 * nj + 1][0] = r2; b[2 * nj + 1][1] = r3;
            }
            #pragma unroll
            for (int mi = 0; mi < 4; mi++)
                #pragma unroll
                for (int ni = 0; ni < 4; ni++)
                    mma16816(acc[mi][ni], a[mi], b[ni]);
        }
        if (q < 2) ISSUE_CHUNK(q + 2, (q + 2) % 3);
    }

    __syncthreads();
    float* st = (float*)sm;   // [128 rows][16 units]
    #pragma unroll
    for (int mi = 0; mi < 4; mi++) {
        int rl0 = wm * 64 + mi * 16 + (lane >> 2);
        int r0 = bm * 128 + rl0;
        float zz0 = g_zz[r0], zz1 = g_zz[r0 + 8];
        #pragma unroll
        for (int ni = 0; ni < 4; ni++) {
            int col = bn * 128 + wn * 32 + ni * 8 + (lane & 3) * 2;
            float e0 = g_ee[col], e1 = g_ee[col + 1];
            float d00 = __fsub_rn(__fadd_rn(zz0, e0), __fmul_rn(2.f, acc[mi][ni][0]));
            float d01 = __fsub_rn(__fadd_rn(zz0, e1), __fmul_rn(2.f, acc[mi][ni][1]));
            float d10 = __fsub_rn(__fadd_rn(zz1, e0), __fmul_rn(2.f, acc[mi][ni][2]));
            float d11 = __fsub_rn(__fadd_rn(zz1, e1), __fmul_rn(2.f, acc[mi][ni][3]));
            float vlo = fminf(d00, d01), vhi = fminf(d10, d11);
            vlo = fminf(vlo, __shfl_xor_sync(0xffffffffu, vlo, 1));
            vlo = fminf(vlo, __shfl_xor_sync(0xffffffffu, vlo, 2));
            vhi = fminf(vhi, __shfl_xor_sync(0xffffffffu, vhi, 1));
            vhi = fminf(vhi, __shfl_xor_sync(0xffffffffu, vhi, 2));
            if ((lane & 3) == 0) {
                st[rl0 * 16 + wn * 4 + ni] = vlo;
                st[(rl0 + 8) * 16 + wn * 4 + ni] = vhi;
            }
        }
    }
    __syncthreads();
    {
        int rl = t >> 1, u0 = (t & 1) * 8;
        float* dst = &g_stmin[(size_t)(bm * 128 + rl) * UNITS + bn * 16 + u0];
        float* src = &st[rl * 16 + u0];
        *(float4*)dst = *(float4*)src;
        *(float4*)(dst + 4) = *(float4*)(src + 4);
    }
}

// ---------------------------------------------------------------------------
// Extraction: warp per n. Global min over 1024 unit-mins, flag units within
// MARGIN, append (n<<10|unit) to global candidate list.
// ---------------------------------------------------------------------------
__global__ __launch_bounds__(256)
void extract_kernel() {
    int n = (blockIdx.x * 256 + threadIdx.x) >> 5;
    int lane = threadIdx.x & 31;
    if (n >= NVEC) return;
    const float4* row = (const float4*)&g_stmin[(size_t)n * UNITS];

    float4 v[8];
    float mn = CUDART_INF_F;
    #pragma unroll
    for (int j = 0; j < 8; j++) {
        v[j] = row[j * 32 + lane];
        mn = fminf(mn, fminf(fminf(v[j].x, v[j].y), fminf(v[j].z, v[j].w)));
    }
    #pragma unroll
    for (int o = 16; o; o >>= 1) mn = fminf(mn, __shfl_xor_sync(0xffffffffu, mn, o));
    const float thr = mn + MARGIN;

    unsigned cnt = 0;
    #pragma unroll
    for (int j = 0; j < 8; j++)
        cnt += (v[j].x <= thr) + (v[j].y <= thr) + (v[j].z <= thr) + (v[j].w <= thr);

    unsigned p = cnt;
    #pragma unroll
    for (int o = 1; o < 32; o <<= 1) {
        unsigned tv = __shfl_up_sync(0xffffffffu, p, o);
        if (lane >= o) p += tv;
    }
    unsigned excl = p - cnt;
    unsigned total = __shfl_sync(0xffffffffu, p, 31);
    unsigned base = 0;
    if (lane == 31) base = atomicAdd(&g_ncand, total);
    base = __shfl_sync(0xffffffffu, base, 31);

    unsigned w = base + excl;
    #pragma unroll
    for (int j = 0; j < 8; j++) {
        int u0 = (j * 32 + lane) * 4;
        float vv[4] = { v[j].x, v[j].y, v[j].z, v[j].w };
        #pragma unroll
        for (int c = 0; c < 4; c++)
            if (vv[c] <= thr && w < CAND_MAX)
                g_cand[w++] = ((unsigned)n << 10) | (unsigned)(u0 + c);
    }
}

// ---------------------------------------------------------------------------
// Rescore: 4 candidates per warp, 32 lanes active. Lane: sub=lane>>3 ->
// candidate, kl=lane&7 -> k within unit. Bit-exact sequential fma chain
// (c ascending; float4 comps x,y,z,w ascending) on g_zt (broadcast within
// 8-lane group) and emb row (contiguous per lane). 8-lane shuffle reduce ->
// one atomicMin(g_best[n]) per candidate. 256-thr blocks for occupancy.
// ---------------------------------------------------------------------------
#define RS_BLOCKS 592
__global__ __launch_bounds__(256)
void rescore_kernel(const float* __restrict__ zt_unused,
                    const float* __restrict__ emb) {
    const int warp = threadIdx.x >> 5, lane = threadIdx.x & 31;
    const int sub = lane >> 3, kl = lane & 7;
    const unsigned gwarp = blockIdx.x * 8 + warp;
    const unsigned stride4 = RS_BLOCKS * 8 * 4;
    const unsigned ncand = g_ncand;

    for (unsigned base = gwarp * 4; base < ncand; base += stride4) {
        unsigned ci = base + (unsigned)sub;
        bool active = ci < ncand;
        unsigned cd = g_cand[active ? ci : 0];
        int n = cd >> 10, unit = cd & 1023;
        int k = unit * 8 + kl;

        const float4* zr = (const float4*)&g_zt[(size_t)n * 256];
        const float4* er = (const float4*)&emb[(size_t)k * 256];
        float acc = 0.f;
        #pragma unroll 8
        for (int c4 = 0; c4 < 64; c4++) {
            float4 zf = zr[c4];
            float4 ef = er[c4];
            acc = fmaf(zf.x, ef.x, acc);
            acc = fmaf(zf.y, ef.y, acc);
            acc = fmaf(zf.z, ef.z, acc);
            acc = fmaf(zf.w, ef.w, acc);
        }
        float d = __fsub_rn(__fadd_rn(g_zz[n], g_ee[k]), __fmul_rn(2.f, acc));
        unsigned long long key =
            ((unsigned long long)__float_as_uint(d) << 32) | (unsigned)k;
        #pragma unroll
        for (int o = 4; o; o >>= 1) {
            unsigned long long ok = __shfl_xor_sync(0xffffffffu, key, o);
            if (ok < key) key = ok;
        }
        if (kl == 0 && active) atomicMin(&g_best[n], key);
    }
}

// ---------------------------------------------------------------------------
// gatherq: zq[n][c] = emb[idx[n]][c], fully coalesced (thread per (n, f4)).
// ---------------------------------------------------------------------------
__global__ void gatherq_kernel(const float* __restrict__ emb) {
    int idx = blockIdx.x * 256 + threadIdx.x;      // NVEC*64
    int n = idx >> 6, f = idx & 63;
    unsigned k = (unsigned)(g_best[n] & 0xFFFFFFFFull);
    ((float4*)g_zq)[(size_t)n * 64 + f] = ((const float4*)emb)[(size_t)k * 64 + f];
}

// ---------------------------------------------------------------------------
// finish: out[o] = fl(z + fl(zq - z)) via 32x32 smem transpose tile; all
// global accesses coalesced. loss = sum fl(zq-z)^2 (double atomics).
// ---------------------------------------------------------------------------
__global__ __launch_bounds__(256)
void finish_kernel(const float* __restrict__ z, float* __restrict__ out) {
    __shared__ float s[32 * 33];
    const int bid = blockIdx.x;
    const int b = bid >> 8, ct = (bid >> 5) & 7, ht = bid & 31;
    const int c0 = ct * 32, hw0 = ht * 32;
    const int t = threadIdx.x;

    {
        int r = t >> 3, q4 = t & 7;
        int n = b * 1024 + hw0 + r;
        float4 w = *(const float4*)&g_zq[(size_t)n * 256 + c0 + q4 * 4];
        float* d = &s[r * 33 + q4 * 4];
        d[0] = w.x; d[1] = w.y; d[2] = w.z; d[3] = w.w;
    }
    __syncthreads();

    const int hwl = t & 31, cl0 = t >> 5;
    float d2s = 0.f;
    #pragma unroll
    for (int it = 0; it < 4; it++) {
        int cl = cl0 + it * 8;
        size_t o = (size_t)b * 262144 + (size_t)(c0 + cl) * 1024 + hw0 + hwl;
        float zv = z[o];
        float q  = s[hwl * 33 + cl];
        float diff = __fsub_rn(q, zv);
        out[o] = __fadd_rn(zv, diff);
        d2s += __fmul_rn(diff, diff);
    }

    #pragma unroll
    for (int off = 16; off; off >>= 1)
        d2s += __shfl_xor_sync(0xffffffffu, d2s, off);
    __shared__ float red[8];
    if ((t & 31) == 0) red[t >> 5] = d2s;
    __syncthreads();
    if (t < 8) {
        float v = red[t];
        #pragma unroll
        for (int off = 4; off; off >>= 1)
            v += __shfl_xor_sync(0xffu, v, off);
        if (t == 0) atomicAdd(&g_loss, (double)v);
    }
}

__global__ void tail_kernel(float* __restrict__ out, int out_size) {
    int i = blockIdx.x * 256 + threadIdx.x;
    if (i < NVEC && out_size >= ZELEMS + NVEC)
        out[ZELEMS + i] = (float)(unsigned)(g_best[i] & 0xFFFFFFFFull);
    if (i == 0 && out_size >= ZELEMS + NVEC + 1) {
        float m = (float)(g_loss / (double)ZELEMS);
        out[ZELEMS + NVEC] = __fadd_rn(m, __fmul_rn(0.25f, m)); // m + BETA*m
    }
}

// ---------------------------------------------------------------------------
extern "C" void kernel_launch(void* const* d_in, const int* in_sizes, int n_in,
                              void* d_out, int out_size) {
    const float* z   = (const float*)d_in[0];
    const float* emb = (const float*)d_in[1];
    float* out = (float*)d_out;

    cudaFuncSetAttribute(filter_gemm_kernel,
                         cudaFuncAttributeMaxDynamicSharedMemorySize, 98304);

    prep_kernel<<<(NVEC + KCODES + 255) / 256, 256>>>(z, emb);
    filter_gemm_kernel<<<128 * 64, 256, 98304>>>();
    extract_kernel<<<NVEC * 32 / 256, 256>>>();
    rescore_kernel<<<RS_BLOCKS, 256>>>(z, emb);
    gatherq_kernel<<<NVEC * 64 / 256, 256>>>(emb);
    finish_kernel<<<16 * 8 * 32, 256>>>(z, out);
    tail_kernel<<<(NVEC + 255) / 256, 256>>>(out, out_size);
}

// round 13
// speedup vs baseline: 6.0500x; 1.0076x over previous
#include <cuda_runtime.h>
#include <cuda_bf16.h>
#include <math_constants.h>

#define NVEC   16384
#define KCODES 8192
#define CDIM   256
#define ZELEMS (16*256*32*32)   /* 4194304 */
#define UNITS  1024             /* per-n units of 8 k */
#define MARGIN 2e-4f
#define CAND_MAX (1u<<22)

__device__ float  g_zz[NVEC];
__device__ float  g_ee[KCODES];
__device__ double g_loss;
__device__ __nv_bfloat16 g_Zh[(size_t)NVEC * CDIM];
__device__ __nv_bfloat16 g_Eh[(size_t)KCODES * CDIM];
__device__ float  g_zt[(size_t)NVEC * CDIM];     /* z transposed to [n][c], fp32 */
__device__ float  g_stmin[(size_t)NVEC * UNITS];
__device__ unsigned g_cand[CAND_MAX];
__device__ unsigned g_ncand;
__device__ unsigned long long g_best[NVEC];
__device__ float  g_zq[(size_t)NVEC * CDIM];

// ---------------------------------------------------------------------------
__device__ __forceinline__ unsigned smem_u32(const void* p) {
    return (unsigned)__cvta_generic_to_shared(p);
}
__device__ __forceinline__ void ldsm4(unsigned& r0, unsigned& r1,
                                      unsigned& r2, unsigned& r3, unsigned a) {
    asm volatile("ldmatrix.sync.aligned.m8n8.x4.shared.b16 {%0,%1,%2,%3}, [%4];"
                 : "=r"(r0), "=r"(r1), "=r"(r2), "=r"(r3) : "r"(a));
}
__device__ __forceinline__ void mma16816(float* c, const unsigned* a, const unsigned* b) {
    asm volatile("mma.sync.aligned.m16n8k16.row.col.f32.bf16.bf16.f32 "
                 "{%0,%1,%2,%3},{%4,%5,%6,%7},{%8,%9},{%0,%1,%2,%3};"
                 : "+f"(c[0]), "+f"(c[1]), "+f"(c[2]), "+f"(c[3])
                 : "r"(a[0]), "r"(a[1]), "r"(a[2]), "r"(a[3]), "r"(b[0]), "r"(b[1]));
}
__device__ __forceinline__ void cp16(unsigned s, const void* g) {
    asm volatile("cp.async.cg.shared.global [%0], [%1], 16;" :: "r"(s), "l"(g));
}
__device__ __forceinline__ unsigned bf2pack(float lo, float hi) {
    __nv_bfloat162 t = __floats2bfloat162_rn(lo, hi);
    return *(unsigned*)&t;
}

// ---------------------------------------------------------------------------
// prep: per-n -> zz (sequential fp32 mul+add) + bf16 Zh row + fp32 g_zt row;
//       per-k -> ee + bf16 Eh row. All row writes thread-contiguous.
// ---------------------------------------------------------------------------
__global__ void prep_kernel(const float* __restrict__ z,
                            const float* __restrict__ emb) {
    int i = blockIdx.x * 256 + threadIdx.x;
    if (i == 0) { g_loss = 0.0; g_ncand = 0u; }
    if (i < NVEC) {
        g_best[i] = 0xFFFFFFFFFFFFFFFFull;
        int b = i >> 10, hw = i & 1023;
        const float* p = z + (size_t)b * 262144 + hw;
        float acc = 0.f;
        #pragma unroll 1
        for (int ch = 0; ch < 8; ch++) {
            float v[32];
            #pragma unroll
            for (int j = 0; j < 32; j++)
                v[j] = p[(size_t)(ch * 32 + j) * 1024];
            #pragma unroll
            for (int j = 0; j < 32; j++)
                acc = __fadd_rn(acc, __fmul_rn(v[j], v[j]));
            uint4* dst = (uint4*)&g_Zh[(size_t)i * 256 + ch * 32];
            #pragma unroll
            for (int q = 0; q < 4; q++)
                dst[q] = make_uint4(bf2pack(v[q*8+0], v[q*8+1]), bf2pack(v[q*8+2], v[q*8+3]),
                                    bf2pack(v[q*8+4], v[q*8+5]), bf2pack(v[q*8+6], v[q*8+7]));
            float4* zt = (float4*)&g_zt[(size_t)i * 256 + ch * 32];
            #pragma unroll
            for (int q = 0; q < 8; q++)
                zt[q] = make_float4(v[q*4], v[q*4+1], v[q*4+2], v[q*4+3]);
        }
        g_zz[i] = acc;
    } else if (i < NVEC + KCODES) {
        int k = i - NVEC;
        const float4* p = (const float4*)(emb + (size_t)k * 256);
        float acc = 0.f;
        #pragma unroll 1
        for (int ch = 0; ch < 8; ch++) {
            float v[32];
            #pragma unroll
            for (int q = 0; q < 8; q++) {
                float4 w = p[ch * 8 + q];
                v[q*4] = w.x; v[q*4+1] = w.y; v[q*4+2] = w.z; v[q*4+3] = w.w;
            }
            #pragma unroll
            for (int j = 0; j < 32; j++)
                acc = __fadd_rn(acc, __fmul_rn(v[j], v[j]));
            uint4* dst = (uint4*)&g_Eh[(size_t)k * 256 + ch * 32];
            #pragma unroll
            for (int q = 0; q < 4; q++)
                dst[q] = make_uint4(bf2pack(v[q*8+0], v[q*8+1]), bf2pack(v[q*8+2], v[q*8+3]),
                                    bf2pack(v[q*8+4], v[q*8+5]), bf2pack(v[q*8+6], v[q*8+7]));
        }
        g_ee[k] = acc;
    }
}

// ---------------------------------------------------------------------------
// Filter GEMM: dot~ = Zh*Eh (K=256), fp32 acc. CTA 128n x 128k, 8 warps (2x4),
// warp 64x32, mma m16n8k16. 3-stage cp.async circular pipeline, 1 sync/chunk.
// Epilogue: per-(row, 8k-unit) min -> smem transpose -> coalesced g_stmin.
// ---------------------------------------------------------------------------
__global__ __launch_bounds__(256, 2)
void filter_gemm_kernel() {
    extern __shared__ char sm[];
    const unsigned smBase = smem_u32(sm);

    const int t = threadIdx.x;
    const int lane = t & 31, warp = t >> 5;
    const int wm = warp >> 2, wn = warp & 3;
    const int bm = blockIdx.x >> 6, bn = blockIdx.x & 63;

    float acc[4][4][4];
    #pragma unroll
    for (int mi = 0; mi < 4; mi++)
        #pragma unroll
        for (int ni = 0; ni < 4; ni++)
            #pragma unroll
            for (int r = 0; r < 4; r++) acc[mi][ni][r] = 0.f;

    const int rA = lane & 15, cAsel = lane >> 4, l7 = lane & 7;
    const int rB = (lane & 7) + ((lane >> 4) << 3), cBsel = (lane >> 3) & 1;

    const int lrow = t >> 3, lch = t & 7;
    const unsigned ldst_off = (unsigned)(lrow * 128 + ((lch ^ (lrow & 7)) << 4));

    #define ISSUE_CHUNK(q, s) do {                                            \
        int coff_ = (q) * 64;                                                  \
        _Pragma("unroll")                                                      \
        for (int i_ = 0; i_ < 4; i_++) {                                       \
            int row_ = lrow + i_ * 32;                                         \
            unsigned off_ = ldst_off + i_ * 32 * 128;                          \
            cp16(smBase + (s) * 32768 + off_,                                  \
                 g_Zh + (size_t)(bm * 128 + row_) * 256 + coff_ + lch * 8);    \
            cp16(smBase + (s) * 32768 + 16384 + off_,                          \
                 g_Eh + (size_t)(bn * 128 + row_) * 256 + coff_ + lch * 8);    \
        }                                                                      \
        asm volatile("cp.async.commit_group;");                                \
    } while (0)

    ISSUE_CHUNK(0, 0);
    ISSUE_CHUNK(1, 1);

    #pragma unroll
    for (int q = 0; q < 4; q++) {
        if (q < 3) asm volatile("cp.async.wait_group 1;");
        else       asm volatile("cp.async.wait_group 0;");
        __syncthreads();

        const unsigned Ab = smBase + (q % 3) * 32768;
        const unsigned Bb = Ab + 16384;

        #pragma unroll
        for (int ks = 0; ks < 4; ks++) {
            unsigned a[4][4], b[4][2];
            #pragma unroll
            for (int mi = 0; mi < 4; mi++) {
                int row = wm * 64 + mi * 16 + rA;
                unsigned ad = Ab + row * 128 + (((2 * ks + cAsel) ^ l7) << 4);
                ldsm4(a[mi][0], a[mi][1], a[mi][2], a[mi][3], ad);
            }
            #pragma unroll
            for (int nj = 0; nj < 2; nj++) {
                int row = wn * 32 + nj * 16 + rB;
                unsigned bd = Bb + row * 128 + (((2 * ks + cBsel) ^ l7) << 4);
                unsigned r0, r1, r2, r3;
                ldsm4(r0, r1, r2, r3, bd);
                b[2 * nj][0] = r0; b[2 * nj][1] = r1;
                b[2 * nj + 1][0] = r2; b[2 * nj + 1][1] = r3;
            }
            #pragma unroll
            for (int mi = 0; mi < 4; mi++)
                #pragma unroll
                for (int ni = 0; ni < 4; ni++)
                    mma16816(acc[mi][ni], a[mi], b[ni]);
        }
        if (q < 2) ISSUE_CHUNK(q + 2, (q + 2) % 3);
    }

    __syncthreads();
    float* st = (float*)sm;   // [128 rows][16 units]
    #pragma unroll
    for (int mi = 0; mi < 4; mi++) {
        int rl0 = wm * 64 + mi * 16 + (lane >> 2);
        int r0 = bm * 128 + rl0;
        float zz0 = g_zz[r0], zz1 = g_zz[r0 + 8];
        #pragma unroll
        for (int ni = 0; ni < 4; ni++) {
            int col = bn * 128 + wn * 32 + ni * 8 + (lane & 3) * 2;
            float e0 = g_ee[col], e1 = g_ee[col + 1];
            float d00 = __fsub_rn(__fadd_rn(zz0, e0), __fmul_rn(2.f, acc[mi][ni][0]));
            float d01 = __fsub_rn(__fadd_rn(zz0, e1), __fmul_rn(2.f, acc[mi][ni][1]));
            float d10 = __fsub_rn(__fadd_rn(zz1, e0), __fmul_rn(2.f, acc[mi][ni][2]));
            float d11 = __fsub_rn(__fadd_rn(zz1, e1), __fmul_rn(2.f, acc[mi][ni][3]));
            float vlo = fminf(d00, d01), vhi = fminf(d10, d11);
            vlo = fminf(vlo, __shfl_xor_sync(0xffffffffu, vlo, 1));
            vlo = fminf(vlo, __shfl_xor_sync(0xffffffffu, vlo, 2));
            vhi = fminf(vhi, __shfl_xor_sync(0xffffffffu, vhi, 1));
            vhi = fminf(vhi, __shfl_xor_sync(0xffffffffu, vhi, 2));
            if ((lane & 3) == 0) {
                st[rl0 * 16 + wn * 4 + ni] = vlo;
                st[(rl0 + 8) * 16 + wn * 4 + ni] = vhi;
            }
        }
    }
    __syncthreads();
    {
        int rl = t >> 1, u0 = (t & 1) * 8;
        float* dst = &g_stmin[(size_t)(bm * 128 + rl) * UNITS + bn * 16 + u0];
        float* src = &st[rl * 16 + u0];
        *(float4*)dst = *(float4*)src;
        *(float4*)(dst + 4) = *(float4*)(src + 4);
    }
}

// ---------------------------------------------------------------------------
// Extraction: warp per n. Global min over 1024 unit-mins, flag units within
// MARGIN, append (n<<10|unit) to global candidate list.
// ---------------------------------------------------------------------------
__global__ __launch_bounds__(256)
void extract_kernel() {
    int n = (blockIdx.x * 256 + threadIdx.x) >> 5;
    int lane = threadIdx.x & 31;
    if (n >= NVEC) return;
    const float4* row = (const float4*)&g_stmin[(size_t)n * UNITS];

    float4 v[8];
    float mn = CUDART_INF_F;
    #pragma unroll
    for (int j = 0; j < 8; j++) {
        v[j] = row[j * 32 + lane];
        mn = fminf(mn, fminf(fminf(v[j].x, v[j].y), fminf(v[j].z, v[j].w)));
    }
    #pragma unroll
    for (int o = 16; o; o >>= 1) mn = fminf(mn, __shfl_xor_sync(0xffffffffu, mn, o));
    const float thr = mn + MARGIN;

    unsigned cnt = 0;
    #pragma unroll
    for (int j = 0; j < 8; j++)
        cnt += (v[j].x <= thr) + (v[j].y <= thr) + (v[j].z <= thr) + (v[j].w <= thr);

    unsigned p = cnt;
    #pragma unroll
    for (int o = 1; o < 32; o <<= 1) {
        unsigned tv = __shfl_up_sync(0xffffffffu, p, o);
        if (lane >= o) p += tv;
    }
    unsigned excl = p - cnt;
    unsigned total = __shfl_sync(0xffffffffu, p, 31);
    unsigned base = 0;
    if (lane == 31) base = atomicAdd(&g_ncand, total);
    base = __shfl_sync(0xffffffffu, base, 31);

    unsigned w = base + excl;
    #pragma unroll
    for (int j = 0; j < 8; j++) {
        int u0 = (j * 32 + lane) * 4;
        float vv[4] = { v[j].x, v[j].y, v[j].z, v[j].w };
        #pragma unroll
        for (int c = 0; c < 4; c++)
            if (vv[c] <= thr && w < CAND_MAX)
                g_cand[w++] = ((unsigned)n << 10) | (unsigned)(u0 + c);
    }
}

// ---------------------------------------------------------------------------
// Rescore: 4 candidates per warp, 32 lanes active. Lane: sub=lane>>3 ->
// candidate, kl=lane&7 -> k within unit. Bit-exact sequential fma chain
// (c ascending; float4 comps x,y,z,w ascending) on g_zt (broadcast within
// 8-lane group) and emb row (contiguous per lane). 8-lane shuffle reduce ->
// one atomicMin(g_best[n]) per candidate. Grid sized for full occupancy
// (latency-bound: throughput ~ resident warps).
// ---------------------------------------------------------------------------
#define RS_BLOCKS 1184
__global__ __launch_bounds__(256)
void rescore_kernel(const float* __restrict__ zt_unused,
                    const float* __restrict__ emb) {
    const int warp = threadIdx.x >> 5, lane = threadIdx.x & 31;
    const int sub = lane >> 3, kl = lane & 7;
    const unsigned gwarp = blockIdx.x * 8 + warp;
    const unsigned stride4 = gridDim.x * 8 * 4;
    const unsigned ncand = g_ncand;

    for (unsigned base = gwarp * 4; base < ncand; base += stride4) {
        unsigned ci = base + (unsigned)sub;
        bool active = ci < ncand;
        unsigned cd = g_cand[active ? ci : 0];
        int n = cd >> 10, unit = cd & 1023;
        int k = unit * 8 + kl;

        const float4* zr = (const float4*)&g_zt[(size_t)n * 256];
        const float4* er = (const float4*)&emb[(size_t)k * 256];
        float acc = 0.f;
        #pragma unroll 8
        for (int c4 = 0; c4 < 64; c4++) {
            float4 zf = zr[c4];
            float4 ef = er[c4];
            acc = fmaf(zf.x, ef.x, acc);
            acc = fmaf(zf.y, ef.y, acc);
            acc = fmaf(zf.z, ef.z, acc);
            acc = fmaf(zf.w, ef.w, acc);
        }
        float d = __fsub_rn(__fadd_rn(g_zz[n], g_ee[k]), __fmul_rn(2.f, acc));
        unsigned long long key =
            ((unsigned long long)__float_as_uint(d) << 32) | (unsigned)k;
        #pragma unroll
        for (int o = 4; o; o >>= 1) {
            unsigned long long ok = __shfl_xor_sync(0xffffffffu, key, o);
            if (ok < key) key = ok;
        }
        if (kl == 0 && active) atomicMin(&g_best[n], key);
    }
}

// ---------------------------------------------------------------------------
// gatherq: zq[n][c] = emb[idx[n]][c], fully coalesced (thread per (n, f4)).
// ---------------------------------------------------------------------------
__global__ void gatherq_kernel(const float* __restrict__ emb) {
    int idx = blockIdx.x * 256 + threadIdx.x;      // NVEC*64
    int n = idx >> 6, f = idx & 63;
    unsigned k = (unsigned)(g_best[n] & 0xFFFFFFFFull);
    ((float4*)g_zq)[(size_t)n * 64 + f] = ((const float4*)emb)[(size_t)k * 64 + f];
}

// ---------------------------------------------------------------------------
// finish: out[o] = fl(z + fl(zq - z)) via 32x32 smem transpose tile; all
// global accesses coalesced. loss = sum fl(zq-z)^2 (double atomics).
// ---------------------------------------------------------------------------
__global__ __launch_bounds__(256)
void finish_kernel(const float* __restrict__ z, float* __restrict__ out) {
    __shared__ float s[32 * 33];
    const int bid = blockIdx.x;
    const int b = bid >> 8, ct = (bid >> 5) & 7, ht = bid & 31;
    const int c0 = ct * 32, hw0 = ht * 32;
    const int t = threadIdx.x;

    {
        int r = t >> 3, q4 = t & 7;
        int n = b * 1024 + hw0 + r;
        float4 w = *(const float4*)&g_zq[(size_t)n * 256 + c0 + q4 * 4];
        float* d = &s[r * 33 + q4 * 4];
        d[0] = w.x; d[1] = w.y; d[2] = w.z; d[3] = w.w;
    }
    __syncthreads();

    const int hwl = t & 31, cl0 = t >> 5;
    float d2s = 0.f;
    #pragma unroll
    for (int it = 0; it < 4; it++) {
        int cl = cl0 + it * 8;
        size_t o = (size_t)b * 262144 + (size_t)(c0 + cl) * 1024 + hw0 + hwl;
        float zv = z[o];
        float q  = s[hwl * 33 + cl];
        float diff = __fsub_rn(q, zv);
        out[o] = __fadd_rn(zv, diff);
        d2s += __fmul_rn(diff, diff);
    }

    #pragma unroll
    for (int off = 16; off; off >>= 1)
        d2s += __shfl_xor_sync(0xffffffffu, d2s, off);
    __shared__ float red[8];
    if ((t & 31) == 0) red[t >> 5] = d2s;
    __syncthreads();
    if (t < 8) {
        float v = red[t];
        #pragma unroll
        for (int off = 4; off; off >>= 1)
            v += __shfl_xor_sync(0xffu, v, off);
        if (t == 0) atomicAdd(&g_loss, (double)v);
    }
}

__global__ void tail_kernel(float* __restrict__ out, int out_size) {
    int i = blockIdx.x * 256 + threadIdx.x;
    if (i < NVEC && out_size >= ZELEMS + NVEC)
        out[ZELEMS + i] = (float)(unsigned)(g_best[i] & 0xFFFFFFFFull);
    if (i == 0 && out_size >= ZELEMS + NVEC + 1) {
        float m = (float)(g_loss / (double)ZELEMS);
        out[ZELEMS + NVEC] = __fadd_rn(m, __fmul_rn(0.25f, m)); // m + BETA*m
    }
}

// ---------------------------------------------------------------------------
extern "C" void kernel_launch(void* const* d_in, const int* in_sizes, int n_in,
                              void* d_out, int out_size) {
    const float* z   = (const float*)d_in[0];
    const float* emb = (const float*)d_in[1];
    float* out = (float*)d_out;

    cudaFuncSetAttribute(filter_gemm_kernel,
                         cudaFuncAttributeMaxDynamicSharedMemorySize, 98304);

    prep_kernel<<<(NVEC + KCODES + 255) / 256, 256>>>(z, emb);
    filter_gemm_kernel<<<128 * 64, 256, 98304>>>();
    extract_kernel<<<NVEC * 32 / 256, 256>>>();
    rescore_kernel<<<RS_BLOCKS, 256>>>(z, emb);
    gatherq_kernel<<<NVEC * 64 / 256, 256>>>(emb);
    finish_kernel<<<16 * 8 * 32, 256>>>(z, out);
    tail_kernel<<<(NVEC + 255) / 256, 256>>>(out, out_size);
}

// round 14
// speedup vs baseline: 6.1383x; 1.0146x over previous
#include <cuda_runtime.h>
#include <cuda_bf16.h>
#include <math_constants.h>

#define NVEC   16384
#define KCODES 8192
#define CDIM   256
#define ZELEMS (16*256*32*32)   /* 4194304 */
#define UNITS  1024             /* per-n units of 8 k */
#define MARGIN 2e-4f
#define CAND_MAX (1u<<22)

__device__ float  g_zz[NVEC];
__device__ float  g_ee[KCODES];
__device__ double g_loss;
__device__ __nv_bfloat16 g_Zh[(size_t)NVEC * CDIM];
__device__ __nv_bfloat16 g_Eh[(size_t)KCODES * CDIM];
__device__ float  g_zt[(size_t)NVEC * CDIM];     /* z transposed to [n][c], fp32 */
__device__ float  g_stmin[(size_t)NVEC * UNITS];
__device__ unsigned char g_mask[(size_t)NVEC * UNITS];  /* per-unit 8-bit candidate mask */
__device__ unsigned g_cand[CAND_MAX];
__device__ unsigned g_ncand;
__device__ unsigned long long g_best[NVEC];
__device__ float  g_zq[(size_t)NVEC * CDIM];

// ---------------------------------------------------------------------------
__device__ __forceinline__ unsigned smem_u32(const void* p) {
    return (unsigned)__cvta_generic_to_shared(p);
}
__device__ __forceinline__ void ldsm4(unsigned& r0, unsigned& r1,
                                      unsigned& r2, unsigned& r3, unsigned a) {
    asm volatile("ldmatrix.sync.aligned.m8n8.x4.shared.b16 {%0,%1,%2,%3}, [%4];"
                 : "=r"(r0), "=r"(r1), "=r"(r2), "=r"(r3) : "r"(a));
}
__device__ __forceinline__ void mma16816(float* c, const unsigned* a, const unsigned* b) {
    asm volatile("mma.sync.aligned.m16n8k16.row.col.f32.bf16.bf16.f32 "
                 "{%0,%1,%2,%3},{%4,%5,%6,%7},{%8,%9},{%0,%1,%2,%3};"
                 : "+f"(c[0]), "+f"(c[1]), "+f"(c[2]), "+f"(c[3])
                 : "r"(a[0]), "r"(a[1]), "r"(a[2]), "r"(a[3]), "r"(b[0]), "r"(b[1]));
}
__device__ __forceinline__ void cp16(unsigned s, const void* g) {
    asm volatile("cp.async.cg.shared.global [%0], [%1], 16;" :: "r"(s), "l"(g));
}
__device__ __forceinline__ unsigned bf2pack(float lo, float hi) {
    __nv_bfloat162 t = __floats2bfloat162_rn(lo, hi);
    return *(unsigned*)&t;
}
// interleave low nibbles: bit 2i <- a[i], bit 2i+1 <- b[i]
__device__ __forceinline__ unsigned interleave4(unsigned a, unsigned b) {
    unsigned m = 0;
    #pragma unroll
    for (int i = 0; i < 4; i++)
        m |= (((a >> i) & 1u) << (2 * i)) | (((b >> i) & 1u) << (2 * i + 1));
    return m;
}

// ---------------------------------------------------------------------------
// prep: per-n -> zz (sequential fp32 mul+add) + bf16 Zh row + fp32 g_zt row;
//       per-k -> ee + bf16 Eh row. All row writes thread-contiguous.
// ---------------------------------------------------------------------------
__global__ void prep_kernel(const float* __restrict__ z,
                            const float* __restrict__ emb) {
    int i = blockIdx.x * 256 + threadIdx.x;
    if (i == 0) { g_loss = 0.0; g_ncand = 0u; }
    if (i < NVEC) {
        g_best[i] = 0xFFFFFFFFFFFFFFFFull;
        int b = i >> 10, hw = i & 1023;
        const float* p = z + (size_t)b * 262144 + hw;
        float acc = 0.f;
        #pragma unroll 1
        for (int ch = 0; ch < 8; ch++) {
            float v[32];
            #pragma unroll
            for (int j = 0; j < 32; j++)
                v[j] = p[(size_t)(ch * 32 + j) * 1024];
            #pragma unroll
            for (int j = 0; j < 32; j++)
                acc = __fadd_rn(acc, __fmul_rn(v[j], v[j]));
            uint4* dst = (uint4*)&g_Zh[(size_t)i * 256 + ch * 32];
            #pragma unroll
            for (int q = 0; q < 4; q++)
                dst[q] = make_uint4(bf2pack(v[q*8+0], v[q*8+1]), bf2pack(v[q*8+2], v[q*8+3]),
                                    bf2pack(v[q*8+4], v[q*8+5]), bf2pack(v[q*8+6], v[q*8+7]));
            float4* zt = (float4*)&g_zt[(size_t)i * 256 + ch * 32];
            #pragma unroll
            for (int q = 0; q < 8; q++)
                zt[q] = make_float4(v[q*4], v[q*4+1], v[q*4+2], v[q*4+3]);
        }
        g_zz[i] = acc;
    } else if (i < NVEC + KCODES) {
        int k = i - NVEC;
        const float4* p = (const float4*)(emb + (size_t)k * 256);
        float acc = 0.f;
        #pragma unroll 1
        for (int ch = 0; ch < 8; ch++) {
            float v[32];
            #pragma unroll
            for (int q = 0; q < 8; q++) {
                float4 w = p[ch * 8 + q];
                v[q*4] = w.x; v[q*4+1] = w.y; v[q*4+2] = w.z; v[q*4+3] = w.w;
            }
            #pragma unroll
            for (int j = 0; j < 32; j++)
                acc = __fadd_rn(acc, __fmul_rn(v[j], v[j]));
            uint4* dst = (uint4*)&g_Eh[(size_t)k * 256 + ch * 32];
            #pragma unroll
            for (int q = 0; q < 4; q++)
                dst[q] = make_uint4(bf2pack(v[q*8+0], v[q*8+1]), bf2pack(v[q*8+2], v[q*8+3]),
                                    bf2pack(v[q*8+4], v[q*8+5]), bf2pack(v[q*8+6], v[q*8+7]));
        }
        g_ee[k] = acc;
    }
}

// ---------------------------------------------------------------------------
// Filter GEMM: dot~ = Zh*Eh (K=256), fp32 acc. CTA 128n x 128k, 8 warps (2x4),
// warp 64x32, mma m16n8k16. 3-stage cp.async circular pipeline, 1 sync/chunk.
// Epilogue: per-(row, 8k-unit) min + per-unit 8-bit mask of k's with
// d~ <= unit_min + MARGIN (conservative superset of global-margin set)
// -> smem transpose -> coalesced g_stmin / g_mask.
// ---------------------------------------------------------------------------
__global__ __launch_bounds__(256, 2)
void filter_gemm_kernel() {
    extern __shared__ char sm[];
    const unsigned smBase = smem_u32(sm);

    const int t = threadIdx.x;
    const int lane = t & 31, warp = t >> 5;
    const int wm = warp >> 2, wn = warp & 3;
    const int bm = blockIdx.x >> 6, bn = blockIdx.x & 63;

    float acc[4][4][4];
    #pragma unroll
    for (int mi = 0; mi < 4; mi++)
        #pragma unroll
        for (int ni = 0; ni < 4; ni++)
            #pragma unroll
            for (int r = 0; r < 4; r++) acc[mi][ni][r] = 0.f;

    const int rA = lane & 15, cAsel = lane >> 4, l7 = lane & 7;
    const int rB = (lane & 7) + ((lane >> 4) << 3), cBsel = (lane >> 3) & 1;

    const int lrow = t >> 3, lch = t & 7;
    const unsigned ldst_off = (unsigned)(lrow * 128 + ((lch ^ (lrow & 7)) << 4));

    #define ISSUE_CHUNK(q, s) do {                                            \
        int coff_ = (q) * 64;                                                  \
        _Pragma("unroll")                                                      \
        for (int i_ = 0; i_ < 4; i_++) {                                       \
            int row_ = lrow + i_ * 32;                                         \
            unsigned off_ = ldst_off + i_ * 32 * 128;                          \
            cp16(smBase + (s) * 32768 + off_,                                  \
                 g_Zh + (size_t)(bm * 128 + row_) * 256 + coff_ + lch * 8);    \
            cp16(smBase + (s) * 32768 + 16384 + off_,                          \
                 g_Eh + (size_t)(bn * 128 + row_) * 256 + coff_ + lch * 8);    \
        }                                                                      \
        asm volatile("cp.async.commit_group;");                                \
    } while (0)

    ISSUE_CHUNK(0, 0);
    ISSUE_CHUNK(1, 1);

    #pragma unroll
    for (int q = 0; q < 4; q++) {
        if (q < 3) asm volatile("cp.async.wait_group 1;");
        else       asm volatile("cp.async.wait_group 0;");
        __syncthreads();

        const unsigned Ab = smBase + (q % 3) * 32768;
        const unsigned Bb = Ab + 16384;

        #pragma unroll
        for (int ks = 0; ks < 4; ks++) {
            unsigned a[4][4], b[4][2];
            #pragma unroll
            for (int mi = 0; mi < 4; mi++) {
                int row = wm * 64 + mi * 16 + rA;
                unsigned ad = Ab + row * 128 + (((2 * ks + cAsel) ^ l7) << 4);
                ldsm4(a[mi][0], a[mi][1], a[mi][2], a[mi][3], ad);
            }
            #pragma unroll
            for (int nj = 0; nj < 2; nj++) {
                int row = wn * 32 + nj * 16 + rB;
                unsigned bd = Bb + row * 128 + (((2 * ks + cBsel) ^ l7) << 4);
                unsigned r0, r1, r2, r3;
                ldsm4(r0, r1, r2, r3, bd);
                b[2 * nj][0] = r0; b[2 * nj][1] = r1;
                b[2 * nj + 1][0] = r2; b[2 * nj + 1][1] = r3;
            }
            #pragma unroll
            for (int mi = 0; mi < 4; mi++)
                #pragma unroll
                for (int ni = 0; ni < 4; ni++)
                    mma16816(acc[mi][ni], a[mi], b[ni]);
        }
        if (q < 2) ISSUE_CHUNK(q + 2, (q + 2) % 3);
    }

    __syncthreads();
    float* st = (float*)sm;                              // [128 rows][16 units]
    unsigned char* stm = (unsigned char*)(sm + 8192);    // [128 rows][16 units]
    #pragma unroll
    for (int mi = 0; mi < 4; mi++) {
        int rl0 = wm * 64 + mi * 16 + (lane >> 2);
        int r0 = bm * 128 + rl0;
        float zz0 = g_zz[r0], zz1 = g_zz[r0 + 8];
        #pragma unroll
        for (int ni = 0; ni < 4; ni++) {
            int col = bn * 128 + wn * 32 + ni * 8 + (lane & 3) * 2;
            float e0 = g_ee[col], e1 = g_ee[col + 1];
            float d00 = __fsub_rn(__fadd_rn(zz0, e0), __fmul_rn(2.f, acc[mi][ni][0]));
            float d01 = __fsub_rn(__fadd_rn(zz0, e1), __fmul_rn(2.f, acc[mi][ni][1]));
            float d10 = __fsub_rn(__fadd_rn(zz1, e0), __fmul_rn(2.f, acc[mi][ni][2]));
            float d11 = __fsub_rn(__fadd_rn(zz1, e1), __fmul_rn(2.f, acc[mi][ni][3]));
            float vlo = fminf(d00, d01), vhi = fminf(d10, d11);
            vlo = fminf(vlo, __shfl_xor_sync(0xffffffffu, vlo, 1));
            vlo = fminf(vlo, __shfl_xor_sync(0xffffffffu, vlo, 2));
            vhi = fminf(vhi, __shfl_xor_sync(0xffffffffu, vhi, 1));
            vhi = fminf(vhi, __shfl_xor_sync(0xffffffffu, vhi, 2));
            // per-unit candidate masks vs unit min + MARGIN
            float thr0 = vlo + MARGIN, thr1 = vhi + MARGIN;
            unsigned b00 = __ballot_sync(0xffffffffu, d00 <= thr0);
            unsigned b01 = __ballot_sync(0xffffffffu, d01 <= thr0);
            unsigned b10 = __ballot_sync(0xffffffffu, d10 <= thr1);
            unsigned b11 = __ballot_sync(0xffffffffu, d11 <= thr1);
            if ((lane & 3) == 0) {
                int g4 = lane & ~3;   // group base lane
                unsigned m0 = interleave4((b00 >> g4) & 0xF, (b01 >> g4) & 0xF);
                unsigned m1 = interleave4((b10 >> g4) & 0xF, (b11 >> g4) & 0xF);
                st[rl0 * 16 + wn * 4 + ni] = vlo;
                st[(rl0 + 8) * 16 + wn * 4 + ni] = vhi;
                stm[rl0 * 16 + wn * 4 + ni] = (unsigned char)m0;
                stm[(rl0 + 8) * 16 + wn * 4 + ni] = (unsigned char)m1;
            }
        }
    }
    __syncthreads();
    {
        int rl = t >> 1, u0 = (t & 1) * 8;
        float* dst = &g_stmin[(size_t)(bm * 128 + rl) * UNITS + bn * 16 + u0];
        float* src = &st[rl * 16 + u0];
        *(float4*)dst = *(float4*)src;
        *(float4*)(dst + 4) = *(float4*)(src + 4);
        *(unsigned long long*)&g_mask[(size_t)(bm * 128 + rl) * UNITS + bn * 16 + u0] =
            *(unsigned long long*)&stm[rl * 16 + u0];
    }
}

// ---------------------------------------------------------------------------
// Extraction: warp per n. Global min over 1024 unit-mins, flag units within
// MARGIN, emit individual k candidates from per-unit masks: (n<<13 | k).
// ---------------------------------------------------------------------------
__global__ __launch_bounds__(256)
void extract_kernel() {
    int n = (blockIdx.x * 256 + threadIdx.x) >> 5;
    int lane = threadIdx.x & 31;
    if (n >= NVEC) return;
    const float4* row = (const float4*)&g_stmin[(size_t)n * UNITS];
    const unsigned* m32 = (const unsigned*)&g_mask[(size_t)n * UNITS];

    float4 v[8]; unsigned mk[8];
    float mn = CUDART_INF_F;
    #pragma unroll
    for (int j = 0; j < 8; j++) {
        v[j] = row[j * 32 + lane];
        mk[j] = m32[j * 32 + lane];
        mn = fminf(mn, fminf(fminf(v[j].x, v[j].y), fminf(v[j].z, v[j].w)));
    }
    #pragma unroll
    for (int o = 16; o; o >>= 1) mn = fminf(mn, __shfl_xor_sync(0xffffffffu, mn, o));
    const float thr = mn + MARGIN;

    unsigned cnt = 0;
    #pragma unroll
    for (int j = 0; j < 8; j++) {
        float vv[4] = { v[j].x, v[j].y, v[j].z, v[j].w };
        #pragma unroll
        for (int c = 0; c < 4; c++)
            if (vv[c] <= thr) cnt += __popc((mk[j] >> (8 * c)) & 0xFFu);
    }

    unsigned p = cnt;
    #pragma unroll
    for (int o = 1; o < 32; o <<= 1) {
        unsigned tv = __shfl_up_sync(0xffffffffu, p, o);
        if (lane >= o) p += tv;
    }
    unsigned excl = p - cnt;
    unsigned total = __shfl_sync(0xffffffffu, p, 31);
    unsigned base = 0;
    if (lane == 31) base = atomicAdd(&g_ncand, total);
    base = __shfl_sync(0xffffffffu, base, 31);

    unsigned w = base + excl;
    #pragma unroll
    for (int j = 0; j < 8; j++) {
        float vv[4] = { v[j].x, v[j].y, v[j].z, v[j].w };
        #pragma unroll
        for (int c = 0; c < 4; c++) {
            if (vv[c] <= thr) {
                unsigned unit = (unsigned)((j * 32 + lane) * 4 + c);
                unsigned bits = (mk[j] >> (8 * c)) & 0xFFu;
                while (bits) {
                    int bbit = __ffs(bits) - 1;
                    bits &= bits - 1;
                    if (w < CAND_MAX)
                        g_cand[w++] = ((unsigned)n << 13) | (unit * 8 + bbit);
                }
            }
        }
    }
}

// ---------------------------------------------------------------------------
// Rescore: one candidate (n, k) per thread. Bit-exact sequential fma chain
// (c ascending; float4 comps x,y,z,w ascending) on g_zt and emb rows.
// Lexicographic (d_bits, k) key -> atomicMin(g_best[n]).
// ---------------------------------------------------------------------------
#define RS_BLOCKS 592
__global__ __launch_bounds__(256)
void rescore_kernel(const float* __restrict__ emb) {
    unsigned idx = blockIdx.x * 256 + threadIdx.x;
    unsigned stride = gridDim.x * 256;
    const unsigned ncand = g_ncand;

    for (unsigned ci = idx; ci < ncand; ci += stride) {
        unsigned cd = g_cand[ci];
        int n = cd >> 13, k = cd & 8191;

        const float4* zr = (const float4*)&g_zt[(size_t)n * 256];
        const float4* er = (const float4*)&emb[(size_t)k * 256];
        float acc = 0.f;
        #pragma unroll 8
        for (int c4 = 0; c4 < 64; c4++) {
            float4 zf = zr[c4];
            float4 ef = er[c4];
            acc = fmaf(zf.x, ef.x, acc);
            acc = fmaf(zf.y, ef.y, acc);
            acc = fmaf(zf.z, ef.z, acc);
            acc = fmaf(zf.w, ef.w, acc);
        }
        float d = __fsub_rn(__fadd_rn(g_zz[n], g_ee[k]), __fmul_rn(2.f, acc));
        unsigned long long key =
            ((unsigned long long)__float_as_uint(d) << 32) | (unsigned)k;
        atomicMin(&g_best[n], key);
    }
}

// ---------------------------------------------------------------------------
// gatherq: zq[n][c] = emb[idx[n]][c], fully coalesced (thread per (n, f4)).
// ---------------------------------------------------------------------------
__global__ void gatherq_kernel(const float* __restrict__ emb) {
    int idx = blockIdx.x * 256 + threadIdx.x;      // NVEC*64
    int n = idx >> 6, f = idx & 63;
    unsigned k = (unsigned)(g_best[n] & 0xFFFFFFFFull);
    ((float4*)g_zq)[(size_t)n * 64 + f] = ((const float4*)emb)[(size_t)k * 64 + f];
}

// ---------------------------------------------------------------------------
// finish: out[o] = fl(z + fl(zq - z)) via 32x32 smem transpose tile; all
// global accesses coalesced. loss = sum fl(zq-z)^2 (double atomics).
// ---------------------------------------------------------------------------
__global__ __launch_bounds__(256)
void finish_kernel(const float* __restrict__ z, float* __restrict__ out) {
    __shared__ float s[32 * 33];
    const int bid = blockIdx.x;
    const int b = bid >> 8, ct = (bid >> 5) & 7, ht = bid & 31;
    const int c0 = ct * 32, hw0 = ht * 32;
    const int t = threadIdx.x;

    {
        int r = t >> 3, q4 = t & 7;
        int n = b * 1024 + hw0 + r;
        float4 w = *(const float4*)&g_zq[(size_t)n * 256 + c0 + q4 * 4];
        float* d = &s[r * 33 + q4 * 4];
        d[0] = w.x; d[1] = w.y; d[2] = w.z; d[3] = w.w;
    }
    __syncthreads();

    const int hwl = t & 31, cl0 = t >> 5;
    float d2s = 0.f;
    #pragma unroll
    for (int it = 0; it < 4; it++) {
        int cl = cl0 + it * 8;
        size_t o = (size_t)b * 262144 + (size_t)(c0 + cl) * 1024 + hw0 + hwl;
        float zv = z[o];
        float q  = s[hwl * 33 + cl];
        float diff = __fsub_rn(q, zv);
        out[o] = __fadd_rn(zv, diff);
        d2s += __fmul_rn(diff, diff);
    }

    #pragma unroll
    for (int off = 16; off; off >>= 1)
        d2s += __shfl_xor_sync(0xffffffffu, d2s, off);
    __shared__ float red[8];
    if ((t & 31) == 0) red[t >> 5] = d2s;
    __syncthreads();
    if (t < 8) {
        float v = red[t];
        #pragma unroll
        for (int off = 4; off; off >>= 1)
            v += __shfl_xor_sync(0xffu, v, off);
        if (t == 0) atomicAdd(&g_loss, (double)v);
    }
}

__global__ void tail_kernel(float* __restrict__ out, int out_size) {
    int i = blockIdx.x * 256 + threadIdx.x;
    if (i < NVEC && out_size >= ZELEMS + NVEC)
        out[ZELEMS + i] = (float)(unsigned)(g_best[i] & 0xFFFFFFFFull);
    if (i == 0 && out_size >= ZELEMS + NVEC + 1) {
        float m = (float)(g_loss / (double)ZELEMS);
        out[ZELEMS + NVEC] = __fadd_rn(m, __fmul_rn(0.25f, m)); // m + BETA*m
    }
}

// ---------------------------------------------------------------------------
extern "C" void kernel_launch(void* const* d_in, const int* in_sizes, int n_in,
                              void* d_out, int out_size) {
    const float* z   = (const float*)d_in[0];
    const float* emb = (const float*)d_in[1];
    float* out = (float*)d_out;

    cudaFuncSetAttribute(filter_gemm_kernel,
                         cudaFuncAttributeMaxDynamicSharedMemorySize, 98304);

    prep_kernel<<<(NVEC + KCODES + 255) / 256, 256>>>(z, emb);
    filter_gemm_kernel<<<128 * 64, 256, 98304>>>();
    extract_kernel<<<NVEC * 32 / 256, 256>>>();
    rescore_kernel<<<RS_BLOCKS, 256>>>(emb);
    gatherq_kernel<<<NVEC * 64 / 256, 256>>>(emb);
    finish_kernel<<<16 * 8 * 32, 256>>>(z, out);
    tail_kernel<<<(NVEC + 255) / 256, 256>>>(out, out_size);
}